// round 1
// baseline (speedup 1.0000x reference)
#include <cuda_runtime.h>
#include <math.h>

#define NB 2
#define NT 4096
#define ND 2048
#define NH 32
#define NN 64
#define NP 64
#define NL 256
#define NC 16
#define NTOK (NB*NT)   // 8192

// ---------------- scratch (device globals; no runtime allocation) ----------
__device__ float g_B[(size_t)NTOK*NN];
__device__ float g_C[(size_t)NTOK*NN];
__device__ float g_dt[(size_t)NTOK*NH];
__device__ float g_cum[(size_t)NB*NH*NC*NL];
__device__ float g_states[(size_t)NB*NC*NH*NN*NP];
__device__ float g_prev[(size_t)NB*NC*NH*NN*NP];
__device__ float g_Y[(size_t)NTOK*ND];

__device__ __forceinline__ float softplus_f(float v) {
    return v > 20.f ? v : log1pf(expf(v));
}

// ---------------------------------------------------------------------------
// Projection GEMM: out[M,N] = A[M,K] @ W[N,K]^T + bias   (osel picks target)
// BM=64, BN=64, BK=16, TM=TN=4, 256 threads
// ---------------------------------------------------------------------------
__global__ __launch_bounds__(256) void proj_gemm(
    const float* __restrict__ A, const float* __restrict__ W,
    const float* __restrict__ bias, int M, int N, int K, int osel)
{
    __shared__ float As[16][68];
    __shared__ float Ws[16][68];
    float* out = (osel == 0) ? g_B : (osel == 1) ? g_C : g_dt;
    const int tid = threadIdx.x;
    const int tn = tid & 15, tm = tid >> 4;
    const int m0 = blockIdx.y * 64, n0 = blockIdx.x * 64;
    const int lr = tid >> 2, lk = (tid & 3) * 4;
    float acc[4][4] = {};

    for (int k0 = 0; k0 < K; k0 += 16) {
        float4 av = *(const float4*)&A[(size_t)(m0 + lr) * K + k0 + lk];
        float4 wv = make_float4(0.f, 0.f, 0.f, 0.f);
        if (n0 + lr < N)
            wv = *(const float4*)&W[(size_t)(n0 + lr) * K + k0 + lk];
        As[lk+0][lr] = av.x; As[lk+1][lr] = av.y; As[lk+2][lr] = av.z; As[lk+3][lr] = av.w;
        Ws[lk+0][lr] = wv.x; Ws[lk+1][lr] = wv.y; Ws[lk+2][lr] = wv.z; Ws[lk+3][lr] = wv.w;
        __syncthreads();
        #pragma unroll
        for (int k = 0; k < 16; k++) {
            float a[4], b[4];
            #pragma unroll
            for (int i = 0; i < 4; i++) a[i] = As[k][tm*4+i];
            #pragma unroll
            for (int j = 0; j < 4; j++) b[j] = Ws[k][tn*4+j];
            #pragma unroll
            for (int i = 0; i < 4; i++)
                #pragma unroll
                for (int j = 0; j < 4; j++)
                    acc[i][j] = fmaf(a[i], b[j], acc[i][j]);
        }
        __syncthreads();
    }
    #pragma unroll
    for (int i = 0; i < 4; i++) {
        int m = m0 + tm*4 + i;
        #pragma unroll
        for (int j = 0; j < 4; j++) {
            int n = n0 + tn*4 + j;
            if (n < N) {
                float v = acc[i][j] + bias[n];
                if (osel == 2) v = softplus_f(v);
                out[(size_t)m * N + n] = v;
            }
        }
    }
}

// ---------------------------------------------------------------------------
// Per-(b,h,c) inclusive cumsum of dA = dt * A  over the chunk (L=256)
// grid linear index == ((b*NH+h)*NC+c)
// ---------------------------------------------------------------------------
__global__ void cumsum_kernel(const float* __restrict__ A_log)
{
    __shared__ float sm[NL];
    int bid = blockIdx.x;
    int c = bid % NC, h = (bid / NC) % NH, b = bid / (NC * NH);
    int s = threadIdx.x;
    float Ah = -expf(A_log[h]);
    int t = c * NL + s;
    sm[s] = g_dt[(size_t)(b*NT + t)*NH + h] * Ah;
    __syncthreads();
    for (int off = 1; off < NL; off <<= 1) {
        float add = (s >= off) ? sm[s - off] : 0.f;
        __syncthreads();
        sm[s] += add;
        __syncthreads();
    }
    g_cum[(size_t)bid * NL + s] = sm[s];
}

// ---------------------------------------------------------------------------
// Chunk states: S[n,p] = sum_s B[s,n] * exp(cum_last - cum_s) * dt_s * x[s,p]
// one block per (b,c,h); 64x64 output, K=256 in s-tiles of 64
// ---------------------------------------------------------------------------
__global__ __launch_bounds__(256) void states_kernel(const float* __restrict__ x)
{
    __shared__ float Bs[64*64];
    __shared__ float XS[64*64];
    int bid = blockIdx.x;
    int h = bid % NH, c = (bid / NH) % NC, b = bid / (NH*NC);
    const int tid = threadIdx.x;
    const int tn = tid & 15, tm = tid >> 4;
    const float* cumc = &g_cum[(size_t)((b*NH + h)*NC + c) * NL];
    const float cum_last = cumc[NL-1];
    float acc[4][4] = {};

    for (int s0 = 0; s0 < NL; s0 += 64) {
        if (s0) __syncthreads();
        int v = tid;
        #pragma unroll
        for (int it = 0; it < 4; it++, v += 256) {
            int row = v >> 4, c4 = (v & 15) * 4;
            int gt = c*NL + s0 + row;
            float w = __expf(cum_last - cumc[s0 + row]) *
                      g_dt[(size_t)(b*NT + gt)*NH + h];
            float4 bv = *(const float4*)&g_B[(size_t)(b*NT + gt)*NN + c4];
            float4 xv = *(const float4*)&x[(size_t)(b*NT + gt)*ND + h*NP + c4];
            *(float4*)&Bs[row*64 + c4] = make_float4(bv.x*w, bv.y*w, bv.z*w, bv.w*w);
            *(float4*)&XS[row*64 + c4] = xv;
        }
        __syncthreads();
        #pragma unroll 8
        for (int s = 0; s < 64; s++) {
            float a[4], bb[4];
            #pragma unroll
            for (int i = 0; i < 4; i++) a[i] = Bs[s*64 + tm*4 + i];
            #pragma unroll
            for (int j = 0; j < 4; j++) bb[j] = XS[s*64 + tn*4 + j];
            #pragma unroll
            for (int i = 0; i < 4; i++)
                #pragma unroll
                for (int j = 0; j < 4; j++)
                    acc[i][j] = fmaf(a[i], bb[j], acc[i][j]);
        }
    }
    float* S = &g_states[(((size_t)b*NC + c)*NH + h) * (NN*NP)];
    #pragma unroll
    for (int i = 0; i < 4; i++)
        #pragma unroll
        for (int j = 0; j < 4; j++)
            S[(tm*4+i)*NP + tn*4 + j] = acc[i][j];
}

// ---------------------------------------------------------------------------
// Inter-chunk scan (recurrence equivalent of decay_chunk einsum):
//   prev[c] = R;  R = exp(a_c) * R + states[c]
// one block per (b,h); each thread owns 16 of 4096 state elements
// ---------------------------------------------------------------------------
__global__ void scan_kernel()
{
    int bid = blockIdx.x;                 // b*NH + h
    int h = bid % NH, b = bid / NH;
    int tid = threadIdx.x;
    int e0 = tid * 16;
    float4 R[4];
    #pragma unroll
    for (int q = 0; q < 4; q++) R[q] = make_float4(0.f, 0.f, 0.f, 0.f);
    #pragma unroll 1
    for (int c = 0; c < NC; c++) {
        size_t off = (((size_t)b*NC + c)*NH + h) * (NN*NP) + e0;
        #pragma unroll
        for (int q = 0; q < 4; q++)
            *(float4*)&g_prev[off + q*4] = R[q];
        float a = g_cum[(size_t)((b*NH + h)*NC + c)*NL + NL - 1];
        float dec = __expf(a);
        #pragma unroll
        for (int q = 0; q < 4; q++) {
            float4 sv = *(const float4*)&g_states[off + q*4];
            R[q].x = fmaf(dec, R[q].x, sv.x);
            R[q].y = fmaf(dec, R[q].y, sv.y);
            R[q].z = fmaf(dec, R[q].z, sv.z);
            R[q].w = fmaf(dec, R[q].w, sv.w);
        }
    }
}

// ---------------------------------------------------------------------------
// Y kernel: per (b,c,h,l-tile of 64)
//   Y = exp(cum_l) * (C @ S_prev)                       (off-diagonal)
//     + sum_{s-tiles<=lt} ((C B^T) .* L) @ (x*dt)       (diagonal, causal)
//     + D_h * x
// smem: Cs (plain), BG (B xor-swizzled, reused for G), XS (xdt)  = 48KB
// ---------------------------------------------------------------------------
__global__ __launch_bounds__(256) void y_kernel(const float* __restrict__ x,
                                                const float* __restrict__ Dvec)
{
    __shared__ float Cs[64*64];
    __shared__ float BG[64*64];
    __shared__ float XS[64*64];
    int bid = blockIdx.x;
    int lt = bid & 3;
    int h  = (bid >> 2) & 31;
    int c  = (bid >> 7) & 15;
    int b  = bid >> 11;
    const int tid = threadIdx.x;
    const int tn = tid & 15, tm = tid >> 4;
    const int t0 = c * NL;

    { // load C tile (rows t0+lt*64+l) and prev-state S[n][p]
        const float* S = &g_prev[(((size_t)b*NC + c)*NH + h) * (NN*NP)];
        int v = tid;
        #pragma unroll
        for (int it = 0; it < 4; it++, v += 256) {
            int row = v >> 4, c4 = (v & 15) * 4;
            *(float4*)&Cs[row*64 + c4] =
                *(const float4*)&g_C[(size_t)(b*NT + t0 + lt*64 + row)*NN + c4];
            *(float4*)&BG[row*64 + c4] = *(const float4*)&S[row*64 + c4];
        }
    }
    __syncthreads();

    const float* cumc = &g_cum[(size_t)((b*NH + h)*NC + c) * NL];
    float cum_l[4], e_l[4];
    #pragma unroll
    for (int i = 0; i < 4; i++) {
        cum_l[i] = cumc[lt*64 + tm*4 + i];
        e_l[i]   = __expf(cum_l[i]);
    }

    float acc[4][4] = {};
    // ---- Y_off = C @ S_prev, scaled by exp(cum_l) afterwards
    #pragma unroll 8
    for (int n = 0; n < 64; n++) {
        float a[4], bb[4];
        #pragma unroll
        for (int i = 0; i < 4; i++) a[i] = Cs[(tm*4+i)*64 + n];
        #pragma unroll
        for (int j = 0; j < 4; j++) bb[j] = BG[n*64 + tn*4 + j];
        #pragma unroll
        for (int i = 0; i < 4; i++)
            #pragma unroll
            for (int j = 0; j < 4; j++)
                acc[i][j] = fmaf(a[i], bb[j], acc[i][j]);
    }
    #pragma unroll
    for (int i = 0; i < 4; i++)
        #pragma unroll
        for (int j = 0; j < 4; j++)
            acc[i][j] *= e_l[i];

    // ---- causal s-tiles
    for (int st = 0; st <= lt; st++) {
        __syncthreads();
        { // load B (xor-swizzled rows) and xdt tile
            int v = tid;
            #pragma unroll
            for (int it = 0; it < 4; it++, v += 256) {
                int row = v >> 4, c4 = (v & 15) * 4;
                int gt = t0 + st*64 + row;
                float4 bv = *(const float4*)&g_B[(size_t)(b*NT + gt)*NN + c4];
                BG[row*64 + ((c4+0+row)&63)] = bv.x;
                BG[row*64 + ((c4+1+row)&63)] = bv.y;
                BG[row*64 + ((c4+2+row)&63)] = bv.z;
                BG[row*64 + ((c4+3+row)&63)] = bv.w;
                float dtv = g_dt[(size_t)(b*NT + gt)*NH + h];
                float4 xv = *(const float4*)&x[(size_t)(b*NT + gt)*ND + h*NP + c4];
                *(float4*)&XS[row*64 + c4] =
                    make_float4(xv.x*dtv, xv.y*dtv, xv.z*dtv, xv.w*dtv);
            }
        }
        __syncthreads();

        // G = C @ B^T   (inner over n; B read through swizzle)
        float g[4][4] = {};
        #pragma unroll 8
        for (int n = 0; n < 64; n++) {
            float a[4], bb[4];
            #pragma unroll
            for (int i = 0; i < 4; i++) a[i] = Cs[(tm*4+i)*64 + n];
            #pragma unroll
            for (int j = 0; j < 4; j++) {
                int sj = tn*4 + j;
                bb[j] = BG[sj*64 + ((n + sj)&63)];
            }
            #pragma unroll
            for (int i = 0; i < 4; i++)
                #pragma unroll
                for (int j = 0; j < 4; j++)
                    g[i][j] = fmaf(a[i], bb[j], g[i][j]);
        }
        // apply L = exp(cum_l - cum_s), causal mask on the diagonal tile
        float cum_s[4];
        #pragma unroll
        for (int j = 0; j < 4; j++) cum_s[j] = cumc[st*64 + tn*4 + j];
        if (st < lt) {
            #pragma unroll
            for (int i = 0; i < 4; i++)
                #pragma unroll
                for (int j = 0; j < 4; j++)
                    g[i][j] *= __expf(cum_l[i] - cum_s[j]);
        } else {
            #pragma unroll
            for (int i = 0; i < 4; i++)
                #pragma unroll
                for (int j = 0; j < 4; j++) {
                    int l = tm*4 + i, s = tn*4 + j;
                    g[i][j] = (s <= l) ? g[i][j] * __expf(cum_l[i] - cum_s[j]) : 0.f;
                }
        }
        __syncthreads();           // everyone done reading BG as B
        #pragma unroll
        for (int i = 0; i < 4; i++)
            #pragma unroll
            for (int j = 0; j < 4; j++)
                BG[(tm*4+i)*64 + tn*4 + j] = g[i][j];   // BG now holds G (plain)
        __syncthreads();

        // Y += G @ XS
        #pragma unroll 8
        for (int k = 0; k < 64; k++) {
            float a[4], bb[4];
            #pragma unroll
            for (int i = 0; i < 4; i++) a[i] = BG[(tm*4+i)*64 + k];
            #pragma unroll
            for (int j = 0; j < 4; j++) bb[j] = XS[k*64 + tn*4 + j];
            #pragma unroll
            for (int i = 0; i < 4; i++)
                #pragma unroll
                for (int j = 0; j < 4; j++)
                    acc[i][j] = fmaf(a[i], bb[j], acc[i][j]);
        }
    }

    // ---- epilogue: + D_h * x, store
    float Dh = Dvec[h];
    #pragma unroll
    for (int i = 0; i < 4; i++) {
        int gt = t0 + lt*64 + tm*4 + i;
        size_t ro = (size_t)(b*NT + gt)*ND + h*NP;
        #pragma unroll
        for (int j = 0; j < 4; j++) {
            int p = tn*4 + j;
            g_Y[ro + p] = acc[i][j] + Dh * x[ro + p];
        }
    }
}

// ---------------------------------------------------------------------------
// Output projection: out[M,N] = g_Y[M,K] @ out_w[N,K]^T + out_b
// BM=BN=128, BK=16, TM=TN=8, 256 threads
// ---------------------------------------------------------------------------
__global__ __launch_bounds__(256, 2) void out_gemm(
    const float* __restrict__ W, const float* __restrict__ bias,
    float* __restrict__ out)
{
    __shared__ float As[16][132];
    __shared__ float Ws[16][132];
    const int tid = threadIdx.x;
    const int tn = tid & 15, tm = tid >> 4;
    const int m0 = blockIdx.y * 128, n0 = blockIdx.x * 128;
    const int lr = tid >> 2, lk = (tid & 3) * 4;
    const float* A = g_Y;
    float acc[8][8] = {};

    for (int k0 = 0; k0 < ND; k0 += 16) {
        float4 a0 = *(const float4*)&A[(size_t)(m0 + lr)      * ND + k0 + lk];
        float4 a1 = *(const float4*)&A[(size_t)(m0 + lr + 64) * ND + k0 + lk];
        float4 w0 = *(const float4*)&W[(size_t)(n0 + lr)      * ND + k0 + lk];
        float4 w1 = *(const float4*)&W[(size_t)(n0 + lr + 64) * ND + k0 + lk];
        As[lk+0][lr] = a0.x; As[lk+1][lr] = a0.y; As[lk+2][lr] = a0.z; As[lk+3][lr] = a0.w;
        As[lk+0][lr+64] = a1.x; As[lk+1][lr+64] = a1.y; As[lk+2][lr+64] = a1.z; As[lk+3][lr+64] = a1.w;
        Ws[lk+0][lr] = w0.x; Ws[lk+1][lr] = w0.y; Ws[lk+2][lr] = w0.z; Ws[lk+3][lr] = w0.w;
        Ws[lk+0][lr+64] = w1.x; Ws[lk+1][lr+64] = w1.y; Ws[lk+2][lr+64] = w1.z; Ws[lk+3][lr+64] = w1.w;
        __syncthreads();
        #pragma unroll
        for (int k = 0; k < 16; k++) {
            float a[8], b[8];
            *(float4*)&a[0] = *(const float4*)&As[k][tm*8];
            *(float4*)&a[4] = *(const float4*)&As[k][tm*8 + 4];
            *(float4*)&b[0] = *(const float4*)&Ws[k][tn*8];
            *(float4*)&b[4] = *(const float4*)&Ws[k][tn*8 + 4];
            #pragma unroll
            for (int i = 0; i < 8; i++)
                #pragma unroll
                for (int j = 0; j < 8; j++)
                    acc[i][j] = fmaf(a[i], b[j], acc[i][j]);
        }
        __syncthreads();
    }
    #pragma unroll
    for (int i = 0; i < 8; i++) {
        size_t ro = (size_t)(m0 + tm*8 + i) * ND + n0 + tn*8;
        #pragma unroll
        for (int j = 0; j < 8; j++)
            out[ro + j] = acc[i][j] + bias[n0 + tn*8 + j];
    }
}

// ---------------------------------------------------------------------------
extern "C" void kernel_launch(void* const* d_in, const int* in_sizes, int n_in,
                              void* d_out, int out_size)
{
    const float* x     = (const float*)d_in[0];
    const float* A_log = (const float*)d_in[1];
    const float* Dvec  = (const float*)d_in[2];
    const float* B_w   = (const float*)d_in[3];
    const float* B_b   = (const float*)d_in[4];
    const float* C_w   = (const float*)d_in[5];
    const float* C_b   = (const float*)d_in[6];
    const float* dt_w  = (const float*)d_in[7];
    const float* dt_b  = (const float*)d_in[8];
    const float* out_w = (const float*)d_in[9];
    const float* out_b = (const float*)d_in[10];
    float* out = (float*)d_out;

    proj_gemm<<<dim3(1, NTOK/64), 256>>>(x, B_w, B_b, NTOK, NN, ND, 0);
    proj_gemm<<<dim3(1, NTOK/64), 256>>>(x, C_w, C_b, NTOK, NN, ND, 1);
    proj_gemm<<<dim3(1, NTOK/64), 256>>>(x, dt_w, dt_b, NTOK, NH, ND, 2);
    cumsum_kernel<<<NB*NH*NC, NL>>>(A_log);
    states_kernel<<<NB*NC*NH, 256>>>(x);
    scan_kernel<<<NB*NH, 256>>>();
    y_kernel<<<NB*NC*NH*4, 256>>>(x, Dvec);
    out_gemm<<<dim3(ND/128, NTOK/128), 256>>>(out_w, out_b, out);
}

// round 3
// speedup vs baseline: 1.7410x; 1.7410x over previous
#include <cuda_runtime.h>
#include <cstdint>
#include <math.h>

#define NB 2
#define NT 4096
#define ND 2048
#define NH 32
#define NN 64
#define NP 64
#define NL 256
#define NC 16
#define NTOK (NB*NT)   // 8192

// ---------------- scratch (device globals; no runtime allocation) ----------
__device__ float g_B[(size_t)NTOK*NN];
__device__ float g_C[(size_t)NTOK*NN];
__device__ float g_dt[(size_t)NTOK*NH];
__device__ float g_cum[(size_t)NB*NH*NC*NL];
__device__ float g_states[(size_t)NB*NC*NH*NN*NP];
__device__ float g_prev[(size_t)NB*NC*NH*NN*NP];
__device__ float g_Y[(size_t)NTOK*ND];

__device__ __forceinline__ float softplus_f(float v) {
    return v > 20.f ? v : log1pf(expf(v));
}

__device__ __forceinline__ float to_tf32(float v) {
    uint32_t u;
    asm("cvt.rna.tf32.f32 %0, %1;" : "=r"(u) : "f"(v));
    return __uint_as_float(u);
}

// ---------------------------------------------------------------------------
// Projection GEMM: out[M,N] = A[M,K] @ W[N,K]^T + bias   (osel picks target)
// BM=64, BN=64, BK=16, TM=TN=4, 256 threads
// ---------------------------------------------------------------------------
__global__ __launch_bounds__(256) void proj_gemm(
    const float* __restrict__ A, const float* __restrict__ W,
    const float* __restrict__ bias, int M, int N, int K, int osel)
{
    __shared__ float As[16][68];
    __shared__ float Ws[16][68];
    float* out = (osel == 0) ? g_B : (osel == 1) ? g_C : g_dt;
    const int tid = threadIdx.x;
    const int tn = tid & 15, tm = tid >> 4;
    const int m0 = blockIdx.y * 64, n0 = blockIdx.x * 64;
    const int lr = tid >> 2, lk = (tid & 3) * 4;
    float acc[4][4] = {};

    for (int k0 = 0; k0 < K; k0 += 16) {
        float4 av = *(const float4*)&A[(size_t)(m0 + lr) * K + k0 + lk];
        float4 wv = make_float4(0.f, 0.f, 0.f, 0.f);
        if (n0 + lr < N)
            wv = *(const float4*)&W[(size_t)(n0 + lr) * K + k0 + lk];
        As[lk+0][lr] = av.x; As[lk+1][lr] = av.y; As[lk+2][lr] = av.z; As[lk+3][lr] = av.w;
        Ws[lk+0][lr] = wv.x; Ws[lk+1][lr] = wv.y; Ws[lk+2][lr] = wv.z; Ws[lk+3][lr] = wv.w;
        __syncthreads();
        #pragma unroll
        for (int k = 0; k < 16; k++) {
            float a[4], b[4];
            #pragma unroll
            for (int i = 0; i < 4; i++) a[i] = As[k][tm*4+i];
            #pragma unroll
            for (int j = 0; j < 4; j++) b[j] = Ws[k][tn*4+j];
            #pragma unroll
            for (int i = 0; i < 4; i++)
                #pragma unroll
                for (int j = 0; j < 4; j++)
                    acc[i][j] = fmaf(a[i], b[j], acc[i][j]);
        }
        __syncthreads();
    }
    #pragma unroll
    for (int i = 0; i < 4; i++) {
        int m = m0 + tm*4 + i;
        #pragma unroll
        for (int j = 0; j < 4; j++) {
            int n = n0 + tn*4 + j;
            if (n < N) {
                float v = acc[i][j] + bias[n];
                if (osel == 2) v = softplus_f(v);
                out[(size_t)m * N + n] = v;
            }
        }
    }
}

// ---------------------------------------------------------------------------
// Per-(b,h,c) inclusive cumsum of dA = dt * A  over the chunk (L=256)
// ---------------------------------------------------------------------------
__global__ void cumsum_kernel(const float* __restrict__ A_log)
{
    __shared__ float sm[NL];
    int bid = blockIdx.x;
    int c = bid % NC, h = (bid / NC) % NH, b = bid / (NC * NH);
    int s = threadIdx.x;
    float Ah = -expf(A_log[h]);
    int t = c * NL + s;
    sm[s] = g_dt[(size_t)(b*NT + t)*NH + h] * Ah;
    __syncthreads();
    for (int off = 1; off < NL; off <<= 1) {
        float add = (s >= off) ? sm[s - off] : 0.f;
        __syncthreads();
        sm[s] += add;
        __syncthreads();
    }
    g_cum[(size_t)bid * NL + s] = sm[s];
}

// ---------------------------------------------------------------------------
// Chunk states: S[n,p] = sum_s B[s,n] * exp(cum_last - cum_s) * dt_s * x[s,p]
// ---------------------------------------------------------------------------
__global__ __launch_bounds__(256) void states_kernel(const float* __restrict__ x)
{
    __shared__ float Bs[64*64];
    __shared__ float XS[64*64];
    int bid = blockIdx.x;
    int h = bid % NH, c = (bid / NH) % NC, b = bid / (NH*NC);
    const int tid = threadIdx.x;
    const int tn = tid & 15, tm = tid >> 4;
    const float* cumc = &g_cum[(size_t)((b*NH + h)*NC + c) * NL];
    const float cum_last = cumc[NL-1];
    float acc[4][4] = {};

    for (int s0 = 0; s0 < NL; s0 += 64) {
        if (s0) __syncthreads();
        int v = tid;
        #pragma unroll
        for (int it = 0; it < 4; it++, v += 256) {
            int row = v >> 4, c4 = (v & 15) * 4;
            int gt = c*NL + s0 + row;
            float w = __expf(cum_last - cumc[s0 + row]) *
                      g_dt[(size_t)(b*NT + gt)*NH + h];
            float4 bv = *(const float4*)&g_B[(size_t)(b*NT + gt)*NN + c4];
            float4 xv = *(const float4*)&x[(size_t)(b*NT + gt)*ND + h*NP + c4];
            *(float4*)&Bs[row*64 + c4] = make_float4(bv.x*w, bv.y*w, bv.z*w, bv.w*w);
            *(float4*)&XS[row*64 + c4] = xv;
        }
        __syncthreads();
        #pragma unroll 8
        for (int s = 0; s < 64; s++) {
            float a[4], bb[4];
            #pragma unroll
            for (int i = 0; i < 4; i++) a[i] = Bs[s*64 + tm*4 + i];
            #pragma unroll
            for (int j = 0; j < 4; j++) bb[j] = XS[s*64 + tn*4 + j];
            #pragma unroll
            for (int i = 0; i < 4; i++)
                #pragma unroll
                for (int j = 0; j < 4; j++)
                    acc[i][j] = fmaf(a[i], bb[j], acc[i][j]);
        }
    }
    float* S = &g_states[(((size_t)b*NC + c)*NH + h) * (NN*NP)];
    #pragma unroll
    for (int i = 0; i < 4; i++)
        #pragma unroll
        for (int j = 0; j < 4; j++)
            S[(tm*4+i)*NP + tn*4 + j] = acc[i][j];
}

// ---------------------------------------------------------------------------
// Inter-chunk scan: prev[c] = R;  R = exp(a_c) * R + states[c]
// ---------------------------------------------------------------------------
__global__ void scan_kernel()
{
    int bid = blockIdx.x;                 // b*NH + h
    int h = bid % NH, b = bid / NH;
    int tid = threadIdx.x;
    int e0 = tid * 16;
    float4 R[4];
    #pragma unroll
    for (int q = 0; q < 4; q++) R[q] = make_float4(0.f, 0.f, 0.f, 0.f);
    #pragma unroll 1
    for (int c = 0; c < NC; c++) {
        size_t off = (((size_t)b*NC + c)*NH + h) * (NN*NP) + e0;
        #pragma unroll
        for (int q = 0; q < 4; q++)
            *(float4*)&g_prev[off + q*4] = R[q];
        float a = g_cum[(size_t)((b*NH + h)*NC + c)*NL + NL - 1];
        float dec = __expf(a);
        #pragma unroll
        for (int q = 0; q < 4; q++) {
            float4 sv = *(const float4*)&g_states[off + q*4];
            R[q].x = fmaf(dec, R[q].x, sv.x);
            R[q].y = fmaf(dec, R[q].y, sv.y);
            R[q].z = fmaf(dec, R[q].z, sv.z);
            R[q].w = fmaf(dec, R[q].w, sv.w);
        }
    }
}

// ---------------------------------------------------------------------------
// Y kernel: per (b,c,h,l-tile of 64)
// ---------------------------------------------------------------------------
__global__ __launch_bounds__(256) void y_kernel(const float* __restrict__ x,
                                                const float* __restrict__ Dvec)
{
    __shared__ float Cs[64*64];
    __shared__ float BG[64*64];
    __shared__ float XS[64*64];
    int bid = blockIdx.x;
    int lt = bid & 3;
    int h  = (bid >> 2) & 31;
    int c  = (bid >> 7) & 15;
    int b  = bid >> 11;
    const int tid = threadIdx.x;
    const int tn = tid & 15, tm = tid >> 4;
    const int t0 = c * NL;

    { // load C tile and prev-state S[n][p]
        const float* S = &g_prev[(((size_t)b*NC + c)*NH + h) * (NN*NP)];
        int v = tid;
        #pragma unroll
        for (int it = 0; it < 4; it++, v += 256) {
            int row = v >> 4, c4 = (v & 15) * 4;
            *(float4*)&Cs[row*64 + c4] =
                *(const float4*)&g_C[(size_t)(b*NT + t0 + lt*64 + row)*NN + c4];
            *(float4*)&BG[row*64 + c4] = *(const float4*)&S[row*64 + c4];
        }
    }
    __syncthreads();

    const float* cumc = &g_cum[(size_t)((b*NH + h)*NC + c) * NL];
    float cum_l[4], e_l[4];
    #pragma unroll
    for (int i = 0; i < 4; i++) {
        cum_l[i] = cumc[lt*64 + tm*4 + i];
        e_l[i]   = __expf(cum_l[i]);
    }

    float acc[4][4] = {};
    // ---- Y_off = C @ S_prev, scaled by exp(cum_l) afterwards
    #pragma unroll 8
    for (int n = 0; n < 64; n++) {
        float a[4], bb[4];
        #pragma unroll
        for (int i = 0; i < 4; i++) a[i] = Cs[(tm*4+i)*64 + n];
        #pragma unroll
        for (int j = 0; j < 4; j++) bb[j] = BG[n*64 + tn*4 + j];
        #pragma unroll
        for (int i = 0; i < 4; i++)
            #pragma unroll
            for (int j = 0; j < 4; j++)
                acc[i][j] = fmaf(a[i], bb[j], acc[i][j]);
    }
    #pragma unroll
    for (int i = 0; i < 4; i++)
        #pragma unroll
        for (int j = 0; j < 4; j++)
            acc[i][j] *= e_l[i];

    // ---- causal s-tiles
    for (int st = 0; st <= lt; st++) {
        __syncthreads();
        { // load B (xor-swizzled rows) and xdt tile
            int v = tid;
            #pragma unroll
            for (int it = 0; it < 4; it++, v += 256) {
                int row = v >> 4, c4 = (v & 15) * 4;
                int gt = t0 + st*64 + row;
                float4 bv = *(const float4*)&g_B[(size_t)(b*NT + gt)*NN + c4];
                BG[row*64 + ((c4+0+row)&63)] = bv.x;
                BG[row*64 + ((c4+1+row)&63)] = bv.y;
                BG[row*64 + ((c4+2+row)&63)] = bv.z;
                BG[row*64 + ((c4+3+row)&63)] = bv.w;
                float dtv = g_dt[(size_t)(b*NT + gt)*NH + h];
                float4 xv = *(const float4*)&x[(size_t)(b*NT + gt)*ND + h*NP + c4];
                *(float4*)&XS[row*64 + c4] =
                    make_float4(xv.x*dtv, xv.y*dtv, xv.z*dtv, xv.w*dtv);
            }
        }
        __syncthreads();

        // G = C @ B^T
        float g[4][4] = {};
        #pragma unroll 8
        for (int n = 0; n < 64; n++) {
            float a[4], bb[4];
            #pragma unroll
            for (int i = 0; i < 4; i++) a[i] = Cs[(tm*4+i)*64 + n];
            #pragma unroll
            for (int j = 0; j < 4; j++) {
                int sj = tn*4 + j;
                bb[j] = BG[sj*64 + ((n + sj)&63)];
            }
            #pragma unroll
            for (int i = 0; i < 4; i++)
                #pragma unroll
                for (int j = 0; j < 4; j++)
                    g[i][j] = fmaf(a[i], bb[j], g[i][j]);
        }
        float cum_s[4];
        #pragma unroll
        for (int j = 0; j < 4; j++) cum_s[j] = cumc[st*64 + tn*4 + j];
        if (st < lt) {
            #pragma unroll
            for (int i = 0; i < 4; i++)
                #pragma unroll
                for (int j = 0; j < 4; j++)
                    g[i][j] *= __expf(cum_l[i] - cum_s[j]);
        } else {
            #pragma unroll
            for (int i = 0; i < 4; i++)
                #pragma unroll
                for (int j = 0; j < 4; j++) {
                    int l = tm*4 + i, s = tn*4 + j;
                    g[i][j] = (s <= l) ? g[i][j] * __expf(cum_l[i] - cum_s[j]) : 0.f;
                }
        }
        __syncthreads();
        #pragma unroll
        for (int i = 0; i < 4; i++)
            #pragma unroll
            for (int j = 0; j < 4; j++)
                BG[(tm*4+i)*64 + tn*4 + j] = g[i][j];
        __syncthreads();

        // Y += G @ XS
        #pragma unroll 8
        for (int k = 0; k < 64; k++) {
            float a[4], bb[4];
            #pragma unroll
            for (int i = 0; i < 4; i++) a[i] = BG[(tm*4+i)*64 + k];
            #pragma unroll
            for (int j = 0; j < 4; j++) bb[j] = XS[k*64 + tn*4 + j];
            #pragma unroll
            for (int i = 0; i < 4; i++)
                #pragma unroll
                for (int j = 0; j < 4; j++)
                    acc[i][j] = fmaf(a[i], bb[j], acc[i][j]);
        }
    }

    float Dh = Dvec[h];
    #pragma unroll
    for (int i = 0; i < 4; i++) {
        int gt = t0 + lt*64 + tm*4 + i;
        size_t ro = (size_t)(b*NT + gt)*ND + h*NP;
        #pragma unroll
        for (int j = 0; j < 4; j++) {
            int p = tn*4 + j;
            g_Y[ro + p] = acc[i][j] + Dh * x[ro + p];
        }
    }
}

// ---------------------------------------------------------------------------
// Output projection, TF32 tensor cores:
//   out[M,N] = g_Y[M,K] @ out_w[N,K]^T + out_b
// CTA tile 128x128x32, 8 warps (2x4), warp tile 64x32, mma.m16n8k8 tf32.
// W is [N,K] row-major -> matches the .col B-fragment layout directly.
// ---------------------------------------------------------------------------
__global__ __launch_bounds__(256) void out_gemm_tf32(
    const float* __restrict__ W, const float* __restrict__ bias,
    float* __restrict__ out)
{
    __shared__ float As[128][36];   // [m][k], pad 36 -> conflict-free frag loads
    __shared__ float Ws[128][36];   // [n][k]
    const int tid  = threadIdx.x;
    const int wid  = tid >> 5, lane = tid & 31;
    const int warp_m = wid >> 2, warp_n = wid & 3;   // 2 x 4
    const int m0 = blockIdx.y * 128, n0 = blockIdx.x * 128;
    const int qrow = tid >> 3;            // 0..31
    const int qc4  = (tid & 7) * 4;       // 0..28
    const int lg = lane >> 2, lq = lane & 3;
    const float* A = g_Y;

    float acc[4][4][4];
    #pragma unroll
    for (int i = 0; i < 4; i++)
        #pragma unroll
        for (int j = 0; j < 4; j++)
            #pragma unroll
            for (int q = 0; q < 4; q++) acc[i][j][q] = 0.f;

    for (int k0 = 0; k0 < ND; k0 += 32) {
        #pragma unroll
        for (int it = 0; it < 4; it++) {
            int r = qrow + it * 32;
            float4 av = *(const float4*)&A[(size_t)(m0 + r) * ND + k0 + qc4];
            float4 wv = *(const float4*)&W[(size_t)(n0 + r) * ND + k0 + qc4];
            As[r][qc4+0] = to_tf32(av.x); As[r][qc4+1] = to_tf32(av.y);
            As[r][qc4+2] = to_tf32(av.z); As[r][qc4+3] = to_tf32(av.w);
            Ws[r][qc4+0] = to_tf32(wv.x); Ws[r][qc4+1] = to_tf32(wv.y);
            Ws[r][qc4+2] = to_tf32(wv.z); Ws[r][qc4+3] = to_tf32(wv.w);
        }
        __syncthreads();

        #pragma unroll
        for (int kk = 0; kk < 32; kk += 8) {
            uint32_t afr[4][4], bfr[4][2];
            #pragma unroll
            for (int i = 0; i < 4; i++) {
                int row = warp_m*64 + i*16 + lg;
                afr[i][0] = __float_as_uint(As[row    ][kk + lq]);
                afr[i][1] = __float_as_uint(As[row + 8][kk + lq]);
                afr[i][2] = __float_as_uint(As[row    ][kk + 4 + lq]);
                afr[i][3] = __float_as_uint(As[row + 8][kk + 4 + lq]);
            }
            #pragma unroll
            for (int j = 0; j < 4; j++) {
                int nrow = warp_n*32 + j*8 + lg;
                bfr[j][0] = __float_as_uint(Ws[nrow][kk + lq]);
                bfr[j][1] = __float_as_uint(Ws[nrow][kk + 4 + lq]);
            }
            #pragma unroll
            for (int i = 0; i < 4; i++)
                #pragma unroll
                for (int j = 0; j < 4; j++) {
                    asm volatile(
                        "mma.sync.aligned.m16n8k8.row.col.f32.tf32.tf32.f32 "
                        "{%0,%1,%2,%3}, {%4,%5,%6,%7}, {%8,%9}, {%0,%1,%2,%3};"
                        : "+f"(acc[i][j][0]), "+f"(acc[i][j][1]),
                          "+f"(acc[i][j][2]), "+f"(acc[i][j][3])
                        : "r"(afr[i][0]), "r"(afr[i][1]),
                          "r"(afr[i][2]), "r"(afr[i][3]),
                          "r"(bfr[j][0]), "r"(bfr[j][1]));
                }
        }
        __syncthreads();
    }

    // epilogue: c-frag layout -> gmem (+bias)
    #pragma unroll
    for (int i = 0; i < 4; i++) {
        int r0 = m0 + warp_m*64 + i*16 + lg;
        #pragma unroll
        for (int j = 0; j < 4; j++) {
            int cc = n0 + warp_n*32 + j*8 + lq*2;
            float b0 = bias[cc], b1 = bias[cc+1];
            out[(size_t)r0       * ND + cc    ] = acc[i][j][0] + b0;
            out[(size_t)r0       * ND + cc + 1] = acc[i][j][1] + b1;
            out[(size_t)(r0 + 8) * ND + cc    ] = acc[i][j][2] + b0;
            out[(size_t)(r0 + 8) * ND + cc + 1] = acc[i][j][3] + b1;
        }
    }
}

// ---------------------------------------------------------------------------
extern "C" void kernel_launch(void* const* d_in, const int* in_sizes, int n_in,
                              void* d_out, int out_size)
{
    const float* x     = (const float*)d_in[0];
    const float* A_log = (const float*)d_in[1];
    const float* Dvec  = (const float*)d_in[2];
    const float* B_w   = (const float*)d_in[3];
    const float* B_b   = (const float*)d_in[4];
    const float* C_w   = (const float*)d_in[5];
    const float* C_b   = (const float*)d_in[6];
    const float* dt_w  = (const float*)d_in[7];
    const float* dt_b  = (const float*)d_in[8];
    const float* out_w = (const float*)d_in[9];
    const float* out_b = (const float*)d_in[10];
    float* out = (float*)d_out;

    proj_gemm<<<dim3(1, NTOK/64), 256>>>(x, B_w, B_b, NTOK, NN, ND, 0);
    proj_gemm<<<dim3(1, NTOK/64), 256>>>(x, C_w, C_b, NTOK, NN, ND, 1);
    proj_gemm<<<dim3(1, NTOK/64), 256>>>(x, dt_w, dt_b, NTOK, NH, ND, 2);
    cumsum_kernel<<<NB*NH*NC, NL>>>(A_log);
    states_kernel<<<NB*NC*NH, 256>>>(x);
    scan_kernel<<<NB*NH, 256>>>();
    y_kernel<<<NB*NC*NH*4, 256>>>(x, Dvec);
    out_gemm_tf32<<<dim3(ND/128, NTOK/128), 256>>>(out_w, out_b, out);
}

// round 5
// speedup vs baseline: 1.7968x; 1.0320x over previous
#include <cuda_runtime.h>
#include <cstdint>
#include <math.h>

#define NB 2
#define NT 4096
#define ND 2048
#define NH 32
#define NN 64
#define NP 64
#define NL 256
#define NC 16
#define NTOK (NB*NT)   // 8192

// swizzled [64][64] accessor: 4-group-preserving, conflict-free fragment reads
#define SW(r,c) (((r)<<6) + ((c) ^ (((r)&15)<<2)))

// ---------------- scratch (device globals; no runtime allocation) ----------
__device__ float g_B[(size_t)NTOK*NN];
__device__ float g_C[(size_t)NTOK*NN];
__device__ float g_dt[(size_t)NTOK*NH];
__device__ float g_cum[(size_t)NB*NH*NC*NL];
__device__ float g_states[(size_t)NB*NC*NH*NN*NP];
__device__ float g_prev[(size_t)NB*NC*NH*NN*NP];
__device__ float g_Y[(size_t)NTOK*ND];

__device__ __forceinline__ float softplus_f(float v) {
    return v > 20.f ? v : log1pf(expf(v));
}

__device__ __forceinline__ float to_tf32(float v) {
    uint32_t u;
    asm("cvt.rna.tf32.f32 %0, %1;" : "=r"(u) : "f"(v));
    return __uint_as_float(u);
}

__device__ __forceinline__ void split_tf32(float v, uint32_t& hi, uint32_t& lo) {
    uint32_t h;
    asm("cvt.rna.tf32.f32 %0, %1;" : "=r"(h) : "f"(v));
    float r = v - __uint_as_float(h);
    uint32_t l;
    asm("cvt.rna.tf32.f32 %0, %1;" : "=r"(l) : "f"(r));
    hi = h; lo = l;
}

__device__ __forceinline__ void mma_tf32(float* d, const uint32_t* a, const uint32_t* b) {
    asm volatile(
        "mma.sync.aligned.m16n8k8.row.col.f32.tf32.tf32.f32 "
        "{%0,%1,%2,%3}, {%4,%5,%6,%7}, {%8,%9}, {%0,%1,%2,%3};"
        : "+f"(d[0]), "+f"(d[1]), "+f"(d[2]), "+f"(d[3])
        : "r"(a[0]), "r"(a[1]), "r"(a[2]), "r"(a[3]),
          "r"(b[0]), "r"(b[1]));
}

// ---------------------------------------------------------------------------
// Fused B+C projection, TF32: [g_B | g_C](M,128) = x(M,2048) @ [B_w;C_w]^T
// BM=64, BN=128, BK=32; 8 warps (2m x 4n), warp tile 32x32.
// ---------------------------------------------------------------------------
__global__ __launch_bounds__(256) void proj_bc_tf32(
    const float* __restrict__ x,
    const float* __restrict__ B_w, const float* __restrict__ B_b,
    const float* __restrict__ C_w, const float* __restrict__ C_b)
{
    __shared__ float As[64*36];
    __shared__ float Ws[128*36];
    const int tid = threadIdx.x;
    const int wid = tid >> 5, lane = tid & 31;
    const int wm = wid >> 2, wn = wid & 3;
    const int lg = lane >> 2, lq = lane & 3;
    const int m0 = blockIdx.x * 64;

    float acc[2][4][4];
    #pragma unroll
    for (int i = 0; i < 2; i++)
        #pragma unroll
        for (int j = 0; j < 4; j++)
            #pragma unroll
            for (int q = 0; q < 4; q++) acc[i][j][q] = 0.f;

    for (int k0 = 0; k0 < ND; k0 += 32) {
        {   // As: 64x32
            int v = tid;
            #pragma unroll
            for (int it = 0; it < 2; it++, v += 256) {
                int row = v >> 3, c4 = (v & 7) * 4;
                float4 av = *(const float4*)&x[(size_t)(m0 + row) * ND + k0 + c4];
                float4 t = make_float4(to_tf32(av.x), to_tf32(av.y),
                                       to_tf32(av.z), to_tf32(av.w));
                *(float4*)&As[row*36 + c4] = t;
            }
            // Ws: 128x32 (rows 0-63 = B_w, 64-127 = C_w)
            v = tid;
            #pragma unroll
            for (int it = 0; it < 4; it++, v += 256) {
                int row = v >> 3, c4 = (v & 7) * 4;
                const float* Wp = (row < 64) ? &B_w[(size_t)row * ND]
                                             : &C_w[(size_t)(row - 64) * ND];
                float4 wv = *(const float4*)&Wp[k0 + c4];
                float4 t = make_float4(to_tf32(wv.x), to_tf32(wv.y),
                                       to_tf32(wv.z), to_tf32(wv.w));
                *(float4*)&Ws[row*36 + c4] = t;
            }
        }
        __syncthreads();
        #pragma unroll
        for (int kk = 0; kk < 32; kk += 8) {
            uint32_t af[2][4], bf[4][2];
            #pragma unroll
            for (int i = 0; i < 2; i++) {
                int r = wm*32 + i*16 + lg;
                af[i][0] = __float_as_uint(As[r*36 + kk + lq]);
                af[i][1] = __float_as_uint(As[(r+8)*36 + kk + lq]);
                af[i][2] = __float_as_uint(As[r*36 + kk + 4 + lq]);
                af[i][3] = __float_as_uint(As[(r+8)*36 + kk + 4 + lq]);
            }
            #pragma unroll
            for (int j = 0; j < 4; j++) {
                int n = wn*32 + j*8 + lg;
                bf[j][0] = __float_as_uint(Ws[n*36 + kk + lq]);
                bf[j][1] = __float_as_uint(Ws[n*36 + kk + 4 + lq]);
            }
            #pragma unroll
            for (int i = 0; i < 2; i++)
                #pragma unroll
                for (int j = 0; j < 4; j++)
                    mma_tf32(acc[i][j], af[i], bf[j]);
        }
        __syncthreads();
    }
    #pragma unroll
    for (int i = 0; i < 2; i++) {
        int r = m0 + wm*32 + i*16 + lg;
        #pragma unroll
        for (int j = 0; j < 4; j++) {
            int n = wn*32 + j*8 + 2*lq;
            if (n < 64) {
                float b0 = B_b[n], b1 = B_b[n+1];
                g_B[(size_t)r*64 + n]       = acc[i][j][0] + b0;
                g_B[(size_t)r*64 + n + 1]   = acc[i][j][1] + b1;
                g_B[(size_t)(r+8)*64 + n]   = acc[i][j][2] + b0;
                g_B[(size_t)(r+8)*64 + n+1] = acc[i][j][3] + b1;
            } else {
                int n2 = n - 64;
                float b0 = C_b[n2], b1 = C_b[n2+1];
                g_C[(size_t)r*64 + n2]       = acc[i][j][0] + b0;
                g_C[(size_t)r*64 + n2 + 1]   = acc[i][j][1] + b1;
                g_C[(size_t)(r+8)*64 + n2]   = acc[i][j][2] + b0;
                g_C[(size_t)(r+8)*64 + n2+1] = acc[i][j][3] + b1;
            }
        }
    }
}

// ---------------------------------------------------------------------------
// Scalar projection GEMM (kept for dt, N=32): out = A @ W^T + bias, softplus
// ---------------------------------------------------------------------------
__global__ __launch_bounds__(256) void proj_gemm(
    const float* __restrict__ A, const float* __restrict__ W,
    const float* __restrict__ bias, int M, int N, int K, int osel)
{
    __shared__ float As[16][68];
    __shared__ float Ws[16][68];
    float* out = (osel == 0) ? g_B : (osel == 1) ? g_C : g_dt;
    const int tid = threadIdx.x;
    const int tn = tid & 15, tm = tid >> 4;
    const int m0 = blockIdx.y * 64, n0 = blockIdx.x * 64;
    const int lr = tid >> 2, lk = (tid & 3) * 4;
    float acc[4][4] = {};

    for (int k0 = 0; k0 < K; k0 += 16) {
        float4 av = *(const float4*)&A[(size_t)(m0 + lr) * K + k0 + lk];
        float4 wv = make_float4(0.f, 0.f, 0.f, 0.f);
        if (n0 + lr < N)
            wv = *(const float4*)&W[(size_t)(n0 + lr) * K + k0 + lk];
        As[lk+0][lr] = av.x; As[lk+1][lr] = av.y; As[lk+2][lr] = av.z; As[lk+3][lr] = av.w;
        Ws[lk+0][lr] = wv.x; Ws[lk+1][lr] = wv.y; Ws[lk+2][lr] = wv.z; Ws[lk+3][lr] = wv.w;
        __syncthreads();
        #pragma unroll
        for (int k = 0; k < 16; k++) {
            float a[4], b[4];
            #pragma unroll
            for (int i = 0; i < 4; i++) a[i] = As[k][tm*4+i];
            #pragma unroll
            for (int j = 0; j < 4; j++) b[j] = Ws[k][tn*4+j];
            #pragma unroll
            for (int i = 0; i < 4; i++)
                #pragma unroll
                for (int j = 0; j < 4; j++)
                    acc[i][j] = fmaf(a[i], b[j], acc[i][j]);
        }
        __syncthreads();
    }
    #pragma unroll
    for (int i = 0; i < 4; i++) {
        int m = m0 + tm*4 + i;
        #pragma unroll
        for (int j = 0; j < 4; j++) {
            int n = n0 + tn*4 + j;
            if (n < N) {
                float v = acc[i][j] + bias[n];
                if (osel == 2) v = softplus_f(v);
                out[(size_t)m * N + n] = v;
            }
        }
    }
}

// ---------------------------------------------------------------------------
// Per-(b,h,c) inclusive cumsum of dA = dt * A  over the chunk (L=256)
// ---------------------------------------------------------------------------
__global__ void cumsum_kernel(const float* __restrict__ A_log)
{
    __shared__ float sm[NL];
    int bid = blockIdx.x;
    int c = bid % NC, h = (bid / NC) % NH, b = bid / (NC * NH);
    int s = threadIdx.x;
    float Ah = -expf(A_log[h]);
    int t = c * NL + s;
    sm[s] = g_dt[(size_t)(b*NT + t)*NH + h] * Ah;
    __syncthreads();
    for (int off = 1; off < NL; off <<= 1) {
        float add = (s >= off) ? sm[s - off] : 0.f;
        __syncthreads();
        sm[s] += add;
        __syncthreads();
    }
    g_cum[(size_t)bid * NL + s] = sm[s];
}

// ---------------------------------------------------------------------------
// Chunk states: S[n,p] = sum_s B[s,n] * exp(cum_last - cum_s) * dt_s * x[s,p]
// ---------------------------------------------------------------------------
__global__ __launch_bounds__(256) void states_kernel(const float* __restrict__ x)
{
    __shared__ float Bs[64*64];
    __shared__ float XS[64*64];
    int bid = blockIdx.x;
    int h = bid % NH, c = (bid / NH) % NC, b = bid / (NH*NC);
    const int tid = threadIdx.x;
    const int tn = tid & 15, tm = tid >> 4;
    const float* cumc = &g_cum[(size_t)((b*NH + h)*NC + c) * NL];
    const float cum_last = cumc[NL-1];
    float acc[4][4] = {};

    for (int s0 = 0; s0 < NL; s0 += 64) {
        if (s0) __syncthreads();
        int v = tid;
        #pragma unroll
        for (int it = 0; it < 4; it++, v += 256) {
            int row = v >> 4, c4 = (v & 15) * 4;
            int gt = c*NL + s0 + row;
            float w = __expf(cum_last - cumc[s0 + row]) *
                      g_dt[(size_t)(b*NT + gt)*NH + h];
            float4 bv = *(const float4*)&g_B[(size_t)(b*NT + gt)*NN + c4];
            float4 xv = *(const float4*)&x[(size_t)(b*NT + gt)*ND + h*NP + c4];
            *(float4*)&Bs[row*64 + c4] = make_float4(bv.x*w, bv.y*w, bv.z*w, bv.w*w);
            *(float4*)&XS[row*64 + c4] = xv;
        }
        __syncthreads();
        #pragma unroll 8
        for (int s = 0; s < 64; s++) {
            float a[4], bb[4];
            #pragma unroll
            for (int i = 0; i < 4; i++) a[i] = Bs[s*64 + tm*4 + i];
            #pragma unroll
            for (int j = 0; j < 4; j++) bb[j] = XS[s*64 + tn*4 + j];
            #pragma unroll
            for (int i = 0; i < 4; i++)
                #pragma unroll
                for (int j = 0; j < 4; j++)
                    acc[i][j] = fmaf(a[i], bb[j], acc[i][j]);
        }
    }
    float* S = &g_states[(((size_t)b*NC + c)*NH + h) * (NN*NP)];
    #pragma unroll
    for (int i = 0; i < 4; i++)
        #pragma unroll
        for (int j = 0; j < 4; j++)
            S[(tm*4+i)*NP + tn*4 + j] = acc[i][j];
}

// ---------------------------------------------------------------------------
// Inter-chunk scan: prev[c] = R;  R = exp(a_c) * R + states[c]
// ---------------------------------------------------------------------------
__global__ void scan_kernel()
{
    int bid = blockIdx.x;                 // b*NH + h
    int h = bid % NH, b = bid / NH;
    int tid = threadIdx.x;
    int e0 = tid * 16;
    float4 R[4];
    #pragma unroll
    for (int q = 0; q < 4; q++) R[q] = make_float4(0.f, 0.f, 0.f, 0.f);
    #pragma unroll 1
    for (int c = 0; c < NC; c++) {
        size_t off = (((size_t)b*NC + c)*NH + h) * (NN*NP) + e0;
        #pragma unroll
        for (int q = 0; q < 4; q++)
            *(float4*)&g_prev[off + q*4] = R[q];
        float a = g_cum[(size_t)((b*NH + h)*NC + c)*NL + NL - 1];
        float dec = __expf(a);
        #pragma unroll
        for (int q = 0; q < 4; q++) {
            float4 sv = *(const float4*)&g_states[off + q*4];
            R[q].x = fmaf(dec, R[q].x, sv.x);
            R[q].y = fmaf(dec, R[q].y, sv.y);
            R[q].z = fmaf(dec, R[q].z, sv.z);
            R[q].w = fmaf(dec, R[q].w, sv.w);
        }
    }
}

// ---------------------------------------------------------------------------
// Y kernel (tensor-core, 3xTF32 for fp32-grade accuracy):
// per (b,c,h,l-tile of 64):
//   Y = exp(cum_l) * (C @ S_prev)
//     + sum_{st<=lt} ((C B^T) .* L) @ (x*dt)
//     + D_h * x
// 8 warps (4m x 2n), warp tile 16x32 (m16n8k8).
// Buffers: swizzled [64][64] (SW macro), 48KB smem total.
// ---------------------------------------------------------------------------
__global__ __launch_bounds__(256) void y_kernel_tc(const float* __restrict__ x,
                                                   const float* __restrict__ Dvec)
{
    __shared__ float Cs[64*64];    // C tile [l][n]
    __shared__ float BG[64*64];    // B tile [s][n], then G [l][s]
    __shared__ float XT[64*64];    // S^T [p][n] for Y_off; then (x*dt)^T [p][s]

    int bid = blockIdx.x;
    int lt = bid & 3;
    int h  = (bid >> 2) & 31;
    int c  = (bid >> 7) & 15;
    int b  = bid >> 11;
    const int tid = threadIdx.x;
    const int wid = tid >> 5, lane = tid & 31;
    const int wm = wid >> 1, wn = wid & 1;
    const int lg = lane >> 2, lq = lane & 3;
    const int t0 = c * NL;
    const float* cumc = &g_cum[(size_t)((b*NH + h)*NC + c) * NL];

    {   // load C tile and S_prev^T
        const float* S = &g_prev[(((size_t)b*NC + c)*NH + h) * (NN*NP)];
        int v = tid;
        #pragma unroll
        for (int it = 0; it < 4; it++, v += 256) {
            int row = v >> 4, c4 = (v & 15) * 4;
            float4 cv = *(const float4*)&g_C[(size_t)(b*NT + t0 + lt*64 + row)*NN + c4];
            *(float4*)&Cs[SW(row, c4)] = cv;
            float4 sv = *(const float4*)&S[row*64 + c4];   // S[n=row][p=c4+q]
            XT[SW(c4+0, row)] = sv.x;
            XT[SW(c4+1, row)] = sv.y;
            XT[SW(c4+2, row)] = sv.z;
            XT[SW(c4+3, row)] = sv.w;
        }
    }
    __syncthreads();

    // per-thread cum_l registers (rows wm*16+lg and +8 of this l-tile)
    const int lr0 = wm*16 + lg;
    const float cl0 = cumc[lt*64 + lr0];
    const float cl1 = cumc[lt*64 + lr0 + 8];

    float acc[4][4];
    #pragma unroll
    for (int j = 0; j < 4; j++)
        #pragma unroll
        for (int q = 0; q < 4; q++) acc[j][q] = 0.f;

    // ---- Y_off = C @ S_prev  (3xTF32)
    #pragma unroll
    for (int kk = 0; kk < 64; kk += 8) {
        uint32_t ah[4], al[4];
        split_tf32(Cs[SW(lr0,   kk + lq)],     ah[0], al[0]);
        split_tf32(Cs[SW(lr0+8, kk + lq)],     ah[1], al[1]);
        split_tf32(Cs[SW(lr0,   kk + 4 + lq)], ah[2], al[2]);
        split_tf32(Cs[SW(lr0+8, kk + 4 + lq)], ah[3], al[3]);
        #pragma unroll
        for (int j = 0; j < 4; j++) {
            int p = wn*32 + j*8 + lg;
            uint32_t bh[2], bl[2];
            split_tf32(XT[SW(p, kk + lq)],     bh[0], bl[0]);
            split_tf32(XT[SW(p, kk + 4 + lq)], bh[1], bl[1]);
            mma_tf32(acc[j], ah, bh);
            mma_tf32(acc[j], ah, bl);
            mma_tf32(acc[j], al, bh);
        }
    }
    {   // scale by exp(cum_l)
        float e0 = __expf(cl0), e1 = __expf(cl1);
        #pragma unroll
        for (int j = 0; j < 4; j++) {
            acc[j][0] *= e0; acc[j][1] *= e0;
            acc[j][2] *= e1; acc[j][3] *= e1;
        }
    }

    // ---- causal s-tiles
    for (int st = 0; st <= lt; st++) {
        __syncthreads();
        {   // load B tile [s][n] and (x*dt)^T [p][s]
            int v = tid;
            #pragma unroll
            for (int it = 0; it < 4; it++, v += 256) {
                int row = v >> 4, c4 = (v & 15) * 4;
                int gt = t0 + st*64 + row;
                float4 bv = *(const float4*)&g_B[(size_t)(b*NT + gt)*NN + c4];
                *(float4*)&BG[SW(row, c4)] = bv;
                float dtv = g_dt[(size_t)(b*NT + gt)*NH + h];
                float4 xv = *(const float4*)&x[(size_t)(b*NT + gt)*ND + h*NP + c4];
                XT[SW(c4+0, row)] = xv.x * dtv;
                XT[SW(c4+1, row)] = xv.y * dtv;
                XT[SW(c4+2, row)] = xv.z * dtv;
                XT[SW(c4+3, row)] = xv.w * dtv;
            }
        }
        __syncthreads();

        // G = C @ B^T  (3xTF32)
        float ga[4][4];
        #pragma unroll
        for (int j = 0; j < 4; j++)
            #pragma unroll
            for (int q = 0; q < 4; q++) ga[j][q] = 0.f;
        #pragma unroll
        for (int kk = 0; kk < 64; kk += 8) {
            uint32_t ah[4], al[4];
            split_tf32(Cs[SW(lr0,   kk + lq)],     ah[0], al[0]);
            split_tf32(Cs[SW(lr0+8, kk + lq)],     ah[1], al[1]);
            split_tf32(Cs[SW(lr0,   kk + 4 + lq)], ah[2], al[2]);
            split_tf32(Cs[SW(lr0+8, kk + 4 + lq)], ah[3], al[3]);
            #pragma unroll
            for (int j = 0; j < 4; j++) {
                int s = wn*32 + j*8 + lg;
                uint32_t bh[2], bl[2];
                split_tf32(BG[SW(s, kk + lq)],     bh[0], bl[0]);
                split_tf32(BG[SW(s, kk + 4 + lq)], bh[1], bl[1]);
                mma_tf32(ga[j], ah, bh);
                mma_tf32(ga[j], ah, bl);
                mma_tf32(ga[j], al, bh);
            }
        }
        // apply L = exp(cum_l - cum_s) (+ causal mask on diagonal tile)
        {
            int l0 = lr0, l1 = lr0 + 8;
            #pragma unroll
            for (int j = 0; j < 4; j++) {
                int s0c = wn*32 + j*8 + 2*lq;
                float cs0 = cumc[st*64 + s0c];
                float cs1 = cumc[st*64 + s0c + 1];
                if (st < lt) {
                    ga[j][0] *= __expf(cl0 - cs0);
                    ga[j][1] *= __expf(cl0 - cs1);
                    ga[j][2] *= __expf(cl1 - cs0);
                    ga[j][3] *= __expf(cl1 - cs1);
                } else {
                    ga[j][0] = (s0c     <= l0) ? ga[j][0] * __expf(cl0 - cs0) : 0.f;
                    ga[j][1] = (s0c + 1 <= l0) ? ga[j][1] * __expf(cl0 - cs1) : 0.f;
                    ga[j][2] = (s0c     <= l1) ? ga[j][2] * __expf(cl1 - cs0) : 0.f;
                    ga[j][3] = (s0c + 1 <= l1) ? ga[j][3] * __expf(cl1 - cs1) : 0.f;
                }
            }
        }
        __syncthreads();      // all warps done reading BG as B
        {   // write G into BG [l][s]
            #pragma unroll
            for (int j = 0; j < 4; j++) {
                int col = wn*32 + j*8 + 2*lq;
                BG[SW(lr0,   col)]     = ga[j][0];
                BG[SW(lr0,   col + 1)] = ga[j][1];
                BG[SW(lr0+8, col)]     = ga[j][2];
                BG[SW(lr0+8, col + 1)] = ga[j][3];
            }
        }
        __syncthreads();

        // Y += G @ (x*dt)   (A = BG [l][s], B = XT [p][s], 3xTF32)
        #pragma unroll
        for (int kk = 0; kk < 64; kk += 8) {
            uint32_t ah[4], al[4];
            split_tf32(BG[SW(lr0,   kk + lq)],     ah[0], al[0]);
            split_tf32(BG[SW(lr0+8, kk + lq)],     ah[1], al[1]);
            split_tf32(BG[SW(lr0,   kk + 4 + lq)], ah[2], al[2]);
            split_tf32(BG[SW(lr0+8, kk + 4 + lq)], ah[3], al[3]);
            #pragma unroll
            for (int j = 0; j < 4; j++) {
                int p = wn*32 + j*8 + lg;
                uint32_t bh[2], bl[2];
                split_tf32(XT[SW(p, kk + lq)],     bh[0], bl[0]);
                split_tf32(XT[SW(p, kk + 4 + lq)], bh[1], bl[1]);
                mma_tf32(acc[j], ah, bh);
                mma_tf32(acc[j], ah, bl);
                mma_tf32(acc[j], al, bh);
            }
        }
    }

    // ---- epilogue: + D_h * x, store
    float Dh = Dvec[h];
    int gt0 = t0 + lt*64 + lr0;
    #pragma unroll
    for (int j = 0; j < 4; j++) {
        int p = wn*32 + j*8 + 2*lq;
        size_t o0 = (size_t)(b*NT + gt0)*ND + h*NP + p;
        size_t o1 = o0 + (size_t)8*ND;
        g_Y[o0]     = acc[j][0] + Dh * x[o0];
        g_Y[o0 + 1] = acc[j][1] + Dh * x[o0 + 1];
        g_Y[o1]     = acc[j][2] + Dh * x[o1];
        g_Y[o1 + 1] = acc[j][3] + Dh * x[o1 + 1];
    }
}

// ---------------------------------------------------------------------------
// Output projection, TF32 tensor cores (unchanged, proven):
// ---------------------------------------------------------------------------
__global__ __launch_bounds__(256) void out_gemm_tf32(
    const float* __restrict__ W, const float* __restrict__ bias,
    float* __restrict__ out)
{
    __shared__ float As[128][36];
    __shared__ float Ws[128][36];
    const int tid  = threadIdx.x;
    const int wid  = tid >> 5, lane = tid & 31;
    const int warp_m = wid >> 2, warp_n = wid & 3;   // 2 x 4
    const int m0 = blockIdx.y * 128, n0 = blockIdx.x * 128;
    const int qrow = tid >> 3;
    const int qc4  = (tid & 7) * 4;
    const int lg = lane >> 2, lq = lane & 3;
    const float* A = g_Y;

    float acc[4][4][4];
    #pragma unroll
    for (int i = 0; i < 4; i++)
        #pragma unroll
        for (int j = 0; j < 4; j++)
            #pragma unroll
            for (int q = 0; q < 4; q++) acc[i][j][q] = 0.f;

    for (int k0 = 0; k0 < ND; k0 += 32) {
        #pragma unroll
        for (int it = 0; it < 4; it++) {
            int r = qrow + it * 32;
            float4 av = *(const float4*)&A[(size_t)(m0 + r) * ND + k0 + qc4];
            float4 wv = *(const float4*)&W[(size_t)(n0 + r) * ND + k0 + qc4];
            As[r][qc4+0] = to_tf32(av.x); As[r][qc4+1] = to_tf32(av.y);
            As[r][qc4+2] = to_tf32(av.z); As[r][qc4+3] = to_tf32(av.w);
            Ws[r][qc4+0] = to_tf32(wv.x); Ws[r][qc4+1] = to_tf32(wv.y);
            Ws[r][qc4+2] = to_tf32(wv.z); Ws[r][qc4+3] = to_tf32(wv.w);
        }
        __syncthreads();

        #pragma unroll
        for (int kk = 0; kk < 32; kk += 8) {
            uint32_t afr[4][4], bfr[4][2];
            #pragma unroll
            for (int i = 0; i < 4; i++) {
                int row = warp_m*64 + i*16 + lg;
                afr[i][0] = __float_as_uint(As[row    ][kk + lq]);
                afr[i][1] = __float_as_uint(As[row + 8][kk + lq]);
                afr[i][2] = __float_as_uint(As[row    ][kk + 4 + lq]);
                afr[i][3] = __float_as_uint(As[row + 8][kk + 4 + lq]);
            }
            #pragma unroll
            for (int j = 0; j < 4; j++) {
                int nrow = warp_n*32 + j*8 + lg;
                bfr[j][0] = __float_as_uint(Ws[nrow][kk + lq]);
                bfr[j][1] = __float_as_uint(Ws[nrow][kk + 4 + lq]);
            }
            #pragma unroll
            for (int i = 0; i < 4; i++)
                #pragma unroll
                for (int j = 0; j < 4; j++)
                    mma_tf32(acc[i][j], afr[i], bfr[j]);
        }
        __syncthreads();
    }

    #pragma unroll
    for (int i = 0; i < 4; i++) {
        int r0 = m0 + warp_m*64 + i*16 + lg;
        #pragma unroll
        for (int j = 0; j < 4; j++) {
            int cc = n0 + warp_n*32 + j*8 + lq*2;
            float b0 = bias[cc], b1 = bias[cc+1];
            out[(size_t)r0       * ND + cc    ] = acc[i][j][0] + b0;
            out[(size_t)r0       * ND + cc + 1] = acc[i][j][1] + b1;
            out[(size_t)(r0 + 8) * ND + cc    ] = acc[i][j][2] + b0;
            out[(size_t)(r0 + 8) * ND + cc + 1] = acc[i][j][3] + b1;
        }
    }
}

// ---------------------------------------------------------------------------
extern "C" void kernel_launch(void* const* d_in, const int* in_sizes, int n_in,
                              void* d_out, int out_size)
{
    const float* x     = (const float*)d_in[0];
    const float* A_log = (const float*)d_in[1];
    const float* Dvec  = (const float*)d_in[2];
    const float* B_w   = (const float*)d_in[3];
    const float* B_b   = (const float*)d_in[4];
    const float* C_w   = (const float*)d_in[5];
    const float* C_b   = (const float*)d_in[6];
    const float* dt_w  = (const float*)d_in[7];
    const float* dt_b  = (const float*)d_in[8];
    const float* out_w = (const float*)d_in[9];
    const float* out_b = (const float*)d_in[10];
    float* out = (float*)d_out;

    proj_bc_tf32<<<NTOK/64, 256>>>(x, B_w, B_b, C_w, C_b);
    proj_gemm<<<dim3(1, NTOK/64), 256>>>(x, dt_w, dt_b, NTOK, NH, ND, 2);
    cumsum_kernel<<<NB*NH*NC, NL>>>(A_log);
    states_kernel<<<NB*NC*NH, 256>>>(x);
    scan_kernel<<<NB*NH, 256>>>();
    y_kernel_tc<<<NB*NC*NH*4, 256>>>(x, Dvec);
    out_gemm_tf32<<<dim3(ND/128, NTOK/128), 256>>>(out_w, out_b, out);
}

// round 6
// speedup vs baseline: 2.1204x; 1.1801x over previous
#include <cuda_runtime.h>
#include <cstdint>
#include <math.h>

#define NB 2
#define NT 4096
#define ND 2048
#define NH 32
#define NN 64
#define NP 64
#define NL 256
#define NC 16
#define NTOK (NB*NT)   // 8192

// swizzled [64][64] accessor: 4-group-preserving, conflict-free fragment reads
#define SW(r,c) (((r)<<6) + ((c) ^ (((r)&15)<<2)))

// ---------------- scratch (device globals; no runtime allocation) ----------
__device__ float g_B[(size_t)NTOK*NN];
__device__ float g_C[(size_t)NTOK*NN];
__device__ float g_dt[(size_t)NTOK*NH];
__device__ float g_cum[(size_t)NB*NH*NC*NL];
__device__ float g_states[(size_t)NB*NC*NH*NN*NP];
__device__ float g_prev[(size_t)NB*NC*NH*NN*NP];
__device__ float g_Y[(size_t)NTOK*ND];

__device__ __forceinline__ float softplus_f(float v) {
    return v > 20.f ? v : log1pf(expf(v));
}

__device__ __forceinline__ float to_tf32(float v) {
    uint32_t u;
    asm("cvt.rna.tf32.f32 %0, %1;" : "=r"(u) : "f"(v));
    return __uint_as_float(u);
}

__device__ __forceinline__ void mma_tf32(float* d, const uint32_t* a, const uint32_t* b) {
    asm volatile(
        "mma.sync.aligned.m16n8k8.row.col.f32.tf32.tf32.f32 "
        "{%0,%1,%2,%3}, {%4,%5,%6,%7}, {%8,%9}, {%0,%1,%2,%3};"
        : "+f"(d[0]), "+f"(d[1]), "+f"(d[2]), "+f"(d[3])
        : "r"(a[0]), "r"(a[1]), "r"(a[2]), "r"(a[3]),
          "r"(b[0]), "r"(b[1]));
}

// ---------------------------------------------------------------------------
// Fused B+C projection, TF32: [g_B | g_C](M,128) = x(M,2048) @ [B_w;C_w]^T
// BM=64, BN=128, BK=32; 8 warps (2m x 4n), warp tile 32x32.
// ---------------------------------------------------------------------------
__global__ __launch_bounds__(256) void proj_bc_tf32(
    const float* __restrict__ x,
    const float* __restrict__ B_w, const float* __restrict__ B_b,
    const float* __restrict__ C_w, const float* __restrict__ C_b)
{
    __shared__ float As[64*36];
    __shared__ float Ws[128*36];
    const int tid = threadIdx.x;
    const int wid = tid >> 5, lane = tid & 31;
    const int wm = wid >> 2, wn = wid & 3;
    const int lg = lane >> 2, lq = lane & 3;
    const int m0 = blockIdx.x * 64;

    float acc[2][4][4];
    #pragma unroll
    for (int i = 0; i < 2; i++)
        #pragma unroll
        for (int j = 0; j < 4; j++)
            #pragma unroll
            for (int q = 0; q < 4; q++) acc[i][j][q] = 0.f;

    for (int k0 = 0; k0 < ND; k0 += 32) {
        {   // As: 64x32
            int v = tid;
            #pragma unroll
            for (int it = 0; it < 2; it++, v += 256) {
                int row = v >> 3, c4 = (v & 7) * 4;
                float4 av = *(const float4*)&x[(size_t)(m0 + row) * ND + k0 + c4];
                float4 t = make_float4(to_tf32(av.x), to_tf32(av.y),
                                       to_tf32(av.z), to_tf32(av.w));
                *(float4*)&As[row*36 + c4] = t;
            }
            // Ws: 128x32 (rows 0-63 = B_w, 64-127 = C_w)
            v = tid;
            #pragma unroll
            for (int it = 0; it < 4; it++, v += 256) {
                int row = v >> 3, c4 = (v & 7) * 4;
                const float* Wp = (row < 64) ? &B_w[(size_t)row * ND]
                                             : &C_w[(size_t)(row - 64) * ND];
                float4 wv = *(const float4*)&Wp[k0 + c4];
                float4 t = make_float4(to_tf32(wv.x), to_tf32(wv.y),
                                       to_tf32(wv.z), to_tf32(wv.w));
                *(float4*)&Ws[row*36 + c4] = t;
            }
        }
        __syncthreads();
        #pragma unroll
        for (int kk = 0; kk < 32; kk += 8) {
            uint32_t af[2][4], bf[4][2];
            #pragma unroll
            for (int i = 0; i < 2; i++) {
                int r = wm*32 + i*16 + lg;
                af[i][0] = __float_as_uint(As[r*36 + kk + lq]);
                af[i][1] = __float_as_uint(As[(r+8)*36 + kk + lq]);
                af[i][2] = __float_as_uint(As[r*36 + kk + 4 + lq]);
                af[i][3] = __float_as_uint(As[(r+8)*36 + kk + 4 + lq]);
            }
            #pragma unroll
            for (int j = 0; j < 4; j++) {
                int n = wn*32 + j*8 + lg;
                bf[j][0] = __float_as_uint(Ws[n*36 + kk + lq]);
                bf[j][1] = __float_as_uint(Ws[n*36 + kk + 4 + lq]);
            }
            #pragma unroll
            for (int i = 0; i < 2; i++)
                #pragma unroll
                for (int j = 0; j < 4; j++)
                    mma_tf32(acc[i][j], af[i], bf[j]);
        }
        __syncthreads();
    }
    #pragma unroll
    for (int i = 0; i < 2; i++) {
        int r = m0 + wm*32 + i*16 + lg;
        #pragma unroll
        for (int j = 0; j < 4; j++) {
            int n = wn*32 + j*8 + 2*lq;
            if (n < 64) {
                float b0 = B_b[n], b1 = B_b[n+1];
                g_B[(size_t)r*64 + n]       = acc[i][j][0] + b0;
                g_B[(size_t)r*64 + n + 1]   = acc[i][j][1] + b1;
                g_B[(size_t)(r+8)*64 + n]   = acc[i][j][2] + b0;
                g_B[(size_t)(r+8)*64 + n+1] = acc[i][j][3] + b1;
            } else {
                int n2 = n - 64;
                float b0 = C_b[n2], b1 = C_b[n2+1];
                g_C[(size_t)r*64 + n2]       = acc[i][j][0] + b0;
                g_C[(size_t)r*64 + n2 + 1]   = acc[i][j][1] + b1;
                g_C[(size_t)(r+8)*64 + n2]   = acc[i][j][2] + b0;
                g_C[(size_t)(r+8)*64 + n2+1] = acc[i][j][3] + b1;
            }
        }
    }
}

// ---------------------------------------------------------------------------
// Scalar projection GEMM (kept for dt, N=32): out = A @ W^T + bias, softplus
// ---------------------------------------------------------------------------
__global__ __launch_bounds__(256) void proj_gemm(
    const float* __restrict__ A, const float* __restrict__ W,
    const float* __restrict__ bias, int M, int N, int K, int osel)
{
    __shared__ float As[16][68];
    __shared__ float Ws[16][68];
    float* out = (osel == 0) ? g_B : (osel == 1) ? g_C : g_dt;
    const int tid = threadIdx.x;
    const int tn = tid & 15, tm = tid >> 4;
    const int m0 = blockIdx.y * 64, n0 = blockIdx.x * 64;
    const int lr = tid >> 2, lk = (tid & 3) * 4;
    float acc[4][4] = {};

    for (int k0 = 0; k0 < K; k0 += 16) {
        float4 av = *(const float4*)&A[(size_t)(m0 + lr) * K + k0 + lk];
        float4 wv = make_float4(0.f, 0.f, 0.f, 0.f);
        if (n0 + lr < N)
            wv = *(const float4*)&W[(size_t)(n0 + lr) * K + k0 + lk];
        As[lk+0][lr] = av.x; As[lk+1][lr] = av.y; As[lk+2][lr] = av.z; As[lk+3][lr] = av.w;
        Ws[lk+0][lr] = wv.x; Ws[lk+1][lr] = wv.y; Ws[lk+2][lr] = wv.z; Ws[lk+3][lr] = wv.w;
        __syncthreads();
        #pragma unroll
        for (int k = 0; k < 16; k++) {
            float a[4], b[4];
            #pragma unroll
            for (int i = 0; i < 4; i++) a[i] = As[k][tm*4+i];
            #pragma unroll
            for (int j = 0; j < 4; j++) b[j] = Ws[k][tn*4+j];
            #pragma unroll
            for (int i = 0; i < 4; i++)
                #pragma unroll
                for (int j = 0; j < 4; j++)
                    acc[i][j] = fmaf(a[i], b[j], acc[i][j]);
        }
        __syncthreads();
    }
    #pragma unroll
    for (int i = 0; i < 4; i++) {
        int m = m0 + tm*4 + i;
        #pragma unroll
        for (int j = 0; j < 4; j++) {
            int n = n0 + tn*4 + j;
            if (n < N) {
                float v = acc[i][j] + bias[n];
                if (osel == 2) v = softplus_f(v);
                out[(size_t)m * N + n] = v;
            }
        }
    }
}

// ---------------------------------------------------------------------------
// Per-(b,h,c) inclusive cumsum of dA = dt * A  over the chunk (L=256)
// ---------------------------------------------------------------------------
__global__ void cumsum_kernel(const float* __restrict__ A_log)
{
    __shared__ float sm[NL];
    int bid = blockIdx.x;
    int c = bid % NC, h = (bid / NC) % NH, b = bid / (NC * NH);
    int s = threadIdx.x;
    float Ah = -expf(A_log[h]);
    int t = c * NL + s;
    sm[s] = g_dt[(size_t)(b*NT + t)*NH + h] * Ah;
    __syncthreads();
    for (int off = 1; off < NL; off <<= 1) {
        float add = (s >= off) ? sm[s - off] : 0.f;
        __syncthreads();
        sm[s] += add;
        __syncthreads();
    }
    g_cum[(size_t)bid * NL + s] = sm[s];
}

// ---------------------------------------------------------------------------
// Chunk states: S[n,p] = sum_s B[s,n] * exp(cum_last - cum_s) * dt_s * x[s,p]
// ---------------------------------------------------------------------------
__global__ __launch_bounds__(256) void states_kernel(const float* __restrict__ x)
{
    __shared__ float Bs[64*64];
    __shared__ float XS[64*64];
    int bid = blockIdx.x;
    int h = bid % NH, c = (bid / NH) % NC, b = bid / (NH*NC);
    const int tid = threadIdx.x;
    const int tn = tid & 15, tm = tid >> 4;
    const float* cumc = &g_cum[(size_t)((b*NH + h)*NC + c) * NL];
    const float cum_last = cumc[NL-1];
    float acc[4][4] = {};

    for (int s0 = 0; s0 < NL; s0 += 64) {
        if (s0) __syncthreads();
        int v = tid;
        #pragma unroll
        for (int it = 0; it < 4; it++, v += 256) {
            int row = v >> 4, c4 = (v & 15) * 4;
            int gt = c*NL + s0 + row;
            float w = __expf(cum_last - cumc[s0 + row]) *
                      g_dt[(size_t)(b*NT + gt)*NH + h];
            float4 bv = *(const float4*)&g_B[(size_t)(b*NT + gt)*NN + c4];
            float4 xv = *(const float4*)&x[(size_t)(b*NT + gt)*ND + h*NP + c4];
            *(float4*)&Bs[row*64 + c4] = make_float4(bv.x*w, bv.y*w, bv.z*w, bv.w*w);
            *(float4*)&XS[row*64 + c4] = xv;
        }
        __syncthreads();
        #pragma unroll 8
        for (int s = 0; s < 64; s++) {
            float a[4], bb[4];
            #pragma unroll
            for (int i = 0; i < 4; i++) a[i] = Bs[s*64 + tm*4 + i];
            #pragma unroll
            for (int j = 0; j < 4; j++) bb[j] = XS[s*64 + tn*4 + j];
            #pragma unroll
            for (int i = 0; i < 4; i++)
                #pragma unroll
                for (int j = 0; j < 4; j++)
                    acc[i][j] = fmaf(a[i], bb[j], acc[i][j]);
        }
    }
    float* S = &g_states[(((size_t)b*NC + c)*NH + h) * (NN*NP)];
    #pragma unroll
    for (int i = 0; i < 4; i++)
        #pragma unroll
        for (int j = 0; j < 4; j++)
            S[(tm*4+i)*NP + tn*4 + j] = acc[i][j];
}

// ---------------------------------------------------------------------------
// Inter-chunk scan: prev[c] = R;  R = exp(a_c) * R + states[c]
// ---------------------------------------------------------------------------
__global__ void scan_kernel()
{
    int bid = blockIdx.x;                 // b*NH + h
    int h = bid % NH, b = bid / NH;
    int tid = threadIdx.x;
    int e0 = tid * 16;
    float4 R[4];
    #pragma unroll
    for (int q = 0; q < 4; q++) R[q] = make_float4(0.f, 0.f, 0.f, 0.f);
    #pragma unroll 1
    for (int c = 0; c < NC; c++) {
        size_t off = (((size_t)b*NC + c)*NH + h) * (NN*NP) + e0;
        #pragma unroll
        for (int q = 0; q < 4; q++)
            *(float4*)&g_prev[off + q*4] = R[q];
        float a = g_cum[(size_t)((b*NH + h)*NC + c)*NL + NL - 1];
        float dec = __expf(a);
        #pragma unroll
        for (int q = 0; q < 4; q++) {
            float4 sv = *(const float4*)&g_states[off + q*4];
            R[q].x = fmaf(dec, R[q].x, sv.x);
            R[q].y = fmaf(dec, R[q].y, sv.y);
            R[q].z = fmaf(dec, R[q].z, sv.z);
            R[q].w = fmaf(dec, R[q].w, sv.w);
        }
    }
}

// ---------------------------------------------------------------------------
// Y kernel (tensor-core, 1xTF32, cvt fused into smem stores):
// per (b,c,h,l-tile of 64):
//   Y = exp(cum_l) * (C @ S_prev)
//     + sum_{st<=lt} ((C B^T) .* L) @ (x*dt)
//     + D_h * x
// 8 warps (4m x 2n), warp tile 16x32 (m16n8k8).
// Buffers: swizzled [64][64] (SW macro), 48KB smem total.
// ---------------------------------------------------------------------------
__global__ __launch_bounds__(256) void y_kernel_tc(const float* __restrict__ x,
                                                   const float* __restrict__ Dvec)
{
    __shared__ float Cs[64*64];    // C tile [l][n] (tf32)
    __shared__ float BG[64*64];    // B tile [s][n] (tf32), then G [l][s] (tf32)
    __shared__ float XT[64*64];    // S^T [p][n]; then (x*dt)^T [p][s] (tf32)

    int bid = blockIdx.x;
    int lt = bid & 3;
    int h  = (bid >> 2) & 31;
    int c  = (bid >> 7) & 15;
    int b  = bid >> 11;
    const int tid = threadIdx.x;
    const int wid = tid >> 5, lane = tid & 31;
    const int wm = wid >> 1, wn = wid & 1;
    const int lg = lane >> 2, lq = lane & 3;
    const int t0 = c * NL;
    const float* cumc = &g_cum[(size_t)((b*NH + h)*NC + c) * NL];

    {   // load C tile and S_prev^T (tf32-rounded at store)
        const float* S = &g_prev[(((size_t)b*NC + c)*NH + h) * (NN*NP)];
        int v = tid;
        #pragma unroll
        for (int it = 0; it < 4; it++, v += 256) {
            int row = v >> 4, c4 = (v & 15) * 4;
            float4 cv = *(const float4*)&g_C[(size_t)(b*NT + t0 + lt*64 + row)*NN + c4];
            *(float4*)&Cs[SW(row, c4)] = make_float4(to_tf32(cv.x), to_tf32(cv.y),
                                                     to_tf32(cv.z), to_tf32(cv.w));
            float4 sv = *(const float4*)&S[row*64 + c4];   // S[n=row][p=c4+q]
            XT[SW(c4+0, row)] = to_tf32(sv.x);
            XT[SW(c4+1, row)] = to_tf32(sv.y);
            XT[SW(c4+2, row)] = to_tf32(sv.z);
            XT[SW(c4+3, row)] = to_tf32(sv.w);
        }
    }
    __syncthreads();

    // per-thread cum_l registers (rows wm*16+lg and +8 of this l-tile)
    const int lr0 = wm*16 + lg;
    const float cl0 = cumc[lt*64 + lr0];
    const float cl1 = cumc[lt*64 + lr0 + 8];

    float acc[4][4];
    #pragma unroll
    for (int j = 0; j < 4; j++)
        #pragma unroll
        for (int q = 0; q < 4; q++) acc[j][q] = 0.f;

    // ---- Y_off = C @ S_prev
    #pragma unroll
    for (int kk = 0; kk < 64; kk += 8) {
        uint32_t ah[4];
        ah[0] = __float_as_uint(Cs[SW(lr0,   kk + lq)]);
        ah[1] = __float_as_uint(Cs[SW(lr0+8, kk + lq)]);
        ah[2] = __float_as_uint(Cs[SW(lr0,   kk + 4 + lq)]);
        ah[3] = __float_as_uint(Cs[SW(lr0+8, kk + 4 + lq)]);
        #pragma unroll
        for (int j = 0; j < 4; j++) {
            int p = wn*32 + j*8 + lg;
            uint32_t bh[2];
            bh[0] = __float_as_uint(XT[SW(p, kk + lq)]);
            bh[1] = __float_as_uint(XT[SW(p, kk + 4 + lq)]);
            mma_tf32(acc[j], ah, bh);
        }
    }
    {   // scale by exp(cum_l)
        float e0 = __expf(cl0), e1 = __expf(cl1);
        #pragma unroll
        for (int j = 0; j < 4; j++) {
            acc[j][0] *= e0; acc[j][1] *= e0;
            acc[j][2] *= e1; acc[j][3] *= e1;
        }
    }

    // ---- causal s-tiles
    for (int st = 0; st <= lt; st++) {
        __syncthreads();
        {   // load B tile [s][n] and (x*dt)^T [p][s] (tf32-rounded)
            int v = tid;
            #pragma unroll
            for (int it = 0; it < 4; it++, v += 256) {
                int row = v >> 4, c4 = (v & 15) * 4;
                int gt = t0 + st*64 + row;
                float4 bv = *(const float4*)&g_B[(size_t)(b*NT + gt)*NN + c4];
                *(float4*)&BG[SW(row, c4)] = make_float4(to_tf32(bv.x), to_tf32(bv.y),
                                                         to_tf32(bv.z), to_tf32(bv.w));
                float dtv = g_dt[(size_t)(b*NT + gt)*NH + h];
                float4 xv = *(const float4*)&x[(size_t)(b*NT + gt)*ND + h*NP + c4];
                XT[SW(c4+0, row)] = to_tf32(xv.x * dtv);
                XT[SW(c4+1, row)] = to_tf32(xv.y * dtv);
                XT[SW(c4+2, row)] = to_tf32(xv.z * dtv);
                XT[SW(c4+3, row)] = to_tf32(xv.w * dtv);
            }
        }
        __syncthreads();

        // G = C @ B^T
        float ga[4][4];
        #pragma unroll
        for (int j = 0; j < 4; j++)
            #pragma unroll
            for (int q = 0; q < 4; q++) ga[j][q] = 0.f;
        #pragma unroll
        for (int kk = 0; kk < 64; kk += 8) {
            uint32_t ah[4];
            ah[0] = __float_as_uint(Cs[SW(lr0,   kk + lq)]);
            ah[1] = __float_as_uint(Cs[SW(lr0+8, kk + lq)]);
            ah[2] = __float_as_uint(Cs[SW(lr0,   kk + 4 + lq)]);
            ah[3] = __float_as_uint(Cs[SW(lr0+8, kk + 4 + lq)]);
            #pragma unroll
            for (int j = 0; j < 4; j++) {
                int s = wn*32 + j*8 + lg;
                uint32_t bh[2];
                bh[0] = __float_as_uint(BG[SW(s, kk + lq)]);
                bh[1] = __float_as_uint(BG[SW(s, kk + 4 + lq)]);
                mma_tf32(ga[j], ah, bh);
            }
        }
        // apply L = exp(cum_l - cum_s) (+ causal mask on diagonal tile)
        {
            int l0 = lr0, l1 = lr0 + 8;
            #pragma unroll
            for (int j = 0; j < 4; j++) {
                int s0c = wn*32 + j*8 + 2*lq;
                float cs0 = cumc[st*64 + s0c];
                float cs1 = cumc[st*64 + s0c + 1];
                if (st < lt) {
                    ga[j][0] *= __expf(cl0 - cs0);
                    ga[j][1] *= __expf(cl0 - cs1);
                    ga[j][2] *= __expf(cl1 - cs0);
                    ga[j][3] *= __expf(cl1 - cs1);
                } else {
                    ga[j][0] = (s0c     <= l0) ? ga[j][0] * __expf(cl0 - cs0) : 0.f;
                    ga[j][1] = (s0c + 1 <= l0) ? ga[j][1] * __expf(cl0 - cs1) : 0.f;
                    ga[j][2] = (s0c     <= l1) ? ga[j][2] * __expf(cl1 - cs0) : 0.f;
                    ga[j][3] = (s0c + 1 <= l1) ? ga[j][3] * __expf(cl1 - cs1) : 0.f;
                }
            }
        }
        __syncthreads();      // all warps done reading BG as B
        {   // write G into BG [l][s] (tf32-rounded)
            #pragma unroll
            for (int j = 0; j < 4; j++) {
                int col = wn*32 + j*8 + 2*lq;
                BG[SW(lr0,   col)]     = to_tf32(ga[j][0]);
                BG[SW(lr0,   col + 1)] = to_tf32(ga[j][1]);
                BG[SW(lr0+8, col)]     = to_tf32(ga[j][2]);
                BG[SW(lr0+8, col + 1)] = to_tf32(ga[j][3]);
            }
        }
        __syncthreads();

        // Y += G @ (x*dt)   (A = BG [l][s], B = XT [p][s])
        #pragma unroll
        for (int kk = 0; kk < 64; kk += 8) {
            uint32_t ah[4];
            ah[0] = __float_as_uint(BG[SW(lr0,   kk + lq)]);
            ah[1] = __float_as_uint(BG[SW(lr0+8, kk + lq)]);
            ah[2] = __float_as_uint(BG[SW(lr0,   kk + 4 + lq)]);
            ah[3] = __float_as_uint(BG[SW(lr0+8, kk + 4 + lq)]);
            #pragma unroll
            for (int j = 0; j < 4; j++) {
                int p = wn*32 + j*8 + lg;
                uint32_t bh[2];
                bh[0] = __float_as_uint(XT[SW(p, kk + lq)]);
                bh[1] = __float_as_uint(XT[SW(p, kk + 4 + lq)]);
                mma_tf32(acc[j], ah, bh);
            }
        }
    }

    // ---- epilogue: + D_h * x, store
    float Dh = Dvec[h];
    int gt0 = t0 + lt*64 + lr0;
    #pragma unroll
    for (int j = 0; j < 4; j++) {
        int p = wn*32 + j*8 + 2*lq;
        size_t o0 = (size_t)(b*NT + gt0)*ND + h*NP + p;
        size_t o1 = o0 + (size_t)8*ND;
        g_Y[o0]     = acc[j][0] + Dh * x[o0];
        g_Y[o0 + 1] = acc[j][1] + Dh * x[o0 + 1];
        g_Y[o1]     = acc[j][2] + Dh * x[o1];
        g_Y[o1 + 1] = acc[j][3] + Dh * x[o1 + 1];
    }
}

// ---------------------------------------------------------------------------
// Output projection, TF32 tensor cores, register-prefetch pipelined:
//   out[M,N] = g_Y[M,K] @ out_w[N,K]^T + out_b
// CTA tile 128x128x32, 8 warps (2x4), warp tile 64x32, mma.m16n8k8.
// ---------------------------------------------------------------------------
__global__ __launch_bounds__(256) void out_gemm_tf32(
    const float* __restrict__ W, const float* __restrict__ bias,
    float* __restrict__ out)
{
    __shared__ float As[128][36];
    __shared__ float Ws[128][36];
    const int tid  = threadIdx.x;
    const int wid  = tid >> 5, lane = tid & 31;
    const int warp_m = wid >> 2, warp_n = wid & 3;   // 2 x 4
    const int m0 = blockIdx.y * 128, n0 = blockIdx.x * 128;
    const int qrow = tid >> 3;
    const int qc4  = (tid & 7) * 4;
    const int lg = lane >> 2, lq = lane & 3;
    const float* A = g_Y;

    float acc[4][4][4];
    #pragma unroll
    for (int i = 0; i < 4; i++)
        #pragma unroll
        for (int j = 0; j < 4; j++)
            #pragma unroll
            for (int q = 0; q < 4; q++) acc[i][j][q] = 0.f;

    // prefetch k0 = 0
    float4 pa[4], pw[4];
    #pragma unroll
    for (int it = 0; it < 4; it++) {
        int r = qrow + it * 32;
        pa[it] = *(const float4*)&A[(size_t)(m0 + r) * ND + qc4];
        pw[it] = *(const float4*)&W[(size_t)(n0 + r) * ND + qc4];
    }

    for (int k0 = 0; k0 < ND; k0 += 32) {
        // store prefetched regs -> smem (tf32)
        #pragma unroll
        for (int it = 0; it < 4; it++) {
            int r = qrow + it * 32;
            As[r][qc4+0] = to_tf32(pa[it].x); As[r][qc4+1] = to_tf32(pa[it].y);
            As[r][qc4+2] = to_tf32(pa[it].z); As[r][qc4+3] = to_tf32(pa[it].w);
            Ws[r][qc4+0] = to_tf32(pw[it].x); Ws[r][qc4+1] = to_tf32(pw[it].y);
            Ws[r][qc4+2] = to_tf32(pw[it].z); Ws[r][qc4+3] = to_tf32(pw[it].w);
        }
        __syncthreads();

        // issue next prefetch (latency hidden behind mma loop)
        if (k0 + 32 < ND) {
            #pragma unroll
            for (int it = 0; it < 4; it++) {
                int r = qrow + it * 32;
                pa[it] = *(const float4*)&A[(size_t)(m0 + r) * ND + k0 + 32 + qc4];
                pw[it] = *(const float4*)&W[(size_t)(n0 + r) * ND + k0 + 32 + qc4];
            }
        }

        #pragma unroll
        for (int kk = 0; kk < 32; kk += 8) {
            uint32_t afr[4][4], bfr[4][2];
            #pragma unroll
            for (int i = 0; i < 4; i++) {
                int row = warp_m*64 + i*16 + lg;
                afr[i][0] = __float_as_uint(As[row    ][kk + lq]);
                afr[i][1] = __float_as_uint(As[row + 8][kk + lq]);
                afr[i][2] = __float_as_uint(As[row    ][kk + 4 + lq]);
                afr[i][3] = __float_as_uint(As[row + 8][kk + 4 + lq]);
            }
            #pragma unroll
            for (int j = 0; j < 4; j++) {
                int nrow = warp_n*32 + j*8 + lg;
                bfr[j][0] = __float_as_uint(Ws[nrow][kk + lq]);
                bfr[j][1] = __float_as_uint(Ws[nrow][kk + 4 + lq]);
            }
            #pragma unroll
            for (int i = 0; i < 4; i++)
                #pragma unroll
                for (int j = 0; j < 4; j++)
                    mma_tf32(acc[i][j], afr[i], bfr[j]);
        }
        __syncthreads();
    }

    #pragma unroll
    for (int i = 0; i < 4; i++) {
        int r0 = m0 + warp_m*64 + i*16 + lg;
        #pragma unroll
        for (int j = 0; j < 4; j++) {
            int cc = n0 + warp_n*32 + j*8 + lq*2;
            float b0 = bias[cc], b1 = bias[cc+1];
            out[(size_t)r0       * ND + cc    ] = acc[i][j][0] + b0;
            out[(size_t)r0       * ND + cc + 1] = acc[i][j][1] + b1;
            out[(size_t)(r0 + 8) * ND + cc    ] = acc[i][j][2] + b0;
            out[(size_t)(r0 + 8) * ND + cc + 1] = acc[i][j][3] + b1;
        }
    }
}

// ---------------------------------------------------------------------------
extern "C" void kernel_launch(void* const* d_in, const int* in_sizes, int n_in,
                              void* d_out, int out_size)
{
    const float* x     = (const float*)d_in[0];
    const float* A_log = (const float*)d_in[1];
    const float* Dvec  = (const float*)d_in[2];
    const float* B_w   = (const float*)d_in[3];
    const float* B_b   = (const float*)d_in[4];
    const float* C_w   = (const float*)d_in[5];
    const float* C_b   = (const float*)d_in[6];
    const float* dt_w  = (const float*)d_in[7];
    const float* dt_b  = (const float*)d_in[8];
    const float* out_w = (const float*)d_in[9];
    const float* out_b = (const float*)d_in[10];
    float* out = (float*)d_out;

    proj_bc_tf32<<<NTOK/64, 256>>>(x, B_w, B_b, C_w, C_b);
    proj_gemm<<<dim3(1, NTOK/64), 256>>>(x, dt_w, dt_b, NTOK, NH, ND, 2);
    cumsum_kernel<<<NB*NH*NC, NL>>>(A_log);
    states_kernel<<<NB*NC*NH, 256>>>(x);
    scan_kernel<<<NB*NH, 256>>>();
    y_kernel_tc<<<NB*NC*NH*4, 256>>>(x, Dvec);
    out_gemm_tf32<<<dim3(ND/128, NTOK/128), 256>>>(out_w, out_b, out);
}

// round 8
// speedup vs baseline: 2.2138x; 1.0440x over previous
#include <cuda_runtime.h>
#include <cstdint>
#include <math.h>

#define NB 2
#define NT 4096
#define ND 2048
#define NH 32
#define NN 64
#define NP 64
#define NL 256
#define NC 16
#define NTOK (NB*NT)   // 8192

// swizzled [64][64] accessor: 4-group-preserving, conflict-free fragment reads
#define SW(r,c) (((r)<<6) + ((c) ^ (((r)&15)<<2)))

// ---------------- scratch (device globals; no runtime allocation) ----------
__device__ float g_B[(size_t)NTOK*NN];
__device__ float g_C[(size_t)NTOK*NN];
__device__ float g_dt[(size_t)NTOK*NH];
__device__ float g_cum[(size_t)NB*NH*NC*NL];
__device__ float g_states[(size_t)NB*NC*NH*NN*NP];
__device__ float g_prev[(size_t)NB*NC*NH*NN*NP];
__device__ float g_Y[(size_t)NTOK*ND];

__device__ __forceinline__ float softplus_f(float v) {
    return v > 20.f ? v : log1pf(expf(v));
}

__device__ __forceinline__ float to_tf32(float v) {
    uint32_t u;
    asm("cvt.rna.tf32.f32 %0, %1;" : "=r"(u) : "f"(v));
    return __uint_as_float(u);
}

__device__ __forceinline__ void mma_tf32(float* d, const uint32_t* a, const uint32_t* b) {
    asm volatile(
        "mma.sync.aligned.m16n8k8.row.col.f32.tf32.tf32.f32 "
        "{%0,%1,%2,%3}, {%4,%5,%6,%7}, {%8,%9}, {%0,%1,%2,%3};"
        : "+f"(d[0]), "+f"(d[1]), "+f"(d[2]), "+f"(d[3])
        : "r"(a[0]), "r"(a[1]), "r"(a[2]), "r"(a[3]),
          "r"(b[0]), "r"(b[1]));
}

// ---------------------------------------------------------------------------
// Fused B+C projection, TF32: [g_B | g_C](M,128) = x(M,2048) @ [B_w;C_w]^T
// ---------------------------------------------------------------------------
__global__ __launch_bounds__(256) void proj_bc_tf32(
    const float* __restrict__ x,
    const float* __restrict__ B_w, const float* __restrict__ B_b,
    const float* __restrict__ C_w, const float* __restrict__ C_b)
{
    __shared__ float As[64*36];
    __shared__ float Ws[128*36];
    const int tid = threadIdx.x;
    const int wid = tid >> 5, lane = tid & 31;
    const int wm = wid >> 2, wn = wid & 3;
    const int lg = lane >> 2, lq = lane & 3;
    const int m0 = blockIdx.x * 64;

    float acc[2][4][4];
    #pragma unroll
    for (int i = 0; i < 2; i++)
        #pragma unroll
        for (int j = 0; j < 4; j++)
            #pragma unroll
            for (int q = 0; q < 4; q++) acc[i][j][q] = 0.f;

    for (int k0 = 0; k0 < ND; k0 += 32) {
        {
            int v = tid;
            #pragma unroll
            for (int it = 0; it < 2; it++, v += 256) {
                int row = v >> 3, c4 = (v & 7) * 4;
                float4 av = *(const float4*)&x[(size_t)(m0 + row) * ND + k0 + c4];
                float4 t = make_float4(to_tf32(av.x), to_tf32(av.y),
                                       to_tf32(av.z), to_tf32(av.w));
                *(float4*)&As[row*36 + c4] = t;
            }
            v = tid;
            #pragma unroll
            for (int it = 0; it < 4; it++, v += 256) {
                int row = v >> 3, c4 = (v & 7) * 4;
                const float* Wp = (row < 64) ? &B_w[(size_t)row * ND]
                                             : &C_w[(size_t)(row - 64) * ND];
                float4 wv = *(const float4*)&Wp[k0 + c4];
                float4 t = make_float4(to_tf32(wv.x), to_tf32(wv.y),
                                       to_tf32(wv.z), to_tf32(wv.w));
                *(float4*)&Ws[row*36 + c4] = t;
            }
        }
        __syncthreads();
        #pragma unroll
        for (int kk = 0; kk < 32; kk += 8) {
            uint32_t af[2][4], bf[4][2];
            #pragma unroll
            for (int i = 0; i < 2; i++) {
                int r = wm*32 + i*16 + lg;
                af[i][0] = __float_as_uint(As[r*36 + kk + lq]);
                af[i][1] = __float_as_uint(As[(r+8)*36 + kk + lq]);
                af[i][2] = __float_as_uint(As[r*36 + kk + 4 + lq]);
                af[i][3] = __float_as_uint(As[(r+8)*36 + kk + 4 + lq]);
            }
            #pragma unroll
            for (int j = 0; j < 4; j++) {
                int n = wn*32 + j*8 + lg;
                bf[j][0] = __float_as_uint(Ws[n*36 + kk + lq]);
                bf[j][1] = __float_as_uint(Ws[n*36 + kk + 4 + lq]);
            }
            #pragma unroll
            for (int i = 0; i < 2; i++)
                #pragma unroll
                for (int j = 0; j < 4; j++)
                    mma_tf32(acc[i][j], af[i], bf[j]);
        }
        __syncthreads();
    }
    #pragma unroll
    for (int i = 0; i < 2; i++) {
        int r = m0 + wm*32 + i*16 + lg;
        #pragma unroll
        for (int j = 0; j < 4; j++) {
            int n = wn*32 + j*8 + 2*lq;
            if (n < 64) {
                float b0 = B_b[n], b1 = B_b[n+1];
                g_B[(size_t)r*64 + n]       = acc[i][j][0] + b0;
                g_B[(size_t)r*64 + n + 1]   = acc[i][j][1] + b1;
                g_B[(size_t)(r+8)*64 + n]   = acc[i][j][2] + b0;
                g_B[(size_t)(r+8)*64 + n+1] = acc[i][j][3] + b1;
            } else {
                int n2 = n - 64;
                float b0 = C_b[n2], b1 = C_b[n2+1];
                g_C[(size_t)r*64 + n2]       = acc[i][j][0] + b0;
                g_C[(size_t)r*64 + n2 + 1]   = acc[i][j][1] + b1;
                g_C[(size_t)(r+8)*64 + n2]   = acc[i][j][2] + b0;
                g_C[(size_t)(r+8)*64 + n2+1] = acc[i][j][3] + b1;
            }
        }
    }
}

// ---------------------------------------------------------------------------
// Scalar projection GEMM (kept for dt, N=32): out = A @ W^T + bias, softplus
// ---------------------------------------------------------------------------
__global__ __launch_bounds__(256) void proj_gemm(
    const float* __restrict__ A, const float* __restrict__ W,
    const float* __restrict__ bias, int M, int N, int K, int osel)
{
    __shared__ float As[16][68];
    __shared__ float Ws[16][68];
    float* out = (osel == 0) ? g_B : (osel == 1) ? g_C : g_dt;
    const int tid = threadIdx.x;
    const int tn = tid & 15, tm = tid >> 4;
    const int m0 = blockIdx.y * 64, n0 = blockIdx.x * 64;
    const int lr = tid >> 2, lk = (tid & 3) * 4;
    float acc[4][4] = {};

    for (int k0 = 0; k0 < K; k0 += 16) {
        float4 av = *(const float4*)&A[(size_t)(m0 + lr) * K + k0 + lk];
        float4 wv = make_float4(0.f, 0.f, 0.f, 0.f);
        if (n0 + lr < N)
            wv = *(const float4*)&W[(size_t)(n0 + lr) * K + k0 + lk];
        As[lk+0][lr] = av.x; As[lk+1][lr] = av.y; As[lk+2][lr] = av.z; As[lk+3][lr] = av.w;
        Ws[lk+0][lr] = wv.x; Ws[lk+1][lr] = wv.y; Ws[lk+2][lr] = wv.z; Ws[lk+3][lr] = wv.w;
        __syncthreads();
        #pragma unroll
        for (int k = 0; k < 16; k++) {
            float a[4], b[4];
            #pragma unroll
            for (int i = 0; i < 4; i++) a[i] = As[k][tm*4+i];
            #pragma unroll
            for (int j = 0; j < 4; j++) b[j] = Ws[k][tn*4+j];
            #pragma unroll
            for (int i = 0; i < 4; i++)
                #pragma unroll
                for (int j = 0; j < 4; j++)
                    acc[i][j] = fmaf(a[i], b[j], acc[i][j]);
        }
        __syncthreads();
    }
    #pragma unroll
    for (int i = 0; i < 4; i++) {
        int m = m0 + tm*4 + i;
        #pragma unroll
        for (int j = 0; j < 4; j++) {
            int n = n0 + tn*4 + j;
            if (n < N) {
                float v = acc[i][j] + bias[n];
                if (osel == 2) v = softplus_f(v);
                out[(size_t)m * N + n] = v;
            }
        }
    }
}

// ---------------------------------------------------------------------------
// Per-(b,h,c) inclusive cumsum of dA = dt * A  over the chunk (L=256)
// ---------------------------------------------------------------------------
__global__ void cumsum_kernel(const float* __restrict__ A_log)
{
    __shared__ float sm[NL];
    int bid = blockIdx.x;
    int c = bid % NC, h = (bid / NC) % NH, b = bid / (NC * NH);
    int s = threadIdx.x;
    float Ah = -expf(A_log[h]);
    int t = c * NL + s;
    sm[s] = g_dt[(size_t)(b*NT + t)*NH + h] * Ah;
    __syncthreads();
    for (int off = 1; off < NL; off <<= 1) {
        float add = (s >= off) ? sm[s - off] : 0.f;
        __syncthreads();
        sm[s] += add;
        __syncthreads();
    }
    g_cum[(size_t)bid * NL + s] = sm[s];
}

// ---------------------------------------------------------------------------
// Chunk states: S[n,p] = sum_s B[s,n] * exp(cum_last - cum_s) * dt_s * x[s,p]
// ---------------------------------------------------------------------------
__global__ __launch_bounds__(256) void states_kernel(const float* __restrict__ x)
{
    __shared__ float Bs[64*64];
    __shared__ float XS[64*64];
    int bid = blockIdx.x;
    int h = bid % NH, c = (bid / NH) % NC, b = bid / (NH*NC);
    const int tid = threadIdx.x;
    const int tn = tid & 15, tm = tid >> 4;
    const float* cumc = &g_cum[(size_t)((b*NH + h)*NC + c) * NL];
    const float cum_last = cumc[NL-1];
    float acc[4][4] = {};

    for (int s0 = 0; s0 < NL; s0 += 64) {
        if (s0) __syncthreads();
        int v = tid;
        #pragma unroll
        for (int it = 0; it < 4; it++, v += 256) {
            int row = v >> 4, c4 = (v & 15) * 4;
            int gt = c*NL + s0 + row;
            float w = __expf(cum_last - cumc[s0 + row]) *
                      g_dt[(size_t)(b*NT + gt)*NH + h];
            float4 bv = *(const float4*)&g_B[(size_t)(b*NT + gt)*NN + c4];
            float4 xv = *(const float4*)&x[(size_t)(b*NT + gt)*ND + h*NP + c4];
            *(float4*)&Bs[row*64 + c4] = make_float4(bv.x*w, bv.y*w, bv.z*w, bv.w*w);
            *(float4*)&XS[row*64 + c4] = xv;
        }
        __syncthreads();
        #pragma unroll 8
        for (int s = 0; s < 64; s++) {
            float a[4], bb[4];
            #pragma unroll
            for (int i = 0; i < 4; i++) a[i] = Bs[s*64 + tm*4 + i];
            #pragma unroll
            for (int j = 0; j < 4; j++) bb[j] = XS[s*64 + tn*4 + j];
            #pragma unroll
            for (int i = 0; i < 4; i++)
                #pragma unroll
                for (int j = 0; j < 4; j++)
                    acc[i][j] = fmaf(a[i], bb[j], acc[i][j]);
        }
    }
    float* S = &g_states[(((size_t)b*NC + c)*NH + h) * (NN*NP)];
    #pragma unroll
    for (int i = 0; i < 4; i++)
        #pragma unroll
        for (int j = 0; j < 4; j++)
            S[(tm*4+i)*NP + tn*4 + j] = acc[i][j];
}

// ---------------------------------------------------------------------------
// Inter-chunk scan: prev[c] = R;  R = exp(a_c) * R + states[c]
// ---------------------------------------------------------------------------
__global__ void scan_kernel()
{
    int bid = blockIdx.x;                 // b*NH + h
    int h = bid % NH, b = bid / NH;
    int tid = threadIdx.x;
    int e0 = tid * 16;
    float4 R[4];
    #pragma unroll
    for (int q = 0; q < 4; q++) R[q] = make_float4(0.f, 0.f, 0.f, 0.f);
    #pragma unroll 1
    for (int c = 0; c < NC; c++) {
        size_t off = (((size_t)b*NC + c)*NH + h) * (NN*NP) + e0;
        #pragma unroll
        for (int q = 0; q < 4; q++)
            *(float4*)&g_prev[off + q*4] = R[q];
        float a = g_cum[(size_t)((b*NH + h)*NC + c)*NL + NL - 1];
        float dec = __expf(a);
        #pragma unroll
        for (int q = 0; q < 4; q++) {
            float4 sv = *(const float4*)&g_states[off + q*4];
            R[q].x = fmaf(dec, R[q].x, sv.x);
            R[q].y = fmaf(dec, R[q].y, sv.y);
            R[q].z = fmaf(dec, R[q].z, sv.z);
            R[q].w = fmaf(dec, R[q].w, sv.w);
        }
    }
}

// ---------------------------------------------------------------------------
// Y kernel (1xTF32 mma; off-diagonal tiles use rank-1 decay factorization
// to cut MUFU work 7x):
//   off-diag: (G .* exp(cl-cs)) @ X == diag(exp(cl-m)) * (G @ (diag(exp(m-cs)) X))
//   with m = cum[tile_end]; both exponents <= 0 -> no overflow.
//   diagonal tile keeps per-element exp (+ causal mask).
// ---------------------------------------------------------------------------
__global__ __launch_bounds__(256) void y_kernel_tc(const float* __restrict__ x,
                                                   const float* __restrict__ Dvec)
{
    __shared__ float Cs[64*64];
    __shared__ float BG[64*64];
    __shared__ float XT[64*64];

    int bid = blockIdx.x;
    int lt = bid & 3;
    int h  = (bid >> 2) & 31;
    int c  = (bid >> 7) & 15;
    int b  = bid >> 11;
    const int tid = threadIdx.x;
    const int wid = tid >> 5, lane = tid & 31;
    const int wm = wid >> 1, wn = wid & 1;
    const int lg = lane >> 2, lq = lane & 3;
    const int t0 = c * NL;
    const float* cumc = &g_cum[(size_t)((b*NH + h)*NC + c) * NL];

    {   // load C tile and S_prev^T (tf32-rounded)
        const float* S = &g_prev[(((size_t)b*NC + c)*NH + h) * (NN*NP)];
        int v = tid;
        #pragma unroll
        for (int it = 0; it < 4; it++, v += 256) {
            int row = v >> 4, c4 = (v & 15) * 4;
            float4 cv = *(const float4*)&g_C[(size_t)(b*NT + t0 + lt*64 + row)*NN + c4];
            *(float4*)&Cs[SW(row, c4)] = make_float4(to_tf32(cv.x), to_tf32(cv.y),
                                                     to_tf32(cv.z), to_tf32(cv.w));
            float4 sv = *(const float4*)&S[row*64 + c4];
            XT[SW(c4+0, row)] = to_tf32(sv.x);
            XT[SW(c4+1, row)] = to_tf32(sv.y);
            XT[SW(c4+2, row)] = to_tf32(sv.z);
            XT[SW(c4+3, row)] = to_tf32(sv.w);
        }
    }
    __syncthreads();

    const int lr0 = wm*16 + lg;
    const float cl0 = cumc[lt*64 + lr0];
    const float cl1 = cumc[lt*64 + lr0 + 8];

    float acc[4][4];
    #pragma unroll
    for (int j = 0; j < 4; j++)
        #pragma unroll
        for (int q = 0; q < 4; q++) acc[j][q] = 0.f;

    // ---- Y_off = C @ S_prev, then scale by exp(cum_l)
    #pragma unroll
    for (int kk = 0; kk < 64; kk += 8) {
        uint32_t ah[4];
        ah[0] = __float_as_uint(Cs[SW(lr0,   kk + lq)]);
        ah[1] = __float_as_uint(Cs[SW(lr0+8, kk + lq)]);
        ah[2] = __float_as_uint(Cs[SW(lr0,   kk + 4 + lq)]);
        ah[3] = __float_as_uint(Cs[SW(lr0+8, kk + 4 + lq)]);
        #pragma unroll
        for (int j = 0; j < 4; j++) {
            int p = wn*32 + j*8 + lg;
            uint32_t bh[2];
            bh[0] = __float_as_uint(XT[SW(p, kk + lq)]);
            bh[1] = __float_as_uint(XT[SW(p, kk + 4 + lq)]);
            mma_tf32(acc[j], ah, bh);
        }
    }
    {
        float e0 = __expf(cl0), e1 = __expf(cl1);
        #pragma unroll
        for (int j = 0; j < 4; j++) {
            acc[j][0] *= e0; acc[j][1] *= e0;
            acc[j][2] *= e1; acc[j][3] *= e1;
        }
    }

    // ---- causal s-tiles
    for (int st = 0; st <= lt; st++) {
        const bool offdiag = (st < lt);
        const float m = cumc[st*64 + 63];
        __syncthreads();
        {   // load B tile [s][n]; X' = (x*dt*e_s)^T [p][s]   (e_s = exp(m-cs), off-diag only)
            int v = tid;
            #pragma unroll
            for (int it = 0; it < 4; it++, v += 256) {
                int row = v >> 4, c4 = (v & 15) * 4;
                int gt = t0 + st*64 + row;
                float4 bv = *(const float4*)&g_B[(size_t)(b*NT + gt)*NN + c4];
                *(float4*)&BG[SW(row, c4)] = make_float4(to_tf32(bv.x), to_tf32(bv.y),
                                                         to_tf32(bv.z), to_tf32(bv.w));
                float sc = g_dt[(size_t)(b*NT + gt)*NH + h];
                if (offdiag) sc *= __expf(m - cumc[st*64 + row]);
                float4 xv = *(const float4*)&x[(size_t)(b*NT + gt)*ND + h*NP + c4];
                XT[SW(c4+0, row)] = to_tf32(xv.x * sc);
                XT[SW(c4+1, row)] = to_tf32(xv.y * sc);
                XT[SW(c4+2, row)] = to_tf32(xv.z * sc);
                XT[SW(c4+3, row)] = to_tf32(xv.w * sc);
            }
        }
        __syncthreads();

        // G = C @ B^T
        float ga[4][4];
        #pragma unroll
        for (int j = 0; j < 4; j++)
            #pragma unroll
            for (int q = 0; q < 4; q++) ga[j][q] = 0.f;
        #pragma unroll
        for (int kk = 0; kk < 64; kk += 8) {
            uint32_t ah[4];
            ah[0] = __float_as_uint(Cs[SW(lr0,   kk + lq)]);
            ah[1] = __float_as_uint(Cs[SW(lr0+8, kk + lq)]);
            ah[2] = __float_as_uint(Cs[SW(lr0,   kk + 4 + lq)]);
            ah[3] = __float_as_uint(Cs[SW(lr0+8, kk + 4 + lq)]);
            #pragma unroll
            for (int j = 0; j < 4; j++) {
                int s = wn*32 + j*8 + lg;
                uint32_t bh[2];
                bh[0] = __float_as_uint(BG[SW(s, kk + lq)]);
                bh[1] = __float_as_uint(BG[SW(s, kk + 4 + lq)]);
                mma_tf32(ga[j], ah, bh);
            }
        }
        if (!offdiag) {
            // diagonal tile: per-element L + causal mask
            int l0 = lr0, l1 = lr0 + 8;
            #pragma unroll
            for (int j = 0; j < 4; j++) {
                int s0c = wn*32 + j*8 + 2*lq;
                float cs0 = cumc[st*64 + s0c];
                float cs1 = cumc[st*64 + s0c + 1];
                ga[j][0] = (s0c     <= l0) ? ga[j][0] * __expf(cl0 - cs0) : 0.f;
                ga[j][1] = (s0c + 1 <= l0) ? ga[j][1] * __expf(cl0 - cs1) : 0.f;
                ga[j][2] = (s0c     <= l1) ? ga[j][2] * __expf(cl1 - cs0) : 0.f;
                ga[j][3] = (s0c + 1 <= l1) ? ga[j][3] * __expf(cl1 - cs1) : 0.f;
            }
        }
        __syncthreads();      // all warps done reading BG as B
        {   // write G into BG [l][s]
            #pragma unroll
            for (int j = 0; j < 4; j++) {
                int col = wn*32 + j*8 + 2*lq;
                BG[SW(lr0,   col)]     = to_tf32(ga[j][0]);
                BG[SW(lr0,   col + 1)] = to_tf32(ga[j][1]);
                BG[SW(lr0+8, col)]     = to_tf32(ga[j][2]);
                BG[SW(lr0+8, col + 1)] = to_tf32(ga[j][3]);
            }
        }
        __syncthreads();

        if (offdiag) {
            // ga2 = G @ X' into fresh accumulator (reuse ga), then acc += e_l * ga2
            #pragma unroll
            for (int j = 0; j < 4; j++)
                #pragma unroll
                for (int q = 0; q < 4; q++) ga[j][q] = 0.f;
            #pragma unroll
            for (int kk = 0; kk < 64; kk += 8) {
                uint32_t ah[4];
                ah[0] = __float_as_uint(BG[SW(lr0,   kk + lq)]);
                ah[1] = __float_as_uint(BG[SW(lr0+8, kk + lq)]);
                ah[2] = __float_as_uint(BG[SW(lr0,   kk + 4 + lq)]);
                ah[3] = __float_as_uint(BG[SW(lr0+8, kk + 4 + lq)]);
                #pragma unroll
                for (int j = 0; j < 4; j++) {
                    int p = wn*32 + j*8 + lg;
                    uint32_t bh[2];
                    bh[0] = __float_as_uint(XT[SW(p, kk + lq)]);
                    bh[1] = __float_as_uint(XT[SW(p, kk + 4 + lq)]);
                    mma_tf32(ga[j], ah, bh);
                }
            }
            float e0 = __expf(cl0 - m), e1 = __expf(cl1 - m);
            #pragma unroll
            for (int j = 0; j < 4; j++) {
                acc[j][0] = fmaf(e0, ga[j][0], acc[j][0]);
                acc[j][1] = fmaf(e0, ga[j][1], acc[j][1]);
                acc[j][2] = fmaf(e1, ga[j][2], acc[j][2]);
                acc[j][3] = fmaf(e1, ga[j][3], acc[j][3]);
            }
        } else {
            // diagonal: accumulate directly
            #pragma unroll
            for (int kk = 0; kk < 64; kk += 8) {
                uint32_t ah[4];
                ah[0] = __float_as_uint(BG[SW(lr0,   kk + lq)]);
                ah[1] = __float_as_uint(BG[SW(lr0+8, kk + lq)]);
                ah[2] = __float_as_uint(BG[SW(lr0,   kk + 4 + lq)]);
                ah[3] = __float_as_uint(BG[SW(lr0+8, kk + 4 + lq)]);
                #pragma unroll
                for (int j = 0; j < 4; j++) {
                    int p = wn*32 + j*8 + lg;
                    uint32_t bh[2];
                    bh[0] = __float_as_uint(XT[SW(p, kk + lq)]);
                    bh[1] = __float_as_uint(XT[SW(p, kk + 4 + lq)]);
                    mma_tf32(acc[j], ah, bh);
                }
            }
        }
    }

    // ---- epilogue: + D_h * x, store
    float Dh = Dvec[h];
    int gt0 = t0 + lt*64 + lr0;
    #pragma unroll
    for (int j = 0; j < 4; j++) {
        int p = wn*32 + j*8 + 2*lq;
        size_t o0 = (size_t)(b*NT + gt0)*ND + h*NP + p;
        size_t o1 = o0 + (size_t)8*ND;
        g_Y[o0]     = acc[j][0] + Dh * x[o0];
        g_Y[o0 + 1] = acc[j][1] + Dh * x[o0 + 1];
        g_Y[o1]     = acc[j][2] + Dh * x[o1];
        g_Y[o1 + 1] = acc[j][3] + Dh * x[o1 + 1];
    }
}

// ---------------------------------------------------------------------------
// Output projection, TF32 mma.sync (proven R6 version):
// ---------------------------------------------------------------------------
__global__ __launch_bounds__(256) void out_gemm_tf32(
    const float* __restrict__ W, const float* __restrict__ bias,
    float* __restrict__ out)
{
    __shared__ float As[128][36];
    __shared__ float Ws[128][36];
    const int tid  = threadIdx.x;
    const int wid  = tid >> 5, lane = tid & 31;
    const int warp_m = wid >> 2, warp_n = wid & 3;   // 2 x 4
    const int m0 = blockIdx.y * 128, n0 = blockIdx.x * 128;
    const int qrow = tid >> 3;
    const int qc4  = (tid & 7) * 4;
    const int lg = lane >> 2, lq = lane & 3;
    const float* A = g_Y;

    float acc[4][4][4];
    #pragma unroll
    for (int i = 0; i < 4; i++)
        #pragma unroll
        for (int j = 0; j < 4; j++)
            #pragma unroll
            for (int q = 0; q < 4; q++) acc[i][j][q] = 0.f;

    float4 pa[4], pw[4];
    #pragma unroll
    for (int it = 0; it < 4; it++) {
        int r = qrow + it * 32;
        pa[it] = *(const float4*)&A[(size_t)(m0 + r) * ND + qc4];
        pw[it] = *(const float4*)&W[(size_t)(n0 + r) * ND + qc4];
    }

    for (int k0 = 0; k0 < ND; k0 += 32) {
        #pragma unroll
        for (int it = 0; it < 4; it++) {
            int r = qrow + it * 32;
            As[r][qc4+0] = to_tf32(pa[it].x); As[r][qc4+1] = to_tf32(pa[it].y);
            As[r][qc4+2] = to_tf32(pa[it].z); As[r][qc4+3] = to_tf32(pa[it].w);
            Ws[r][qc4+0] = to_tf32(pw[it].x); Ws[r][qc4+1] = to_tf32(pw[it].y);
            Ws[r][qc4+2] = to_tf32(pw[it].z); Ws[r][qc4+3] = to_tf32(pw[it].w);
        }
        __syncthreads();

        if (k0 + 32 < ND) {
            #pragma unroll
            for (int it = 0; it < 4; it++) {
                int r = qrow + it * 32;
                pa[it] = *(const float4*)&A[(size_t)(m0 + r) * ND + k0 + 32 + qc4];
                pw[it] = *(const float4*)&W[(size_t)(n0 + r) * ND + k0 + 32 + qc4];
            }
        }

        #pragma unroll
        for (int kk = 0; kk < 32; kk += 8) {
            uint32_t afr[4][4], bfr[4][2];
            #pragma unroll
            for (int i = 0; i < 4; i++) {
                int row = warp_m*64 + i*16 + lg;
                afr[i][0] = __float_as_uint(As[row    ][kk + lq]);
                afr[i][1] = __float_as_uint(As[row + 8][kk + lq]);
                afr[i][2] = __float_as_uint(As[row    ][kk + 4 + lq]);
                afr[i][3] = __float_as_uint(As[row + 8][kk + 4 + lq]);
            }
            #pragma unroll
            for (int j = 0; j < 4; j++) {
                int nrow = warp_n*32 + j*8 + lg;
                bfr[j][0] = __float_as_uint(Ws[nrow][kk + lq]);
                bfr[j][1] = __float_as_uint(Ws[nrow][kk + 4 + lq]);
            }
            #pragma unroll
            for (int i = 0; i < 4; i++)
                #pragma unroll
                for (int j = 0; j < 4; j++)
                    mma_tf32(acc[i][j], afr[i], bfr[j]);
        }
        __syncthreads();
    }

    #pragma unroll
    for (int i = 0; i < 4; i++) {
        int r0 = m0 + warp_m*64 + i*16 + lg;
        #pragma unroll
        for (int j = 0; j < 4; j++) {
            int cc = n0 + warp_n*32 + j*8 + lq*2;
            float b0 = bias[cc], b1 = bias[cc+1];
            out[(size_t)r0       * ND + cc    ] = acc[i][j][0] + b0;
            out[(size_t)r0       * ND + cc + 1] = acc[i][j][1] + b1;
            out[(size_t)(r0 + 8) * ND + cc    ] = acc[i][j][2] + b0;
            out[(size_t)(r0 + 8) * ND + cc + 1] = acc[i][j][3] + b1;
        }
    }
}

// ---------------------------------------------------------------------------
extern "C" void kernel_launch(void* const* d_in, const int* in_sizes, int n_in,
                              void* d_out, int out_size)
{
    const float* x     = (const float*)d_in[0];
    const float* A_log = (const float*)d_in[1];
    const float* Dvec  = (const float*)d_in[2];
    const float* B_w   = (const float*)d_in[3];
    const float* B_b   = (const float*)d_in[4];
    const float* C_w   = (const float*)d_in[5];
    const float* C_b   = (const float*)d_in[6];
    const float* dt_w  = (const float*)d_in[7];
    const float* dt_b  = (const float*)d_in[8];
    const float* out_w = (const float*)d_in[9];
    const float* out_b = (const float*)d_in[10];
    float* out = (float*)d_out;

    proj_bc_tf32<<<NTOK/64, 256>>>(x, B_w, B_b, C_w, C_b);
    proj_gemm<<<dim3(1, NTOK/64), 256>>>(x, dt_w, dt_b, NTOK, NH, ND, 2);
    cumsum_kernel<<<NB*NH*NC, NL>>>(A_log);
    states_kernel<<<NB*NC*NH, 256>>>(x);
    scan_kernel<<<NB*NH, 256>>>();
    y_kernel_tc<<<NB*NC*NH*4, 256>>>(x, Dvec);
    out_gemm_tf32<<<dim3(ND/128, NTOK/128), 256>>>(out_w, out_b, out);
}

// round 9
// speedup vs baseline: 2.2177x; 1.0018x over previous
#include <cuda_runtime.h>
#include <cstdint>
#include <math.h>

#define NB 2
#define NT 4096
#define ND 2048
#define NH 32
#define NN 64
#define NP 64
#define NL 256
#define NC 16
#define NTOK (NB*NT)   // 8192

// swizzled [64][64] accessor: 4-group-preserving, conflict-free fragment reads
#define SW(r,c) (((r)<<6) + ((c) ^ (((r)&15)<<2)))

// ---------------- scratch (device globals; no runtime allocation) ----------
__device__ float g_B[(size_t)NTOK*NN];
__device__ float g_C[(size_t)NTOK*NN];
__device__ float g_dt[(size_t)NTOK*NH];
__device__ float g_cum[(size_t)NB*NH*NC*NL];
__device__ float g_states[(size_t)NB*NC*NH*NN*NP];
__device__ float g_prev[(size_t)NB*NC*NH*NN*NP];
__device__ float g_Y[(size_t)NTOK*ND];

__device__ __forceinline__ float softplus_f(float v) {
    return v > 20.f ? v : log1pf(expf(v));
}

__device__ __forceinline__ float to_tf32(float v) {
    uint32_t u;
    asm("cvt.rna.tf32.f32 %0, %1;" : "=r"(u) : "f"(v));
    return __uint_as_float(u);
}

__device__ __forceinline__ void mma_tf32(float* d, const uint32_t* a, const uint32_t* b) {
    asm volatile(
        "mma.sync.aligned.m16n8k8.row.col.f32.tf32.tf32.f32 "
        "{%0,%1,%2,%3}, {%4,%5,%6,%7}, {%8,%9}, {%0,%1,%2,%3};"
        : "+f"(d[0]), "+f"(d[1]), "+f"(d[2]), "+f"(d[3])
        : "r"(a[0]), "r"(a[1]), "r"(a[2]), "r"(a[3]),
          "r"(b[0]), "r"(b[1]));
}

// ---------------------------------------------------------------------------
// Fused B+C projection, TF32: [g_B | g_C](M,128) = x(M,2048) @ [B_w;C_w]^T
// ---------------------------------------------------------------------------
__global__ __launch_bounds__(256) void proj_bc_tf32(
    const float* __restrict__ x,
    const float* __restrict__ B_w, const float* __restrict__ B_b,
    const float* __restrict__ C_w, const float* __restrict__ C_b)
{
    __shared__ float As[64*36];
    __shared__ float Ws[128*36];
    const int tid = threadIdx.x;
    const int wid = tid >> 5, lane = tid & 31;
    const int wm = wid >> 2, wn = wid & 3;
    const int lg = lane >> 2, lq = lane & 3;
    const int m0 = blockIdx.x * 64;

    float acc[2][4][4];
    #pragma unroll
    for (int i = 0; i < 2; i++)
        #pragma unroll
        for (int j = 0; j < 4; j++)
            #pragma unroll
            for (int q = 0; q < 4; q++) acc[i][j][q] = 0.f;

    for (int k0 = 0; k0 < ND; k0 += 32) {
        {
            int v = tid;
            #pragma unroll
            for (int it = 0; it < 2; it++, v += 256) {
                int row = v >> 3, c4 = (v & 7) * 4;
                float4 av = *(const float4*)&x[(size_t)(m0 + row) * ND + k0 + c4];
                float4 t = make_float4(to_tf32(av.x), to_tf32(av.y),
                                       to_tf32(av.z), to_tf32(av.w));
                *(float4*)&As[row*36 + c4] = t;
            }
            v = tid;
            #pragma unroll
            for (int it = 0; it < 4; it++, v += 256) {
                int row = v >> 3, c4 = (v & 7) * 4;
                const float* Wp = (row < 64) ? &B_w[(size_t)row * ND]
                                             : &C_w[(size_t)(row - 64) * ND];
                float4 wv = *(const float4*)&Wp[k0 + c4];
                float4 t = make_float4(to_tf32(wv.x), to_tf32(wv.y),
                                       to_tf32(wv.z), to_tf32(wv.w));
                *(float4*)&Ws[row*36 + c4] = t;
            }
        }
        __syncthreads();
        #pragma unroll
        for (int kk = 0; kk < 32; kk += 8) {
            uint32_t af[2][4], bf[4][2];
            #pragma unroll
            for (int i = 0; i < 2; i++) {
                int r = wm*32 + i*16 + lg;
                af[i][0] = __float_as_uint(As[r*36 + kk + lq]);
                af[i][1] = __float_as_uint(As[(r+8)*36 + kk + lq]);
                af[i][2] = __float_as_uint(As[r*36 + kk + 4 + lq]);
                af[i][3] = __float_as_uint(As[(r+8)*36 + kk + 4 + lq]);
            }
            #pragma unroll
            for (int j = 0; j < 4; j++) {
                int n = wn*32 + j*8 + lg;
                bf[j][0] = __float_as_uint(Ws[n*36 + kk + lq]);
                bf[j][1] = __float_as_uint(Ws[n*36 + kk + 4 + lq]);
            }
            #pragma unroll
            for (int i = 0; i < 2; i++)
                #pragma unroll
                for (int j = 0; j < 4; j++)
                    mma_tf32(acc[i][j], af[i], bf[j]);
        }
        __syncthreads();
    }
    #pragma unroll
    for (int i = 0; i < 2; i++) {
        int r = m0 + wm*32 + i*16 + lg;
        #pragma unroll
        for (int j = 0; j < 4; j++) {
            int n = wn*32 + j*8 + 2*lq;
            if (n < 64) {
                float b0 = B_b[n], b1 = B_b[n+1];
                g_B[(size_t)r*64 + n]       = acc[i][j][0] + b0;
                g_B[(size_t)r*64 + n + 1]   = acc[i][j][1] + b1;
                g_B[(size_t)(r+8)*64 + n]   = acc[i][j][2] + b0;
                g_B[(size_t)(r+8)*64 + n+1] = acc[i][j][3] + b1;
            } else {
                int n2 = n - 64;
                float b0 = C_b[n2], b1 = C_b[n2+1];
                g_C[(size_t)r*64 + n2]       = acc[i][j][0] + b0;
                g_C[(size_t)r*64 + n2 + 1]   = acc[i][j][1] + b1;
                g_C[(size_t)(r+8)*64 + n2]   = acc[i][j][2] + b0;
                g_C[(size_t)(r+8)*64 + n2+1] = acc[i][j][3] + b1;
            }
        }
    }
}

// ---------------------------------------------------------------------------
// Scalar projection GEMM (kept for dt, N=32): out = A @ W^T + bias, softplus
// ---------------------------------------------------------------------------
__global__ __launch_bounds__(256) void proj_gemm(
    const float* __restrict__ A, const float* __restrict__ W,
    const float* __restrict__ bias, int M, int N, int K, int osel)
{
    __shared__ float As[16][68];
    __shared__ float Ws[16][68];
    float* out = (osel == 0) ? g_B : (osel == 1) ? g_C : g_dt;
    const int tid = threadIdx.x;
    const int tn = tid & 15, tm = tid >> 4;
    const int m0 = blockIdx.y * 64, n0 = blockIdx.x * 64;
    const int lr = tid >> 2, lk = (tid & 3) * 4;
    float acc[4][4] = {};

    for (int k0 = 0; k0 < K; k0 += 16) {
        float4 av = *(const float4*)&A[(size_t)(m0 + lr) * K + k0 + lk];
        float4 wv = make_float4(0.f, 0.f, 0.f, 0.f);
        if (n0 + lr < N)
            wv = *(const float4*)&W[(size_t)(n0 + lr) * K + k0 + lk];
        As[lk+0][lr] = av.x; As[lk+1][lr] = av.y; As[lk+2][lr] = av.z; As[lk+3][lr] = av.w;
        Ws[lk+0][lr] = wv.x; Ws[lk+1][lr] = wv.y; Ws[lk+2][lr] = wv.z; Ws[lk+3][lr] = wv.w;
        __syncthreads();
        #pragma unroll
        for (int k = 0; k < 16; k++) {
            float a[4], b[4];
            #pragma unroll
            for (int i = 0; i < 4; i++) a[i] = As[k][tm*4+i];
            #pragma unroll
            for (int j = 0; j < 4; j++) b[j] = Ws[k][tn*4+j];
            #pragma unroll
            for (int i = 0; i < 4; i++)
                #pragma unroll
                for (int j = 0; j < 4; j++)
                    acc[i][j] = fmaf(a[i], b[j], acc[i][j]);
        }
        __syncthreads();
    }
    #pragma unroll
    for (int i = 0; i < 4; i++) {
        int m = m0 + tm*4 + i;
        #pragma unroll
        for (int j = 0; j < 4; j++) {
            int n = n0 + tn*4 + j;
            if (n < N) {
                float v = acc[i][j] + bias[n];
                if (osel == 2) v = softplus_f(v);
                out[(size_t)m * N + n] = v;
            }
        }
    }
}

// ---------------------------------------------------------------------------
// Per-(b,h,c) inclusive cumsum of dA = dt * A  over the chunk (L=256)
// ---------------------------------------------------------------------------
__global__ void cumsum_kernel(const float* __restrict__ A_log)
{
    __shared__ float sm[NL];
    int bid = blockIdx.x;
    int c = bid % NC, h = (bid / NC) % NH, b = bid / (NC * NH);
    int s = threadIdx.x;
    float Ah = -expf(A_log[h]);
    int t = c * NL + s;
    sm[s] = g_dt[(size_t)(b*NT + t)*NH + h] * Ah;
    __syncthreads();
    for (int off = 1; off < NL; off <<= 1) {
        float add = (s >= off) ? sm[s - off] : 0.f;
        __syncthreads();
        sm[s] += add;
        __syncthreads();
    }
    g_cum[(size_t)bid * NL + s] = sm[s];
}

// ---------------------------------------------------------------------------
// Chunk states, 1xTF32 mma:
//   S[n,p] = sum_s (B[s,n]*w_s) * x[s,p],  w_s = exp(cum_last-cum_s)*dt_s
// A-tile = (B*w)^T [n][s], B-tile = x^T [p][s], both swizzled; K = 256 in
// 4 subtiles of 64. 8 warps (4n x 2p), warp tile 16x32.
// ---------------------------------------------------------------------------
__global__ __launch_bounds__(256) void states_tc(const float* __restrict__ x)
{
    __shared__ float BT[64*64];
    __shared__ float XS[64*64];
    int bid = blockIdx.x;
    int h = bid % NH, c = (bid / NH) % NC, b = bid / (NH*NC);
    const int tid = threadIdx.x;
    const int wid = tid >> 5, lane = tid & 31;
    const int wm = wid >> 1, wn = wid & 1;
    const int lg = lane >> 2, lq = lane & 3;
    const float* cumc = &g_cum[(size_t)((b*NH + h)*NC + c) * NL];
    const float cum_last = cumc[NL-1];
    const int lr0 = wm*16 + lg;

    float acc[4][4];
    #pragma unroll
    for (int j = 0; j < 4; j++)
        #pragma unroll
        for (int q = 0; q < 4; q++) acc[j][q] = 0.f;

    for (int s0 = 0; s0 < NL; s0 += 64) {
        if (s0) __syncthreads();
        int v = tid;
        #pragma unroll
        for (int it = 0; it < 4; it++, v += 256) {
            int row = v >> 4, c4 = (v & 15) * 4;   // row = s_local
            int gt = c*NL + s0 + row;
            float w = __expf(cum_last - cumc[s0 + row]) *
                      g_dt[(size_t)(b*NT + gt)*NH + h];
            float4 bv = *(const float4*)&g_B[(size_t)(b*NT + gt)*NN + c4];
            float4 xv = *(const float4*)&x[(size_t)(b*NT + gt)*ND + h*NP + c4];
            BT[SW(c4+0, row)] = to_tf32(bv.x * w);
            BT[SW(c4+1, row)] = to_tf32(bv.y * w);
            BT[SW(c4+2, row)] = to_tf32(bv.z * w);
            BT[SW(c4+3, row)] = to_tf32(bv.w * w);
            XS[SW(c4+0, row)] = to_tf32(xv.x);
            XS[SW(c4+1, row)] = to_tf32(xv.y);
            XS[SW(c4+2, row)] = to_tf32(xv.z);
            XS[SW(c4+3, row)] = to_tf32(xv.w);
        }
        __syncthreads();
        #pragma unroll
        for (int kk = 0; kk < 64; kk += 8) {
            uint32_t ah[4];
            ah[0] = __float_as_uint(BT[SW(lr0,   kk + lq)]);
            ah[1] = __float_as_uint(BT[SW(lr0+8, kk + lq)]);
            ah[2] = __float_as_uint(BT[SW(lr0,   kk + 4 + lq)]);
            ah[3] = __float_as_uint(BT[SW(lr0+8, kk + 4 + lq)]);
            #pragma unroll
            for (int j = 0; j < 4; j++) {
                int p = wn*32 + j*8 + lg;
                uint32_t bh[2];
                bh[0] = __float_as_uint(XS[SW(p, kk + lq)]);
                bh[1] = __float_as_uint(XS[SW(p, kk + 4 + lq)]);
                mma_tf32(acc[j], ah, bh);
            }
        }
    }
    float* S = &g_states[(((size_t)b*NC + c)*NH + h) * (NN*NP)];
    #pragma unroll
    for (int j = 0; j < 4; j++) {
        int p = wn*32 + j*8 + 2*lq;
        S[(size_t)lr0*NP + p]         = acc[j][0];
        S[(size_t)lr0*NP + p + 1]     = acc[j][1];
        S[(size_t)(lr0+8)*NP + p]     = acc[j][2];
        S[(size_t)(lr0+8)*NP + p + 1] = acc[j][3];
    }
}

// ---------------------------------------------------------------------------
// Inter-chunk scan: prev[c] = R;  R = exp(a_c) * R + states[c]
// ---------------------------------------------------------------------------
__global__ void scan_kernel()
{
    int bid = blockIdx.x;                 // b*NH + h
    int h = bid % NH, b = bid / NH;
    int tid = threadIdx.x;
    int e0 = tid * 16;
    float4 R[4];
    #pragma unroll
    for (int q = 0; q < 4; q++) R[q] = make_float4(0.f, 0.f, 0.f, 0.f);
    #pragma unroll 1
    for (int c = 0; c < NC; c++) {
        size_t off = (((size_t)b*NC + c)*NH + h) * (NN*NP) + e0;
        #pragma unroll
        for (int q = 0; q < 4; q++)
            *(float4*)&g_prev[off + q*4] = R[q];
        float a = g_cum[(size_t)((b*NH + h)*NC + c)*NL + NL - 1];
        float dec = __expf(a);
        #pragma unroll
        for (int q = 0; q < 4; q++) {
            float4 sv = *(const float4*)&g_states[off + q*4];
            R[q].x = fmaf(dec, R[q].x, sv.x);
            R[q].y = fmaf(dec, R[q].y, sv.y);
            R[q].z = fmaf(dec, R[q].z, sv.z);
            R[q].w = fmaf(dec, R[q].w, sv.w);
        }
    }
}

// ---------------------------------------------------------------------------
// Y kernel (1xTF32, rank-1 decay factorization, separate G buffer to cut
// one __syncthreads per s-tile). Dynamic smem: 4 x 16KB = 64KB.
// ---------------------------------------------------------------------------
#define Y_SMEM (4*64*64*4)
__global__ __launch_bounds__(256) void y_kernel_tc(const float* __restrict__ x,
                                                   const float* __restrict__ Dvec)
{
    extern __shared__ float ysm[];
    float* Cs = ysm;             // C tile [l][n]
    float* BG = ysm + 4096;      // B tile [s][n]
    float* XT = ysm + 8192;      // S^T [p][n]; then (x*dt*e_s)^T [p][s]
    float* GS = ysm + 12288;     // G [l][s]

    int bid = blockIdx.x;
    int lt = bid & 3;
    int h  = (bid >> 2) & 31;
    int c  = (bid >> 7) & 15;
    int b  = bid >> 11;
    const int tid = threadIdx.x;
    const int wid = tid >> 5, lane = tid & 31;
    const int wm = wid >> 1, wn = wid & 1;
    const int lg = lane >> 2, lq = lane & 3;
    const int t0 = c * NL;
    const float* cumc = &g_cum[(size_t)((b*NH + h)*NC + c) * NL];

    {   // load C tile and S_prev^T (tf32-rounded)
        const float* S = &g_prev[(((size_t)b*NC + c)*NH + h) * (NN*NP)];
        int v = tid;
        #pragma unroll
        for (int it = 0; it < 4; it++, v += 256) {
            int row = v >> 4, c4 = (v & 15) * 4;
            float4 cv = *(const float4*)&g_C[(size_t)(b*NT + t0 + lt*64 + row)*NN + c4];
            *(float4*)&Cs[SW(row, c4)] = make_float4(to_tf32(cv.x), to_tf32(cv.y),
                                                     to_tf32(cv.z), to_tf32(cv.w));
            float4 sv = *(const float4*)&S[row*64 + c4];
            XT[SW(c4+0, row)] = to_tf32(sv.x);
            XT[SW(c4+1, row)] = to_tf32(sv.y);
            XT[SW(c4+2, row)] = to_tf32(sv.z);
            XT[SW(c4+3, row)] = to_tf32(sv.w);
        }
    }
    __syncthreads();

    const int lr0 = wm*16 + lg;
    const float cl0 = cumc[lt*64 + lr0];
    const float cl1 = cumc[lt*64 + lr0 + 8];

    float acc[4][4];
    #pragma unroll
    for (int j = 0; j < 4; j++)
        #pragma unroll
        for (int q = 0; q < 4; q++) acc[j][q] = 0.f;

    // ---- Y_off = C @ S_prev, then scale by exp(cum_l)
    #pragma unroll
    for (int kk = 0; kk < 64; kk += 8) {
        uint32_t ah[4];
        ah[0] = __float_as_uint(Cs[SW(lr0,   kk + lq)]);
        ah[1] = __float_as_uint(Cs[SW(lr0+8, kk + lq)]);
        ah[2] = __float_as_uint(Cs[SW(lr0,   kk + 4 + lq)]);
        ah[3] = __float_as_uint(Cs[SW(lr0+8, kk + 4 + lq)]);
        #pragma unroll
        for (int j = 0; j < 4; j++) {
            int p = wn*32 + j*8 + lg;
            uint32_t bh[2];
            bh[0] = __float_as_uint(XT[SW(p, kk + lq)]);
            bh[1] = __float_as_uint(XT[SW(p, kk + 4 + lq)]);
            mma_tf32(acc[j], ah, bh);
        }
    }
    {
        float e0 = __expf(cl0), e1 = __expf(cl1);
        #pragma unroll
        for (int j = 0; j < 4; j++) {
            acc[j][0] *= e0; acc[j][1] *= e0;
            acc[j][2] *= e1; acc[j][3] *= e1;
        }
    }

    // ---- causal s-tiles
    for (int st = 0; st <= lt; st++) {
        const bool offdiag = (st < lt);
        const float m = cumc[st*64 + 63];
        __syncthreads();   // prior readers of BG/XT done
        {   // load B tile [s][n]; X' = (x*dt*e_s)^T [p][s]
            int v = tid;
            #pragma unroll
            for (int it = 0; it < 4; it++, v += 256) {
                int row = v >> 4, c4 = (v & 15) * 4;
                int gt = t0 + st*64 + row;
                float4 bv = *(const float4*)&g_B[(size_t)(b*NT + gt)*NN + c4];
                *(float4*)&BG[SW(row, c4)] = make_float4(to_tf32(bv.x), to_tf32(bv.y),
                                                         to_tf32(bv.z), to_tf32(bv.w));
                float sc = g_dt[(size_t)(b*NT + gt)*NH + h];
                if (offdiag) sc *= __expf(m - cumc[st*64 + row]);
                float4 xv = *(const float4*)&x[(size_t)(b*NT + gt)*ND + h*NP + c4];
                XT[SW(c4+0, row)] = to_tf32(xv.x * sc);
                XT[SW(c4+1, row)] = to_tf32(xv.y * sc);
                XT[SW(c4+2, row)] = to_tf32(xv.z * sc);
                XT[SW(c4+3, row)] = to_tf32(xv.w * sc);
            }
        }
        __syncthreads();

        // G = C @ B^T
        float ga[4][4];
        #pragma unroll
        for (int j = 0; j < 4; j++)
            #pragma unroll
            for (int q = 0; q < 4; q++) ga[j][q] = 0.f;
        #pragma unroll
        for (int kk = 0; kk < 64; kk += 8) {
            uint32_t ah[4];
            ah[0] = __float_as_uint(Cs[SW(lr0,   kk + lq)]);
            ah[1] = __float_as_uint(Cs[SW(lr0+8, kk + lq)]);
            ah[2] = __float_as_uint(Cs[SW(lr0,   kk + 4 + lq)]);
            ah[3] = __float_as_uint(Cs[SW(lr0+8, kk + 4 + lq)]);
            #pragma unroll
            for (int j = 0; j < 4; j++) {
                int s = wn*32 + j*8 + lg;
                uint32_t bh[2];
                bh[0] = __float_as_uint(BG[SW(s, kk + lq)]);
                bh[1] = __float_as_uint(BG[SW(s, kk + 4 + lq)]);
                mma_tf32(ga[j], ah, bh);
            }
        }
        if (!offdiag) {
            // diagonal tile: per-element L + causal mask
            int l0 = lr0, l1 = lr0 + 8;
            #pragma unroll
            for (int j = 0; j < 4; j++) {
                int s0c = wn*32 + j*8 + 2*lq;
                float cs0 = cumc[st*64 + s0c];
                float cs1 = cumc[st*64 + s0c + 1];
                ga[j][0] = (s0c     <= l0) ? ga[j][0] * __expf(cl0 - cs0) : 0.f;
                ga[j][1] = (s0c + 1 <= l0) ? ga[j][1] * __expf(cl0 - cs1) : 0.f;
                ga[j][2] = (s0c     <= l1) ? ga[j][2] * __expf(cl1 - cs0) : 0.f;
                ga[j][3] = (s0c + 1 <= l1) ? ga[j][3] * __expf(cl1 - cs1) : 0.f;
            }
        }
        // write G to its own buffer (no pre-sync needed: GS has no readers yet)
        {
            #pragma unroll
            for (int j = 0; j < 4; j++) {
                int col = wn*32 + j*8 + 2*lq;
                GS[SW(lr0,   col)]     = to_tf32(ga[j][0]);
                GS[SW(lr0,   col + 1)] = to_tf32(ga[j][1]);
                GS[SW(lr0+8, col)]     = to_tf32(ga[j][2]);
                GS[SW(lr0+8, col + 1)] = to_tf32(ga[j][3]);
            }
        }
        __syncthreads();   // all G visible

        if (offdiag) {
            #pragma unroll
            for (int j = 0; j < 4; j++)
                #pragma unroll
                for (int q = 0; q < 4; q++) ga[j][q] = 0.f;
            #pragma unroll
            for (int kk = 0; kk < 64; kk += 8) {
                uint32_t ah[4];
                ah[0] = __float_as_uint(GS[SW(lr0,   kk + lq)]);
                ah[1] = __float_as_uint(GS[SW(lr0+8, kk + lq)]);
                ah[2] = __float_as_uint(GS[SW(lr0,   kk + 4 + lq)]);
                ah[3] = __float_as_uint(GS[SW(lr0+8, kk + 4 + lq)]);
                #pragma unroll
                for (int j = 0; j < 4; j++) {
                    int p = wn*32 + j*8 + lg;
                    uint32_t bh[2];
                    bh[0] = __float_as_uint(XT[SW(p, kk + lq)]);
                    bh[1] = __float_as_uint(XT[SW(p, kk + 4 + lq)]);
                    mma_tf32(ga[j], ah, bh);
                }
            }
            float e0 = __expf(cl0 - m), e1 = __expf(cl1 - m);
            #pragma unroll
            for (int j = 0; j < 4; j++) {
                acc[j][0] = fmaf(e0, ga[j][0], acc[j][0]);
                acc[j][1] = fmaf(e0, ga[j][1], acc[j][1]);
                acc[j][2] = fmaf(e1, ga[j][2], acc[j][2]);
                acc[j][3] = fmaf(e1, ga[j][3], acc[j][3]);
            }
        } else {
            #pragma unroll
            for (int kk = 0; kk < 64; kk += 8) {
                uint32_t ah[4];
                ah[0] = __float_as_uint(GS[SW(lr0,   kk + lq)]);
                ah[1] = __float_as_uint(GS[SW(lr0+8, kk + lq)]);
                ah[2] = __float_as_uint(GS[SW(lr0,   kk + 4 + lq)]);
                ah[3] = __float_as_uint(GS[SW(lr0+8, kk + 4 + lq)]);
                #pragma unroll
                for (int j = 0; j < 4; j++) {
                    int p = wn*32 + j*8 + lg;
                    uint32_t bh[2];
                    bh[0] = __float_as_uint(XT[SW(p, kk + lq)]);
                    bh[1] = __float_as_uint(XT[SW(p, kk + 4 + lq)]);
                    mma_tf32(acc[j], ah, bh);
                }
            }
        }
    }

    // ---- epilogue: + D_h * x, store
    float Dh = Dvec[h];
    int gt0 = t0 + lt*64 + lr0;
    #pragma unroll
    for (int j = 0; j < 4; j++) {
        int p = wn*32 + j*8 + 2*lq;
        size_t o0 = (size_t)(b*NT + gt0)*ND + h*NP + p;
        size_t o1 = o0 + (size_t)8*ND;
        g_Y[o0]     = acc[j][0] + Dh * x[o0];
        g_Y[o0 + 1] = acc[j][1] + Dh * x[o0 + 1];
        g_Y[o1]     = acc[j][2] + Dh * x[o1];
        g_Y[o1 + 1] = acc[j][3] + Dh * x[o1 + 1];
    }
}

// ---------------------------------------------------------------------------
// Output projection, TF32 mma.sync (proven):
// ---------------------------------------------------------------------------
__global__ __launch_bounds__(256) void out_gemm_tf32(
    const float* __restrict__ W, const float* __restrict__ bias,
    float* __restrict__ out)
{
    __shared__ float As[128][36];
    __shared__ float Ws[128][36];
    const int tid  = threadIdx.x;
    const int wid  = tid >> 5, lane = tid & 31;
    const int warp_m = wid >> 2, warp_n = wid & 3;   // 2 x 4
    const int m0 = blockIdx.y * 128, n0 = blockIdx.x * 128;
    const int qrow = tid >> 3;
    const int qc4  = (tid & 7) * 4;
    const int lg = lane >> 2, lq = lane & 3;
    const float* A = g_Y;

    float acc[4][4][4];
    #pragma unroll
    for (int i = 0; i < 4; i++)
        #pragma unroll
        for (int j = 0; j < 4; j++)
            #pragma unroll
            for (int q = 0; q < 4; q++) acc[i][j][q] = 0.f;

    float4 pa[4], pw[4];
    #pragma unroll
    for (int it = 0; it < 4; it++) {
        int r = qrow + it * 32;
        pa[it] = *(const float4*)&A[(size_t)(m0 + r) * ND + qc4];
        pw[it] = *(const float4*)&W[(size_t)(n0 + r) * ND + qc4];
    }

    for (int k0 = 0; k0 < ND; k0 += 32) {
        #pragma unroll
        for (int it = 0; it < 4; it++) {
            int r = qrow + it * 32;
            As[r][qc4+0] = to_tf32(pa[it].x); As[r][qc4+1] = to_tf32(pa[it].y);
            As[r][qc4+2] = to_tf32(pa[it].z); As[r][qc4+3] = to_tf32(pa[it].w);
            Ws[r][qc4+0] = to_tf32(pw[it].x); Ws[r][qc4+1] = to_tf32(pw[it].y);
            Ws[r][qc4+2] = to_tf32(pw[it].z); Ws[r][qc4+3] = to_tf32(pw[it].w);
        }
        __syncthreads();

        if (k0 + 32 < ND) {
            #pragma unroll
            for (int it = 0; it < 4; it++) {
                int r = qrow + it * 32;
                pa[it] = *(const float4*)&A[(size_t)(m0 + r) * ND + k0 + 32 + qc4];
                pw[it] = *(const float4*)&W[(size_t)(n0 + r) * ND + k0 + 32 + qc4];
            }
        }

        #pragma unroll
        for (int kk = 0; kk < 32; kk += 8) {
            uint32_t afr[4][4], bfr[4][2];
            #pragma unroll
            for (int i = 0; i < 4; i++) {
                int row = warp_m*64 + i*16 + lg;
                afr[i][0] = __float_as_uint(As[row    ][kk + lq]);
                afr[i][1] = __float_as_uint(As[row + 8][kk + lq]);
                afr[i][2] = __float_as_uint(As[row    ][kk + 4 + lq]);
                afr[i][3] = __float_as_uint(As[row + 8][kk + 4 + lq]);
            }
            #pragma unroll
            for (int j = 0; j < 4; j++) {
                int nrow = warp_n*32 + j*8 + lg;
                bfr[j][0] = __float_as_uint(Ws[nrow][kk + lq]);
                bfr[j][1] = __float_as_uint(Ws[nrow][kk + 4 + lq]);
            }
            #pragma unroll
            for (int i = 0; i < 4; i++)
                #pragma unroll
                for (int j = 0; j < 4; j++)
                    mma_tf32(acc[i][j], afr[i], bfr[j]);
        }
        __syncthreads();
    }

    #pragma unroll
    for (int i = 0; i < 4; i++) {
        int r0 = m0 + warp_m*64 + i*16 + lg;
        #pragma unroll
        for (int j = 0; j < 4; j++) {
            int cc = n0 + warp_n*32 + j*8 + lq*2;
            float b0 = bias[cc], b1 = bias[cc+1];
            out[(size_t)r0       * ND + cc    ] = acc[i][j][0] + b0;
            out[(size_t)r0       * ND + cc + 1] = acc[i][j][1] + b1;
            out[(size_t)(r0 + 8) * ND + cc    ] = acc[i][j][2] + b0;
            out[(size_t)(r0 + 8) * ND + cc + 1] = acc[i][j][3] + b1;
        }
    }
}

// ---------------------------------------------------------------------------
extern "C" void kernel_launch(void* const* d_in, const int* in_sizes, int n_in,
                              void* d_out, int out_size)
{
    const float* x     = (const float*)d_in[0];
    const float* A_log = (const float*)d_in[1];
    const float* Dvec  = (const float*)d_in[2];
    const float* B_w   = (const float*)d_in[3];
    const float* B_b   = (const float*)d_in[4];
    const float* C_w   = (const float*)d_in[5];
    const float* C_b   = (const float*)d_in[6];
    const float* dt_w  = (const float*)d_in[7];
    const float* dt_b  = (const float*)d_in[8];
    const float* out_w = (const float*)d_in[9];
    const float* out_b = (const float*)d_in[10];
    float* out = (float*)d_out;

    cudaFuncSetAttribute(y_kernel_tc, cudaFuncAttributeMaxDynamicSharedMemorySize,
                         Y_SMEM);

    proj_bc_tf32<<<NTOK/64, 256>>>(x, B_w, B_b, C_w, C_b);
    proj_gemm<<<dim3(1, NTOK/64), 256>>>(x, dt_w, dt_b, NTOK, NH, ND, 2);
    cumsum_kernel<<<NB*NH*NC, NL>>>(A_log);
    states_tc<<<NB*NC*NH, 256>>>(x);
    scan_kernel<<<NB*NH, 256>>>();
    y_kernel_tc<<<NB*NC*NH*4, 256, Y_SMEM>>>(x, Dvec);
    out_gemm_tf32<<<dim3(ND/128, NTOK/128), 256>>>(out_w, out_b, out);
}

// round 10
// speedup vs baseline: 2.6299x; 1.1859x over previous
#include <cuda_runtime.h>
#include <cstdint>
#include <math.h>

#define NB 2
#define NT 4096
#define ND 2048
#define NH 32
#define NN 64
#define NP 64
#define NL 256
#define NC 16
#define NTOK (NB*NT)   // 8192

// swizzled [64][64] accessor (A-frag tiles): 4-group-preserving, conflict-free
#define SW(r,c) (((r)<<6) + ((c) ^ (((r)&15)<<2)))
// pad-72 k-major tiles: row stride 72 floats (72 mod 32 = 8 -> conflict-free
// transposed fragment gathers: bank = lq*8+lg covers all 32 banks)
#define P72 72

// ---------------- scratch (device globals; no runtime allocation) ----------
__device__ float g_B[(size_t)NTOK*NN];
__device__ float g_C[(size_t)NTOK*NN];
__device__ float g_dt[(size_t)NTOK*NH];
__device__ float g_cum[(size_t)NB*NH*NC*NL];
__device__ float g_states[(size_t)NB*NC*NH*NN*NP];
__device__ float g_prev[(size_t)NB*NC*NH*NN*NP];
__device__ float g_Y[(size_t)NTOK*ND];

__device__ __forceinline__ float softplus_f(float v) {
    return v > 20.f ? v : log1pf(expf(v));
}

__device__ __forceinline__ float to_tf32(float v) {
    uint32_t u;
    asm("cvt.rna.tf32.f32 %0, %1;" : "=r"(u) : "f"(v));
    return __uint_as_float(u);
}

__device__ __forceinline__ float4 tf32x4(float4 v) {
    return make_float4(to_tf32(v.x), to_tf32(v.y), to_tf32(v.z), to_tf32(v.w));
}

__device__ __forceinline__ void mma_tf32(float* d, const uint32_t* a, const uint32_t* b) {
    asm volatile(
        "mma.sync.aligned.m16n8k8.row.col.f32.tf32.tf32.f32 "
        "{%0,%1,%2,%3}, {%4,%5,%6,%7}, {%8,%9}, {%0,%1,%2,%3};"
        : "+f"(d[0]), "+f"(d[1]), "+f"(d[2]), "+f"(d[3])
        : "r"(a[0]), "r"(a[1]), "r"(a[2]), "r"(a[3]),
          "r"(b[0]), "r"(b[1]));
}

// ---------------------------------------------------------------------------
// Fused B+C projection, TF32: [g_B | g_C](M,128) = x(M,2048) @ [B_w;C_w]^T
// ---------------------------------------------------------------------------
__global__ __launch_bounds__(256) void proj_bc_tf32(
    const float* __restrict__ x,
    const float* __restrict__ B_w, const float* __restrict__ B_b,
    const float* __restrict__ C_w, const float* __restrict__ C_b)
{
    __shared__ float As[64*36];
    __shared__ float Ws[128*36];
    const int tid = threadIdx.x;
    const int wid = tid >> 5, lane = tid & 31;
    const int wm = wid >> 2, wn = wid & 3;
    const int lg = lane >> 2, lq = lane & 3;
    const int m0 = blockIdx.x * 64;

    float acc[2][4][4];
    #pragma unroll
    for (int i = 0; i < 2; i++)
        #pragma unroll
        for (int j = 0; j < 4; j++)
            #pragma unroll
            for (int q = 0; q < 4; q++) acc[i][j][q] = 0.f;

    for (int k0 = 0; k0 < ND; k0 += 32) {
        {
            int v = tid;
            #pragma unroll
            for (int it = 0; it < 2; it++, v += 256) {
                int row = v >> 3, c4 = (v & 7) * 4;
                float4 av = *(const float4*)&x[(size_t)(m0 + row) * ND + k0 + c4];
                *(float4*)&As[row*36 + c4] = tf32x4(av);
            }
            v = tid;
            #pragma unroll
            for (int it = 0; it < 4; it++, v += 256) {
                int row = v >> 3, c4 = (v & 7) * 4;
                const float* Wp = (row < 64) ? &B_w[(size_t)row * ND]
                                             : &C_w[(size_t)(row - 64) * ND];
                float4 wv = *(const float4*)&Wp[k0 + c4];
                *(float4*)&Ws[row*36 + c4] = tf32x4(wv);
            }
        }
        __syncthreads();
        #pragma unroll
        for (int kk = 0; kk < 32; kk += 8) {
            uint32_t af[2][4], bf[4][2];
            #pragma unroll
            for (int i = 0; i < 2; i++) {
                int r = wm*32 + i*16 + lg;
                af[i][0] = __float_as_uint(As[r*36 + kk + lq]);
                af[i][1] = __float_as_uint(As[(r+8)*36 + kk + lq]);
                af[i][2] = __float_as_uint(As[r*36 + kk + 4 + lq]);
                af[i][3] = __float_as_uint(As[(r+8)*36 + kk + 4 + lq]);
            }
            #pragma unroll
            for (int j = 0; j < 4; j++) {
                int n = wn*32 + j*8 + lg;
                bf[j][0] = __float_as_uint(Ws[n*36 + kk + lq]);
                bf[j][1] = __float_as_uint(Ws[n*36 + kk + 4 + lq]);
            }
            #pragma unroll
            for (int i = 0; i < 2; i++)
                #pragma unroll
                for (int j = 0; j < 4; j++)
                    mma_tf32(acc[i][j], af[i], bf[j]);
        }
        __syncthreads();
    }
    #pragma unroll
    for (int i = 0; i < 2; i++) {
        int r = m0 + wm*32 + i*16 + lg;
        #pragma unroll
        for (int j = 0; j < 4; j++) {
            int n = wn*32 + j*8 + 2*lq;
            if (n < 64) {
                float b0 = B_b[n], b1 = B_b[n+1];
                g_B[(size_t)r*64 + n]       = acc[i][j][0] + b0;
                g_B[(size_t)r*64 + n + 1]   = acc[i][j][1] + b1;
                g_B[(size_t)(r+8)*64 + n]   = acc[i][j][2] + b0;
                g_B[(size_t)(r+8)*64 + n+1] = acc[i][j][3] + b1;
            } else {
                int n2 = n - 64;
                float b0 = C_b[n2], b1 = C_b[n2+1];
                g_C[(size_t)r*64 + n2]       = acc[i][j][0] + b0;
                g_C[(size_t)r*64 + n2 + 1]   = acc[i][j][1] + b1;
                g_C[(size_t)(r+8)*64 + n2]   = acc[i][j][2] + b0;
                g_C[(size_t)(r+8)*64 + n2+1] = acc[i][j][3] + b1;
            }
        }
    }
}

// ---------------------------------------------------------------------------
// dt projection, fp32 scalar, BM=BN=32, grid 256 CTAs (was 128 -> <1 wave)
// ---------------------------------------------------------------------------
__global__ __launch_bounds__(256) void proj_dt32(
    const float* __restrict__ A, const float* __restrict__ W,
    const float* __restrict__ bias)
{
    __shared__ float As[32][36];
    __shared__ float Ws[32][36];
    const int tid = threadIdx.x;
    const int tn = tid & 15, tm = tid >> 4;
    const int m0 = blockIdx.x * 32;
    const int lr = tid >> 3, lk = (tid & 7) * 4;
    float acc[2][2] = {};

    for (int k0 = 0; k0 < ND; k0 += 32) {
        float4 av = *(const float4*)&A[(size_t)(m0 + lr) * ND + k0 + lk];
        float4 wv = *(const float4*)&W[(size_t)lr * ND + k0 + lk];
        As[lk+0][lr] = av.x; As[lk+1][lr] = av.y; As[lk+2][lr] = av.z; As[lk+3][lr] = av.w;
        Ws[lk+0][lr] = wv.x; Ws[lk+1][lr] = wv.y; Ws[lk+2][lr] = wv.z; Ws[lk+3][lr] = wv.w;
        __syncthreads();
        #pragma unroll
        for (int k = 0; k < 32; k++) {
            float a0 = As[k][tm*2], a1 = As[k][tm*2+1];
            float b0 = Ws[k][tn*2], b1 = Ws[k][tn*2+1];
            acc[0][0] = fmaf(a0, b0, acc[0][0]);
            acc[0][1] = fmaf(a0, b1, acc[0][1]);
            acc[1][0] = fmaf(a1, b0, acc[1][0]);
            acc[1][1] = fmaf(a1, b1, acc[1][1]);
        }
        __syncthreads();
    }
    #pragma unroll
    for (int i = 0; i < 2; i++)
        #pragma unroll
        for (int j = 0; j < 2; j++) {
            int m = m0 + tm*2 + i, n = tn*2 + j;
            g_dt[(size_t)m * NH + n] = softplus_f(acc[i][j] + bias[n]);
        }
}

// ---------------------------------------------------------------------------
// Per-(b,h,c) inclusive cumsum of dA = dt * A  over the chunk (L=256)
// ---------------------------------------------------------------------------
__global__ void cumsum_kernel(const float* __restrict__ A_log)
{
    __shared__ float sm[NL];
    int bid = blockIdx.x;
    int c = bid % NC, h = (bid / NC) % NH, b = bid / (NC * NH);
    int s = threadIdx.x;
    float Ah = -expf(A_log[h]);
    int t = c * NL + s;
    sm[s] = g_dt[(size_t)(b*NT + t)*NH + h] * Ah;
    __syncthreads();
    for (int off = 1; off < NL; off <<= 1) {
        float add = (s >= off) ? sm[s - off] : 0.f;
        __syncthreads();
        sm[s] += add;
        __syncthreads();
    }
    g_cum[(size_t)bid * NL + s] = sm[s];
}

// ---------------------------------------------------------------------------
// Chunk states, 1xTF32 mma, native pad-72 tiles (no scalar transpose STS):
//   S[n,p] = sum_s (B[s,n]*w_s) * x[s,p]
// BT [s][n] pad-72, XS [s][p] pad-72, float4 stores; fragments gathered
// transposed (k-major) -> conflict-free.
// ---------------------------------------------------------------------------
__global__ __launch_bounds__(256) void states_tc(const float* __restrict__ x)
{
    __shared__ float BT[64*P72];
    __shared__ float XS[64*P72];
    int bid = blockIdx.x;
    int h = bid % NH, c = (bid / NH) % NC, b = bid / (NH*NC);
    const int tid = threadIdx.x;
    const int wid = tid >> 5, lane = tid & 31;
    const int wm = wid >> 1, wn = wid & 1;
    const int lg = lane >> 2, lq = lane & 3;
    const float* cumc = &g_cum[(size_t)((b*NH + h)*NC + c) * NL];
    const float cum_last = cumc[NL-1];
    const int lr0 = wm*16 + lg;

    float acc[4][4];
    #pragma unroll
    for (int j = 0; j < 4; j++)
        #pragma unroll
        for (int q = 0; q < 4; q++) acc[j][q] = 0.f;

    for (int s0 = 0; s0 < NL; s0 += 64) {
        if (s0) __syncthreads();
        int v = tid;
        #pragma unroll
        for (int it = 0; it < 4; it++, v += 256) {
            int row = v >> 4, c4 = (v & 15) * 4;   // row = s_local
            int gt = c*NL + s0 + row;
            float w = __expf(cum_last - cumc[s0 + row]) *
                      g_dt[(size_t)(b*NT + gt)*NH + h];
            float4 bv = *(const float4*)&g_B[(size_t)(b*NT + gt)*NN + c4];
            float4 xv = *(const float4*)&x[(size_t)(b*NT + gt)*ND + h*NP + c4];
            *(float4*)&BT[row*P72 + c4] =
                make_float4(to_tf32(bv.x*w), to_tf32(bv.y*w),
                            to_tf32(bv.z*w), to_tf32(bv.w*w));
            *(float4*)&XS[row*P72 + c4] = tf32x4(xv);
        }
        __syncthreads();
        #pragma unroll
        for (int kk = 0; kk < 64; kk += 8) {
            uint32_t ah[4];
            // A[m=n][k=s] gathered from BT [s][n]-major
            ah[0] = __float_as_uint(BT[(kk+lq)*P72   + lr0]);
            ah[1] = __float_as_uint(BT[(kk+lq)*P72   + lr0 + 8]);
            ah[2] = __float_as_uint(BT[(kk+4+lq)*P72 + lr0]);
            ah[3] = __float_as_uint(BT[(kk+4+lq)*P72 + lr0 + 8]);
            #pragma unroll
            for (int j = 0; j < 4; j++) {
                int p = wn*32 + j*8 + lg;
                uint32_t bh[2];
                // B[k=s][n=p] gathered from XS [s][p]-major
                bh[0] = __float_as_uint(XS[(kk+lq)*P72   + p]);
                bh[1] = __float_as_uint(XS[(kk+4+lq)*P72 + p]);
                mma_tf32(acc[j], ah, bh);
            }
        }
    }
    float* S = &g_states[(((size_t)b*NC + c)*NH + h) * (NN*NP)];
    #pragma unroll
    for (int j = 0; j < 4; j++) {
        int p = wn*32 + j*8 + 2*lq;
        S[(size_t)lr0*NP + p]         = acc[j][0];
        S[(size_t)lr0*NP + p + 1]     = acc[j][1];
        S[(size_t)(lr0+8)*NP + p]     = acc[j][2];
        S[(size_t)(lr0+8)*NP + p + 1] = acc[j][3];
    }
}

// ---------------------------------------------------------------------------
// Inter-chunk scan, element-parallel: grid NB*NH*16, 256 thr; each thread
// owns ONE state element's 16-chunk chain.
// ---------------------------------------------------------------------------
__global__ void scan_kernel()
{
    int bid = blockIdx.x;
    int ec = bid & 15;              // element chunk (256 elems each)
    int bh = bid >> 4;              // b*NH + h
    int h = bh % NH, b = bh / NH;
    int e = ec * 256 + threadIdx.x; // 0..4095
    float R = 0.f;
    #pragma unroll 1
    for (int c = 0; c < NC; c++) {
        size_t off = (((size_t)b*NC + c)*NH + h) * (NN*NP) + e;
        g_prev[off] = R;
        float dec = __expf(g_cum[(size_t)((b*NH + h)*NC + c)*NL + NL - 1]);
        R = fmaf(dec, R, g_states[off]);
    }
}

// ---------------------------------------------------------------------------
// Y kernel (1xTF32, rank-1 decay factorization; XT native pad-72 float4
// staging — no scalar transpose stores).
// smem floats: Cs 4096 | BG 4096 | GS 4096 | XT 64*72  -> 67584 bytes
// ---------------------------------------------------------------------------
#define Y_SMEM ((12288 + 64*P72)*4)
__global__ __launch_bounds__(256) void y_kernel_tc(const float* __restrict__ x,
                                                   const float* __restrict__ Dvec)
{
    extern __shared__ float ysm[];
    float* Cs = ysm;             // C tile [l][n] swizzled
    float* BG = ysm + 4096;      // B tile [s][n] swizzled
    float* GS = ysm + 8192;      // G [l][s] swizzled
    float* XT = ysm + 12288;     // S [n][p] / (x*dt*e_s) [s][p], pad-72

    int bid = blockIdx.x;
    int lt = bid & 3;
    int h  = (bid >> 2) & 31;
    int c  = (bid >> 7) & 15;
    int b  = bid >> 11;
    const int tid = threadIdx.x;
    const int wid = tid >> 5, lane = tid & 31;
    const int wm = wid >> 1, wn = wid & 1;
    const int lg = lane >> 2, lq = lane & 3;
    const int t0 = c * NL;
    const float* cumc = &g_cum[(size_t)((b*NH + h)*NC + c) * NL];

    {   // load C tile (swizzled) and S_prev native [n][p] pad-72
        const float* S = &g_prev[(((size_t)b*NC + c)*NH + h) * (NN*NP)];
        int v = tid;
        #pragma unroll
        for (int it = 0; it < 4; it++, v += 256) {
            int row = v >> 4, c4 = (v & 15) * 4;
            float4 cv = *(const float4*)&g_C[(size_t)(b*NT + t0 + lt*64 + row)*NN + c4];
            *(float4*)&Cs[SW(row, c4)] = tf32x4(cv);
            float4 sv = *(const float4*)&S[row*64 + c4];   // row=n, c4=p
            *(float4*)&XT[row*P72 + c4] = tf32x4(sv);
        }
    }
    __syncthreads();

    const int lr0 = wm*16 + lg;
    const float cl0 = cumc[lt*64 + lr0];
    const float cl1 = cumc[lt*64 + lr0 + 8];

    float acc[4][4];
    #pragma unroll
    for (int j = 0; j < 4; j++)
        #pragma unroll
        for (int q = 0; q < 4; q++) acc[j][q] = 0.f;

    // ---- Y_off = C @ S_prev, then scale by exp(cum_l)
    #pragma unroll
    for (int kk = 0; kk < 64; kk += 8) {
        uint32_t ah[4];
        ah[0] = __float_as_uint(Cs[SW(lr0,   kk + lq)]);
        ah[1] = __float_as_uint(Cs[SW(lr0+8, kk + lq)]);
        ah[2] = __float_as_uint(Cs[SW(lr0,   kk + 4 + lq)]);
        ah[3] = __float_as_uint(Cs[SW(lr0+8, kk + 4 + lq)]);
        #pragma unroll
        for (int j = 0; j < 4; j++) {
            int p = wn*32 + j*8 + lg;
            uint32_t bh[2];
            // B[k=n][n-dim=p] from XT [n][p]-major
            bh[0] = __float_as_uint(XT[(kk+lq)*P72   + p]);
            bh[1] = __float_as_uint(XT[(kk+4+lq)*P72 + p]);
            mma_tf32(acc[j], ah, bh);
        }
    }
    {
        float e0 = __expf(cl0), e1 = __expf(cl1);
        #pragma unroll
        for (int j = 0; j < 4; j++) {
            acc[j][0] *= e0; acc[j][1] *= e0;
            acc[j][2] *= e1; acc[j][3] *= e1;
        }
    }

    // ---- causal s-tiles
    for (int st = 0; st <= lt; st++) {
        const bool offdiag = (st < lt);
        const float m = cumc[st*64 + 63];
        __syncthreads();
        {   // B tile swizzled [s][n]; X' native [s][p] pad-72
            int v = tid;
            #pragma unroll
            for (int it = 0; it < 4; it++, v += 256) {
                int row = v >> 4, c4 = (v & 15) * 4;
                int gt = t0 + st*64 + row;
                float4 bv = *(const float4*)&g_B[(size_t)(b*NT + gt)*NN + c4];
                *(float4*)&BG[SW(row, c4)] = tf32x4(bv);
                float sc = g_dt[(size_t)(b*NT + gt)*NH + h];
                if (offdiag) sc *= __expf(m - cumc[st*64 + row]);
                float4 xv = *(const float4*)&x[(size_t)(b*NT + gt)*ND + h*NP + c4];
                *(float4*)&XT[row*P72 + c4] =
                    make_float4(to_tf32(xv.x*sc), to_tf32(xv.y*sc),
                                to_tf32(xv.z*sc), to_tf32(xv.w*sc));
            }
        }
        __syncthreads();

        // G = C @ B^T
        float ga[4][4];
        #pragma unroll
        for (int j = 0; j < 4; j++)
            #pragma unroll
            for (int q = 0; q < 4; q++) ga[j][q] = 0.f;
        #pragma unroll
        for (int kk = 0; kk < 64; kk += 8) {
            uint32_t ah[4];
            ah[0] = __float_as_uint(Cs[SW(lr0,   kk + lq)]);
            ah[1] = __float_as_uint(Cs[SW(lr0+8, kk + lq)]);
            ah[2] = __float_as_uint(Cs[SW(lr0,   kk + 4 + lq)]);
            ah[3] = __float_as_uint(Cs[SW(lr0+8, kk + 4 + lq)]);
            #pragma unroll
            for (int j = 0; j < 4; j++) {
                int s = wn*32 + j*8 + lg;
                uint32_t bh[2];
                bh[0] = __float_as_uint(BG[SW(s, kk + lq)]);
                bh[1] = __float_as_uint(BG[SW(s, kk + 4 + lq)]);
                mma_tf32(ga[j], ah, bh);
            }
        }
        if (!offdiag) {
            int l0 = lr0, l1 = lr0 + 8;
            #pragma unroll
            for (int j = 0; j < 4; j++) {
                int s0c = wn*32 + j*8 + 2*lq;
                float cs0 = cumc[st*64 + s0c];
                float cs1 = cumc[st*64 + s0c + 1];
                ga[j][0] = (s0c     <= l0) ? ga[j][0] * __expf(cl0 - cs0) : 0.f;
                ga[j][1] = (s0c + 1 <= l0) ? ga[j][1] * __expf(cl0 - cs1) : 0.f;
                ga[j][2] = (s0c     <= l1) ? ga[j][2] * __expf(cl1 - cs0) : 0.f;
                ga[j][3] = (s0c + 1 <= l1) ? ga[j][3] * __expf(cl1 - cs1) : 0.f;
            }
        }
        {   // write G to its own buffer
            #pragma unroll
            for (int j = 0; j < 4; j++) {
                int col = wn*32 + j*8 + 2*lq;
                GS[SW(lr0,   col)]     = to_tf32(ga[j][0]);
                GS[SW(lr0,   col + 1)] = to_tf32(ga[j][1]);
                GS[SW(lr0+8, col)]     = to_tf32(ga[j][2]);
                GS[SW(lr0+8, col + 1)] = to_tf32(ga[j][3]);
            }
        }
        __syncthreads();

        if (offdiag) {
            #pragma unroll
            for (int j = 0; j < 4; j++)
                #pragma unroll
                for (int q = 0; q < 4; q++) ga[j][q] = 0.f;
            #pragma unroll
            for (int kk = 0; kk < 64; kk += 8) {
                uint32_t ah[4];
                ah[0] = __float_as_uint(GS[SW(lr0,   kk + lq)]);
                ah[1] = __float_as_uint(GS[SW(lr0+8, kk + lq)]);
                ah[2] = __float_as_uint(GS[SW(lr0,   kk + 4 + lq)]);
                ah[3] = __float_as_uint(GS[SW(lr0+8, kk + 4 + lq)]);
                #pragma unroll
                for (int j = 0; j < 4; j++) {
                    int p = wn*32 + j*8 + lg;
                    uint32_t bh[2];
                    bh[0] = __float_as_uint(XT[(kk+lq)*P72   + p]);
                    bh[1] = __float_as_uint(XT[(kk+4+lq)*P72 + p]);
                    mma_tf32(ga[j], ah, bh);
                }
            }
            float e0 = __expf(cl0 - m), e1 = __expf(cl1 - m);
            #pragma unroll
            for (int j = 0; j < 4; j++) {
                acc[j][0] = fmaf(e0, ga[j][0], acc[j][0]);
                acc[j][1] = fmaf(e0, ga[j][1], acc[j][1]);
                acc[j][2] = fmaf(e1, ga[j][2], acc[j][2]);
                acc[j][3] = fmaf(e1, ga[j][3], acc[j][3]);
            }
        } else {
            #pragma unroll
            for (int kk = 0; kk < 64; kk += 8) {
                uint32_t ah[4];
                ah[0] = __float_as_uint(GS[SW(lr0,   kk + lq)]);
                ah[1] = __float_as_uint(GS[SW(lr0+8, kk + lq)]);
                ah[2] = __float_as_uint(GS[SW(lr0,   kk + 4 + lq)]);
                ah[3] = __float_as_uint(GS[SW(lr0+8, kk + 4 + lq)]);
                #pragma unroll
                for (int j = 0; j < 4; j++) {
                    int p = wn*32 + j*8 + lg;
                    uint32_t bh[2];
                    bh[0] = __float_as_uint(XT[(kk+lq)*P72   + p]);
                    bh[1] = __float_as_uint(XT[(kk+4+lq)*P72 + p]);
                    mma_tf32(acc[j], ah, bh);
                }
            }
        }
    }

    // ---- epilogue: + D_h * x, store
    float Dh = Dvec[h];
    int gt0 = t0 + lt*64 + lr0;
    #pragma unroll
    for (int j = 0; j < 4; j++) {
        int p = wn*32 + j*8 + 2*lq;
        size_t o0 = (size_t)(b*NT + gt0)*ND + h*NP + p;
        size_t o1 = o0 + (size_t)8*ND;
        g_Y[o0]     = acc[j][0] + Dh * x[o0];
        g_Y[o0 + 1] = acc[j][1] + Dh * x[o0 + 1];
        g_Y[o1]     = acc[j][2] + Dh * x[o1];
        g_Y[o1 + 1] = acc[j][3] + Dh * x[o1 + 1];
    }
}

// ---------------------------------------------------------------------------
// Output projection, TF32 mma.sync (proven):
// ---------------------------------------------------------------------------
__global__ __launch_bounds__(256) void out_gemm_tf32(
    const float* __restrict__ W, const float* __restrict__ bias,
    float* __restrict__ out)
{
    __shared__ float As[128][36];
    __shared__ float Ws[128][36];
    const int tid  = threadIdx.x;
    const int wid  = tid >> 5, lane = tid & 31;
    const int warp_m = wid >> 2, warp_n = wid & 3;   // 2 x 4
    const int m0 = blockIdx.y * 128, n0 = blockIdx.x * 128;
    const int qrow = tid >> 3;
    const int qc4  = (tid & 7) * 4;
    const int lg = lane >> 2, lq = lane & 3;
    const float* A = g_Y;

    float acc[4][4][4];
    #pragma unroll
    for (int i = 0; i < 4; i++)
        #pragma unroll
        for (int j = 0; j < 4; j++)
            #pragma unroll
            for (int q = 0; q < 4; q++) acc[i][j][q] = 0.f;

    float4 pa[4], pw[4];
    #pragma unroll
    for (int it = 0; it < 4; it++) {
        int r = qrow + it * 32;
        pa[it] = *(const float4*)&A[(size_t)(m0 + r) * ND + qc4];
        pw[it] = *(const float4*)&W[(size_t)(n0 + r) * ND + qc4];
    }

    for (int k0 = 0; k0 < ND; k0 += 32) {
        #pragma unroll
        for (int it = 0; it < 4; it++) {
            int r = qrow + it * 32;
            As[r][qc4+0] = to_tf32(pa[it].x); As[r][qc4+1] = to_tf32(pa[it].y);
            As[r][qc4+2] = to_tf32(pa[it].z); As[r][qc4+3] = to_tf32(pa[it].w);
            Ws[r][qc4+0] = to_tf32(pw[it].x); Ws[r][qc4+1] = to_tf32(pw[it].y);
            Ws[r][qc4+2] = to_tf32(pw[it].z); Ws[r][qc4+3] = to_tf32(pw[it].w);
        }
        __syncthreads();

        if (k0 + 32 < ND) {
            #pragma unroll
            for (int it = 0; it < 4; it++) {
                int r = qrow + it * 32;
                pa[it] = *(const float4*)&A[(size_t)(m0 + r) * ND + k0 + 32 + qc4];
                pw[it] = *(const float4*)&W[(size_t)(n0 + r) * ND + k0 + 32 + qc4];
            }
        }

        #pragma unroll
        for (int kk = 0; kk < 32; kk += 8) {
            uint32_t afr[4][4], bfr[4][2];
            #pragma unroll
            for (int i = 0; i < 4; i++) {
                int row = warp_m*64 + i*16 + lg;
                afr[i][0] = __float_as_uint(As[row    ][kk + lq]);
                afr[i][1] = __float_as_uint(As[row + 8][kk + lq]);
                afr[i][2] = __float_as_uint(As[row    ][kk + 4 + lq]);
                afr[i][3] = __float_as_uint(As[row + 8][kk + 4 + lq]);
            }
            #pragma unroll
            for (int j = 0; j < 4; j++) {
                int nrow = warp_n*32 + j*8 + lg;
                bfr[j][0] = __float_as_uint(Ws[nrow][kk + lq]);
                bfr[j][1] = __float_as_uint(Ws[nrow][kk + 4 + lq]);
            }
            #pragma unroll
            for (int i = 0; i < 4; i++)
                #pragma unroll
                for (int j = 0; j < 4; j++)
                    mma_tf32(acc[i][j], afr[i], bfr[j]);
        }
        __syncthreads();
    }

    #pragma unroll
    for (int i = 0; i < 4; i++) {
        int r0 = m0 + warp_m*64 + i*16 + lg;
        #pragma unroll
        for (int j = 0; j < 4; j++) {
            int cc = n0 + warp_n*32 + j*8 + lq*2;
            float b0 = bias[cc], b1 = bias[cc+1];
            out[(size_t)r0       * ND + cc    ] = acc[i][j][0] + b0;
            out[(size_t)r0       * ND + cc + 1] = acc[i][j][1] + b1;
            out[(size_t)(r0 + 8) * ND + cc    ] = acc[i][j][2] + b0;
            out[(size_t)(r0 + 8) * ND + cc + 1] = acc[i][j][3] + b1;
        }
    }
}

// ---------------------------------------------------------------------------
extern "C" void kernel_launch(void* const* d_in, const int* in_sizes, int n_in,
                              void* d_out, int out_size)
{
    const float* x     = (const float*)d_in[0];
    const float* A_log = (const float*)d_in[1];
    const float* Dvec  = (const float*)d_in[2];
    const float* B_w   = (const float*)d_in[3];
    const float* B_b   = (const float*)d_in[4];
    const float* C_w   = (const float*)d_in[5];
    const float* C_b   = (const float*)d_in[6];
    const float* dt_w  = (const float*)d_in[7];
    const float* dt_b  = (const float*)d_in[8];
    const float* out_w = (const float*)d_in[9];
    const float* out_b = (const float*)d_in[10];
    float* out = (float*)d_out;

    cudaFuncSetAttribute(y_kernel_tc, cudaFuncAttributeMaxDynamicSharedMemorySize,
                         Y_SMEM);

    proj_bc_tf32<<<NTOK/64, 256>>>(x, B_w, B_b, C_w, C_b);
    proj_dt32<<<NTOK/32, 256>>>(x, dt_w, dt_b);
    cumsum_kernel<<<NB*NH*NC, NL>>>(A_log);
    states_tc<<<NB*NC*NH, 256>>>(x);
    scan_kernel<<<NB*NH*16, 256>>>();
    y_kernel_tc<<<NB*NC*NH*4, 256, Y_SMEM>>>(x, Dvec);
    out_gemm_tf32<<<dim3(ND/128, NTOK/128), 256>>>(out_w, out_b, out);
}

// round 11
// speedup vs baseline: 2.6408x; 1.0041x over previous
#include <cuda_runtime.h>
#include <cstdint>
#include <math.h>

#define NB 2
#define NT 4096
#define ND 2048
#define NH 32
#define NN 64
#define NP 64
#define NL 256
#define NC 16
#define NTOK (NB*NT)   // 8192

// swizzled [64][64] accessor (A-frag tiles): 4-group-preserving, conflict-free
#define SW(r,c) (((r)<<6) + ((c) ^ (((r)&15)<<2)))
// pad-72 k-major tiles: conflict-free transposed fragment gathers
#define P72 72

// ---------------- scratch (device globals; no runtime allocation) ----------
__device__ float g_B[(size_t)NTOK*NN];
__device__ float g_C[(size_t)NTOK*NN];
__device__ float g_dt[(size_t)NTOK*NH];
__device__ float g_cum[(size_t)NB*NH*NC*NL];
__device__ float g_states[(size_t)NB*NC*NH*NN*NP];
__device__ float g_prev[(size_t)NB*NC*NH*NN*NP];
__device__ float g_Y[(size_t)NTOK*ND];

__device__ __forceinline__ float softplus_f(float v) {
    return v > 20.f ? v : log1pf(expf(v));
}

__device__ __forceinline__ float to_tf32(float v) {
    uint32_t u;
    asm("cvt.rna.tf32.f32 %0, %1;" : "=r"(u) : "f"(v));
    return __uint_as_float(u);
}

__device__ __forceinline__ float4 tf32x4(float4 v) {
    return make_float4(to_tf32(v.x), to_tf32(v.y), to_tf32(v.z), to_tf32(v.w));
}

__device__ __forceinline__ void mma_tf32(float* d, const uint32_t* a, const uint32_t* b) {
    asm volatile(
        "mma.sync.aligned.m16n8k8.row.col.f32.tf32.tf32.f32 "
        "{%0,%1,%2,%3}, {%4,%5,%6,%7}, {%8,%9}, {%0,%1,%2,%3};"
        : "+f"(d[0]), "+f"(d[1]), "+f"(d[2]), "+f"(d[3])
        : "r"(a[0]), "r"(a[1]), "r"(a[2]), "r"(a[3]),
          "r"(b[0]), "r"(b[1]));
}

// ---------------------------------------------------------------------------
// B/C projection, TF32, BN=64 (256 CTAs -> full wave):
//   blockIdx.y == 0 -> g_B = x @ B_w^T + B_b ; == 1 -> g_C
// 8 warps: 2m x 4n, warp tile 32x16.
// ---------------------------------------------------------------------------
__global__ __launch_bounds__(256) void proj_bc64(
    const float* __restrict__ x,
    const float* __restrict__ B_w, const float* __restrict__ B_b,
    const float* __restrict__ C_w, const float* __restrict__ C_b)
{
    __shared__ float As[64*36];
    __shared__ float Ws[64*36];
    const int tid = threadIdx.x;
    const int wid = tid >> 5, lane = tid & 31;
    const int wm = wid >> 2, wn = wid & 3;
    const int lg = lane >> 2, lq = lane & 3;
    const int m0 = blockIdx.x * 64;
    const int osel = blockIdx.y;
    const float* W = osel ? C_w : B_w;
    const float* bias = osel ? C_b : B_b;
    float* out = osel ? g_C : g_B;

    float acc[2][2][4];
    #pragma unroll
    for (int i = 0; i < 2; i++)
        #pragma unroll
        for (int j = 0; j < 2; j++)
            #pragma unroll
            for (int q = 0; q < 4; q++) acc[i][j][q] = 0.f;

    for (int k0 = 0; k0 < ND; k0 += 32) {
        int v = tid;
        #pragma unroll
        for (int it = 0; it < 2; it++, v += 256) {
            int row = v >> 3, c4 = (v & 7) * 4;
            float4 av = *(const float4*)&x[(size_t)(m0 + row) * ND + k0 + c4];
            *(float4*)&As[row*36 + c4] = tf32x4(av);
            float4 wv = *(const float4*)&W[(size_t)row * ND + k0 + c4];
            *(float4*)&Ws[row*36 + c4] = tf32x4(wv);
        }
        __syncthreads();
        #pragma unroll
        for (int kk = 0; kk < 32; kk += 8) {
            uint32_t af[2][4], bf[2][2];
            #pragma unroll
            for (int i = 0; i < 2; i++) {
                int r = wm*32 + i*16 + lg;
                af[i][0] = __float_as_uint(As[r*36 + kk + lq]);
                af[i][1] = __float_as_uint(As[(r+8)*36 + kk + lq]);
                af[i][2] = __float_as_uint(As[r*36 + kk + 4 + lq]);
                af[i][3] = __float_as_uint(As[(r+8)*36 + kk + 4 + lq]);
            }
            #pragma unroll
            for (int j = 0; j < 2; j++) {
                int n = wn*16 + j*8 + lg;
                bf[j][0] = __float_as_uint(Ws[n*36 + kk + lq]);
                bf[j][1] = __float_as_uint(Ws[n*36 + kk + 4 + lq]);
            }
            #pragma unroll
            for (int i = 0; i < 2; i++)
                #pragma unroll
                for (int j = 0; j < 2; j++)
                    mma_tf32(acc[i][j], af[i], bf[j]);
        }
        __syncthreads();
    }
    #pragma unroll
    for (int i = 0; i < 2; i++) {
        int r = m0 + wm*32 + i*16 + lg;
        #pragma unroll
        for (int j = 0; j < 2; j++) {
            int n = wn*16 + j*8 + 2*lq;
            float b0 = bias[n], b1 = bias[n+1];
            out[(size_t)r*64 + n]       = acc[i][j][0] + b0;
            out[(size_t)r*64 + n + 1]   = acc[i][j][1] + b1;
            out[(size_t)(r+8)*64 + n]   = acc[i][j][2] + b0;
            out[(size_t)(r+8)*64 + n+1] = acc[i][j][3] + b1;
        }
    }
}

// ---------------------------------------------------------------------------
// dt projection, fp32 scalar, BM=32, 256 CTAs
// ---------------------------------------------------------------------------
__global__ __launch_bounds__(256) void proj_dt32(
    const float* __restrict__ A, const float* __restrict__ W,
    const float* __restrict__ bias)
{
    __shared__ float As[32][36];
    __shared__ float Ws[32][36];
    const int tid = threadIdx.x;
    const int tn = tid & 15, tm = tid >> 4;
    const int m0 = blockIdx.x * 32;
    const int lr = tid >> 3, lk = (tid & 7) * 4;
    float acc[2][2] = {};

    for (int k0 = 0; k0 < ND; k0 += 32) {
        float4 av = *(const float4*)&A[(size_t)(m0 + lr) * ND + k0 + lk];
        float4 wv = *(const float4*)&W[(size_t)lr * ND + k0 + lk];
        As[lk+0][lr] = av.x; As[lk+1][lr] = av.y; As[lk+2][lr] = av.z; As[lk+3][lr] = av.w;
        Ws[lk+0][lr] = wv.x; Ws[lk+1][lr] = wv.y; Ws[lk+2][lr] = wv.z; Ws[lk+3][lr] = wv.w;
        __syncthreads();
        #pragma unroll
        for (int k = 0; k < 32; k++) {
            float a0 = As[k][tm*2], a1 = As[k][tm*2+1];
            float b0 = Ws[k][tn*2], b1 = Ws[k][tn*2+1];
            acc[0][0] = fmaf(a0, b0, acc[0][0]);
            acc[0][1] = fmaf(a0, b1, acc[0][1]);
            acc[1][0] = fmaf(a1, b0, acc[1][0]);
            acc[1][1] = fmaf(a1, b1, acc[1][1]);
        }
        __syncthreads();
    }
    #pragma unroll
    for (int i = 0; i < 2; i++)
        #pragma unroll
        for (int j = 0; j < 2; j++) {
            int m = m0 + tm*2 + i, n = tn*2 + j;
            g_dt[(size_t)m * NH + n] = softplus_f(acc[i][j] + bias[n]);
        }
}

// ---------------------------------------------------------------------------
// Per-(b,h,c) inclusive cumsum of dA = dt * A  over the chunk (L=256)
// ---------------------------------------------------------------------------
__global__ void cumsum_kernel(const float* __restrict__ A_log)
{
    __shared__ float sm[NL];
    int bid = blockIdx.x;
    int c = bid % NC, h = (bid / NC) % NH, b = bid / (NC * NH);
    int s = threadIdx.x;
    float Ah = -expf(A_log[h]);
    int t = c * NL + s;
    sm[s] = g_dt[(size_t)(b*NT + t)*NH + h] * Ah;
    __syncthreads();
    for (int off = 1; off < NL; off <<= 1) {
        float add = (s >= off) ? sm[s - off] : 0.f;
        __syncthreads();
        sm[s] += add;
        __syncthreads();
    }
    g_cum[(size_t)bid * NL + s] = sm[s];
}

// ---------------------------------------------------------------------------
// Chunk states, 1xTF32 mma, pad-72 tiles (proven R10)
// ---------------------------------------------------------------------------
__global__ __launch_bounds__(256) void states_tc(const float* __restrict__ x)
{
    __shared__ float BT[64*P72];
    __shared__ float XS[64*P72];
    int bid = blockIdx.x;
    int h = bid % NH, c = (bid / NH) % NC, b = bid / (NH*NC);
    const int tid = threadIdx.x;
    const int wid = tid >> 5, lane = tid & 31;
    const int wm = wid >> 1, wn = wid & 1;
    const int lg = lane >> 2, lq = lane & 3;
    const float* cumc = &g_cum[(size_t)((b*NH + h)*NC + c) * NL];
    const float cum_last = cumc[NL-1];
    const int lr0 = wm*16 + lg;

    float acc[4][4];
    #pragma unroll
    for (int j = 0; j < 4; j++)
        #pragma unroll
        for (int q = 0; q < 4; q++) acc[j][q] = 0.f;

    for (int s0 = 0; s0 < NL; s0 += 64) {
        if (s0) __syncthreads();
        int v = tid;
        #pragma unroll
        for (int it = 0; it < 4; it++, v += 256) {
            int row = v >> 4, c4 = (v & 15) * 4;
            int gt = c*NL + s0 + row;
            float w = __expf(cum_last - cumc[s0 + row]) *
                      g_dt[(size_t)(b*NT + gt)*NH + h];
            float4 bv = *(const float4*)&g_B[(size_t)(b*NT + gt)*NN + c4];
            float4 xv = *(const float4*)&x[(size_t)(b*NT + gt)*ND + h*NP + c4];
            *(float4*)&BT[row*P72 + c4] =
                make_float4(to_tf32(bv.x*w), to_tf32(bv.y*w),
                            to_tf32(bv.z*w), to_tf32(bv.w*w));
            *(float4*)&XS[row*P72 + c4] = tf32x4(xv);
        }
        __syncthreads();
        #pragma unroll
        for (int kk = 0; kk < 64; kk += 8) {
            uint32_t ah[4];
            ah[0] = __float_as_uint(BT[(kk+lq)*P72   + lr0]);
            ah[1] = __float_as_uint(BT[(kk+lq)*P72   + lr0 + 8]);
            ah[2] = __float_as_uint(BT[(kk+4+lq)*P72 + lr0]);
            ah[3] = __float_as_uint(BT[(kk+4+lq)*P72 + lr0 + 8]);
            #pragma unroll
            for (int j = 0; j < 4; j++) {
                int p = wn*32 + j*8 + lg;
                uint32_t bh[2];
                bh[0] = __float_as_uint(XS[(kk+lq)*P72   + p]);
                bh[1] = __float_as_uint(XS[(kk+4+lq)*P72 + p]);
                mma_tf32(acc[j], ah, bh);
            }
        }
    }
    float* S = &g_states[(((size_t)b*NC + c)*NH + h) * (NN*NP)];
    #pragma unroll
    for (int j = 0; j < 4; j++) {
        int p = wn*32 + j*8 + 2*lq;
        S[(size_t)lr0*NP + p]         = acc[j][0];
        S[(size_t)lr0*NP + p + 1]     = acc[j][1];
        S[(size_t)(lr0+8)*NP + p]     = acc[j][2];
        S[(size_t)(lr0+8)*NP + p + 1] = acc[j][3];
    }
}

// ---------------------------------------------------------------------------
// Inter-chunk scan, element-parallel (proven R10)
// ---------------------------------------------------------------------------
__global__ void scan_kernel()
{
    int bid = blockIdx.x;
    int ec = bid & 15;
    int bh = bid >> 4;
    int h = bh % NH, b = bh / NH;
    int e = ec * 256 + threadIdx.x;
    float R = 0.f;
    #pragma unroll 1
    for (int c = 0; c < NC; c++) {
        size_t off = (((size_t)b*NC + c)*NH + h) * (NN*NP) + e;
        g_prev[off] = R;
        float dec = __expf(g_cum[(size_t)((b*NH + h)*NC + c)*NL + NL - 1]);
        R = fmaf(dec, R, g_states[off]);
    }
}

// ---------------------------------------------------------------------------
// Y kernel, merged l-tile pairs: one CTA handles lt in {pr*2, pr*2+1}.
// Shared s-tile staging (B/xdt loaded once per st, serving both lts),
// ES[s] = exp(m - cs) smem table applied to offdiag G (X stays unscaled so
// the diagonal path keeps per-element exp+mask).
// smem floats: Cs[2]*4096 | BG 4096 | GS[2]*4096 | XT 64*72 | ES 64
// ---------------------------------------------------------------------------
#define Y_SMEM ((5*4096 + 64*P72 + 64)*4)
__global__ __launch_bounds__(256) void y_kernel_tc(const float* __restrict__ x,
                                                   const float* __restrict__ Dvec)
{
    extern __shared__ float ysm[];
    float* Cs  = ysm;                 // 2 tiles, swizzled
    float* BG  = ysm + 8192;
    float* GS  = ysm + 12288;         // 2 tiles, swizzled
    float* XT  = ysm + 20480;         // pad-72
    float* ES  = ysm + 20480 + 64*P72;

    int bid = blockIdx.x;
    int pr = bid & 1;
    int h  = (bid >> 1) & 31;
    int c  = (bid >> 6) & 15;
    int b  = bid >> 10;
    const int lt0 = pr*2, lt1 = lt0 + 1;
    const int tid = threadIdx.x;
    const int wid = tid >> 5, lane = tid & 31;
    const int wm = wid >> 1, wn = wid & 1;
    const int lg = lane >> 2, lq = lane & 3;
    const int t0 = c * NL;
    const float* cumc = &g_cum[(size_t)((b*NH + h)*NC + c) * NL];

    {   // load both C tiles (swizzled) and S_prev (pad-72)
        const float* S = &g_prev[(((size_t)b*NC + c)*NH + h) * (NN*NP)];
        #pragma unroll
        for (int t = 0; t < 2; t++) {
            int v = tid;
            #pragma unroll
            for (int it = 0; it < 4; it++, v += 256) {
                int row = v >> 4, c4 = (v & 15) * 4;
                float4 cv = *(const float4*)
                    &g_C[(size_t)(b*NT + t0 + (lt0+t)*64 + row)*NN + c4];
                *(float4*)&Cs[t*4096 + SW(row, c4)] = tf32x4(cv);
            }
        }
        int v = tid;
        #pragma unroll
        for (int it = 0; it < 4; it++, v += 256) {
            int row = v >> 4, c4 = (v & 15) * 4;
            float4 sv = *(const float4*)&S[row*64 + c4];
            *(float4*)&XT[row*P72 + c4] = tf32x4(sv);
        }
    }
    __syncthreads();

    const int lr0 = wm*16 + lg;
    float cl[2][2];
    #pragma unroll
    for (int t = 0; t < 2; t++) {
        cl[t][0] = cumc[(lt0+t)*64 + lr0];
        cl[t][1] = cumc[(lt0+t)*64 + lr0 + 8];
    }

    float acc[2][4][4];
    #pragma unroll
    for (int t = 0; t < 2; t++)
        #pragma unroll
        for (int j = 0; j < 4; j++)
            #pragma unroll
            for (int q = 0; q < 4; q++) acc[t][j][q] = 0.f;

    // ---- Y_off = C @ S_prev, scale by exp(cum_l), both lts
    #pragma unroll
    for (int t = 0; t < 2; t++) {
        const float* Ct = Cs + t*4096;
        #pragma unroll
        for (int kk = 0; kk < 64; kk += 8) {
            uint32_t ah[4];
            ah[0] = __float_as_uint(Ct[SW(lr0,   kk + lq)]);
            ah[1] = __float_as_uint(Ct[SW(lr0+8, kk + lq)]);
            ah[2] = __float_as_uint(Ct[SW(lr0,   kk + 4 + lq)]);
            ah[3] = __float_as_uint(Ct[SW(lr0+8, kk + 4 + lq)]);
            #pragma unroll
            for (int j = 0; j < 4; j++) {
                int p = wn*32 + j*8 + lg;
                uint32_t bh[2];
                bh[0] = __float_as_uint(XT[(kk+lq)*P72   + p]);
                bh[1] = __float_as_uint(XT[(kk+4+lq)*P72 + p]);
                mma_tf32(acc[t][j], ah, bh);
            }
        }
        float e0 = __expf(cl[t][0]), e1 = __expf(cl[t][1]);
        #pragma unroll
        for (int j = 0; j < 4; j++) {
            acc[t][j][0] *= e0; acc[t][j][1] *= e0;
            acc[t][j][2] *= e1; acc[t][j][3] *= e1;
        }
    }

    // ---- causal s-tiles (shared staging for both lts)
    for (int st = 0; st <= lt1; st++) {
        const float m = cumc[st*64 + 63];
        __syncthreads();
        {   // BG swizzled [s][n]; XT = xdt (unscaled) [s][p] pad-72; ES table
            int v = tid;
            #pragma unroll
            for (int it = 0; it < 4; it++, v += 256) {
                int row = v >> 4, c4 = (v & 15) * 4;
                int gt = t0 + st*64 + row;
                float4 bv = *(const float4*)&g_B[(size_t)(b*NT + gt)*NN + c4];
                *(float4*)&BG[SW(row, c4)] = tf32x4(bv);
                float sc = g_dt[(size_t)(b*NT + gt)*NH + h];
                float4 xv = *(const float4*)&x[(size_t)(b*NT + gt)*ND + h*NP + c4];
                *(float4*)&XT[row*P72 + c4] =
                    make_float4(to_tf32(xv.x*sc), to_tf32(xv.y*sc),
                                to_tf32(xv.z*sc), to_tf32(xv.w*sc));
            }
            if (tid < 64) ES[tid] = __expf(m - cumc[st*64 + tid]);
        }
        __syncthreads();

        // G phase for each live lt
        #pragma unroll
        for (int t = 0; t < 2; t++) {
            int lt = lt0 + t;
            if (st > lt) continue;
            const float* Ct = Cs + t*4096;
            float ga[4][4];
            #pragma unroll
            for (int j = 0; j < 4; j++)
                #pragma unroll
                for (int q = 0; q < 4; q++) ga[j][q] = 0.f;
            #pragma unroll
            for (int kk = 0; kk < 64; kk += 8) {
                uint32_t ah[4];
                ah[0] = __float_as_uint(Ct[SW(lr0,   kk + lq)]);
                ah[1] = __float_as_uint(Ct[SW(lr0+8, kk + lq)]);
                ah[2] = __float_as_uint(Ct[SW(lr0,   kk + 4 + lq)]);
                ah[3] = __float_as_uint(Ct[SW(lr0+8, kk + 4 + lq)]);
                #pragma unroll
                for (int j = 0; j < 4; j++) {
                    int s = wn*32 + j*8 + lg;
                    uint32_t bh[2];
                    bh[0] = __float_as_uint(BG[SW(s, kk + lq)]);
                    bh[1] = __float_as_uint(BG[SW(s, kk + 4 + lq)]);
                    mma_tf32(ga[j], ah, bh);
                }
            }
            if (st == lt) {
                // diagonal: per-element L + causal mask (X unscaled)
                int l0 = lr0, l1 = lr0 + 8;
                #pragma unroll
                for (int j = 0; j < 4; j++) {
                    int s0c = wn*32 + j*8 + 2*lq;
                    float cs0 = cumc[st*64 + s0c];
                    float cs1 = cumc[st*64 + s0c + 1];
                    ga[j][0] = (s0c     <= l0) ? ga[j][0] * __expf(cl[t][0] - cs0) : 0.f;
                    ga[j][1] = (s0c + 1 <= l0) ? ga[j][1] * __expf(cl[t][0] - cs1) : 0.f;
                    ga[j][2] = (s0c     <= l1) ? ga[j][2] * __expf(cl[t][1] - cs0) : 0.f;
                    ga[j][3] = (s0c + 1 <= l1) ? ga[j][3] * __expf(cl[t][1] - cs1) : 0.f;
                }
            } else {
                // off-diagonal: fold exp(m - cs) (per column) from ES table
                #pragma unroll
                for (int j = 0; j < 4; j++) {
                    int s0c = wn*32 + j*8 + 2*lq;
                    float e0 = ES[s0c], e1 = ES[s0c + 1];
                    ga[j][0] *= e0; ga[j][1] *= e1;
                    ga[j][2] *= e0; ga[j][3] *= e1;
                }
            }
            float* Gt = GS + t*4096;
            #pragma unroll
            for (int j = 0; j < 4; j++) {
                int col = wn*32 + j*8 + 2*lq;
                Gt[SW(lr0,   col)]     = to_tf32(ga[j][0]);
                Gt[SW(lr0,   col + 1)] = to_tf32(ga[j][1]);
                Gt[SW(lr0+8, col)]     = to_tf32(ga[j][2]);
                Gt[SW(lr0+8, col + 1)] = to_tf32(ga[j][3]);
            }
        }
        __syncthreads();   // all G tiles visible

        // Y accumulation for each live lt
        #pragma unroll
        for (int t = 0; t < 2; t++) {
            int lt = lt0 + t;
            if (st > lt) continue;
            const float* Gt = GS + t*4096;
            if (st == lt) {
                // diagonal: accumulate directly (L fully applied in G)
                #pragma unroll
                for (int kk = 0; kk < 64; kk += 8) {
                    uint32_t ah[4];
                    ah[0] = __float_as_uint(Gt[SW(lr0,   kk + lq)]);
                    ah[1] = __float_as_uint(Gt[SW(lr0+8, kk + lq)]);
                    ah[2] = __float_as_uint(Gt[SW(lr0,   kk + 4 + lq)]);
                    ah[3] = __float_as_uint(Gt[SW(lr0+8, kk + 4 + lq)]);
                    #pragma unroll
                    for (int j = 0; j < 4; j++) {
                        int p = wn*32 + j*8 + lg;
                        uint32_t bh[2];
                        bh[0] = __float_as_uint(XT[(kk+lq)*P72   + p]);
                        bh[1] = __float_as_uint(XT[(kk+4+lq)*P72 + p]);
                        mma_tf32(acc[t][j], ah, bh);
                    }
                }
            } else {
                float ga[4][4];
                #pragma unroll
                for (int j = 0; j < 4; j++)
                    #pragma unroll
                    for (int q = 0; q < 4; q++) ga[j][q] = 0.f;
                #pragma unroll
                for (int kk = 0; kk < 64; kk += 8) {
                    uint32_t ah[4];
                    ah[0] = __float_as_uint(Gt[SW(lr0,   kk + lq)]);
                    ah[1] = __float_as_uint(Gt[SW(lr0+8, kk + lq)]);
                    ah[2] = __float_as_uint(Gt[SW(lr0,   kk + 4 + lq)]);
                    ah[3] = __float_as_uint(Gt[SW(lr0+8, kk + 4 + lq)]);
                    #pragma unroll
                    for (int j = 0; j < 4; j++) {
                        int p = wn*32 + j*8 + lg;
                        uint32_t bh[2];
                        bh[0] = __float_as_uint(XT[(kk+lq)*P72   + p]);
                        bh[1] = __float_as_uint(XT[(kk+4+lq)*P72 + p]);
                        mma_tf32(ga[j], ah, bh);
                    }
                }
                float e0 = __expf(cl[t][0] - m), e1 = __expf(cl[t][1] - m);
                #pragma unroll
                for (int j = 0; j < 4; j++) {
                    acc[t][j][0] = fmaf(e0, ga[j][0], acc[t][j][0]);
                    acc[t][j][1] = fmaf(e0, ga[j][1], acc[t][j][1]);
                    acc[t][j][2] = fmaf(e1, ga[j][2], acc[t][j][2]);
                    acc[t][j][3] = fmaf(e1, ga[j][3], acc[t][j][3]);
                }
            }
        }
    }

    // ---- epilogue: + D_h * x, store both lts
    float Dh = Dvec[h];
    #pragma unroll
    for (int t = 0; t < 2; t++) {
        int gt0 = t0 + (lt0+t)*64 + lr0;
        #pragma unroll
        for (int j = 0; j < 4; j++) {
            int p = wn*32 + j*8 + 2*lq;
            size_t o0 = (size_t)(b*NT + gt0)*ND + h*NP + p;
            size_t o1 = o0 + (size_t)8*ND;
            g_Y[o0]     = acc[t][j][0] + Dh * x[o0];
            g_Y[o0 + 1] = acc[t][j][1] + Dh * x[o0 + 1];
            g_Y[o1]     = acc[t][j][2] + Dh * x[o1];
            g_Y[o1 + 1] = acc[t][j][3] + Dh * x[o1 + 1];
        }
    }
}

// ---------------------------------------------------------------------------
// Output projection, TF32 mma.sync (proven, at HMMA ceiling):
// ---------------------------------------------------------------------------
__global__ __launch_bounds__(256) void out_gemm_tf32(
    const float* __restrict__ W, const float* __restrict__ bias,
    float* __restrict__ out)
{
    __shared__ float As[128][36];
    __shared__ float Ws[128][36];
    const int tid  = threadIdx.x;
    const int wid  = tid >> 5, lane = tid & 31;
    const int warp_m = wid >> 2, warp_n = wid & 3;
    const int m0 = blockIdx.y * 128, n0 = blockIdx.x * 128;
    const int qrow = tid >> 3;
    const int qc4  = (tid & 7) * 4;
    const int lg = lane >> 2, lq = lane & 3;
    const float* A = g_Y;

    float acc[4][4][4];
    #pragma unroll
    for (int i = 0; i < 4; i++)
        #pragma unroll
        for (int j = 0; j < 4; j++)
            #pragma unroll
            for (int q = 0; q < 4; q++) acc[i][j][q] = 0.f;

    float4 pa[4], pw[4];
    #pragma unroll
    for (int it = 0; it < 4; it++) {
        int r = qrow + it * 32;
        pa[it] = *(const float4*)&A[(size_t)(m0 + r) * ND + qc4];
        pw[it] = *(const float4*)&W[(size_t)(n0 + r) * ND + qc4];
    }

    for (int k0 = 0; k0 < ND; k0 += 32) {
        #pragma unroll
        for (int it = 0; it < 4; it++) {
            int r = qrow + it * 32;
            As[r][qc4+0] = to_tf32(pa[it].x); As[r][qc4+1] = to_tf32(pa[it].y);
            As[r][qc4+2] = to_tf32(pa[it].z); As[r][qc4+3] = to_tf32(pa[it].w);
            Ws[r][qc4+0] = to_tf32(pw[it].x); Ws[r][qc4+1] = to_tf32(pw[it].y);
            Ws[r][qc4+2] = to_tf32(pw[it].z); Ws[r][qc4+3] = to_tf32(pw[it].w);
        }
        __syncthreads();

        if (k0 + 32 < ND) {
            #pragma unroll
            for (int it = 0; it < 4; it++) {
                int r = qrow + it * 32;
                pa[it] = *(const float4*)&A[(size_t)(m0 + r) * ND + k0 + 32 + qc4];
                pw[it] = *(const float4*)&W[(size_t)(n0 + r) * ND + k0 + 32 + qc4];
            }
        }

        #pragma unroll
        for (int kk = 0; kk < 32; kk += 8) {
            uint32_t afr[4][4], bfr[4][2];
            #pragma unroll
            for (int i = 0; i < 4; i++) {
                int row = warp_m*64 + i*16 + lg;
                afr[i][0] = __float_as_uint(As[row    ][kk + lq]);
                afr[i][1] = __float_as_uint(As[row + 8][kk + lq]);
                afr[i][2] = __float_as_uint(As[row    ][kk + 4 + lq]);
                afr[i][3] = __float_as_uint(As[row + 8][kk + 4 + lq]);
            }
            #pragma unroll
            for (int j = 0; j < 4; j++) {
                int nrow = warp_n*32 + j*8 + lg;
                bfr[j][0] = __float_as_uint(Ws[nrow][kk + lq]);
                bfr[j][1] = __float_as_uint(Ws[nrow][kk + 4 + lq]);
            }
            #pragma unroll
            for (int i = 0; i < 4; i++)
                #pragma unroll
                for (int j = 0; j < 4; j++)
                    mma_tf32(acc[i][j], afr[i], bfr[j]);
        }
        __syncthreads();
    }

    #pragma unroll
    for (int i = 0; i < 4; i++) {
        int r0 = m0 + warp_m*64 + i*16 + lg;
        #pragma unroll
        for (int j = 0; j < 4; j++) {
            int cc = n0 + warp_n*32 + j*8 + lq*2;
            float b0 = bias[cc], b1 = bias[cc+1];
            out[(size_t)r0       * ND + cc    ] = acc[i][j][0] + b0;
            out[(size_t)r0       * ND + cc + 1] = acc[i][j][1] + b1;
            out[(size_t)(r0 + 8) * ND + cc    ] = acc[i][j][2] + b0;
            out[(size_t)(r0 + 8) * ND + cc + 1] = acc[i][j][3] + b1;
        }
    }
}

// ---------------------------------------------------------------------------
extern "C" void kernel_launch(void* const* d_in, const int* in_sizes, int n_in,
                              void* d_out, int out_size)
{
    const float* x     = (const float*)d_in[0];
    const float* A_log = (const float*)d_in[1];
    const float* Dvec  = (const float*)d_in[2];
    const float* B_w   = (const float*)d_in[3];
    const float* B_b   = (const float*)d_in[4];
    const float* C_w   = (const float*)d_in[5];
    const float* C_b   = (const float*)d_in[6];
    const float* dt_w  = (const float*)d_in[7];
    const float* dt_b  = (const float*)d_in[8];
    const float* out_w = (const float*)d_in[9];
    const float* out_b = (const float*)d_in[10];
    float* out = (float*)d_out;

    cudaFuncSetAttribute(y_kernel_tc, cudaFuncAttributeMaxDynamicSharedMemorySize,
                         Y_SMEM);

    proj_bc64<<<dim3(NTOK/64, 2), 256>>>(x, B_w, B_b, C_w, C_b);
    proj_dt32<<<NTOK/32, 256>>>(x, dt_w, dt_b);
    cumsum_kernel<<<NB*NH*NC, NL>>>(A_log);
    states_tc<<<NB*NC*NH, 256>>>(x);
    scan_kernel<<<NB*NH*16, 256>>>();
    y_kernel_tc<<<NB*NC*NH*2, 256, Y_SMEM>>>(x, Dvec);
    out_gemm_tf32<<<dim3(ND/128, NTOK/128), 256>>>(out_w, out_b, out);
}

// round 12
// speedup vs baseline: 2.7055x; 1.0245x over previous
#include <cuda_runtime.h>
#include <cstdint>
#include <math.h>

#define NB 2
#define NT 4096
#define ND 2048
#define NH 32
#define NN 64
#define NP 64
#define NL 256
#define NC 16
#define NTOK (NB*NT)   // 8192

// swizzled [64][64] accessor (A-frag tiles): 4-group-preserving, conflict-free
#define SW(r,c) (((r)<<6) + ((c) ^ (((r)&15)<<2)))
// pad-72 k-major tiles: conflict-free transposed fragment gathers
#define P72 72

// ---------------- scratch (device globals; no runtime allocation) ----------
__device__ float g_B[(size_t)NTOK*NN];
__device__ float g_C[(size_t)NTOK*NN];
__device__ float g_dt[(size_t)NTOK*NH];
__device__ float g_cum[(size_t)NB*NH*NC*NL];
__device__ float g_states[(size_t)NB*NC*NH*NN*NP];
__device__ float g_prev[(size_t)NB*NC*NH*NN*NP];
__device__ float g_Y[(size_t)NTOK*ND];

__device__ __forceinline__ float softplus_f(float v) {
    return v > 20.f ? v : log1pf(expf(v));
}

__device__ __forceinline__ float to_tf32(float v) {
    uint32_t u;
    asm("cvt.rna.tf32.f32 %0, %1;" : "=r"(u) : "f"(v));
    return __uint_as_float(u);
}

__device__ __forceinline__ float4 tf32x4(float4 v) {
    return make_float4(to_tf32(v.x), to_tf32(v.y), to_tf32(v.z), to_tf32(v.w));
}

__device__ __forceinline__ void mma_tf32(float* d, const uint32_t* a, const uint32_t* b) {
    asm volatile(
        "mma.sync.aligned.m16n8k8.row.col.f32.tf32.tf32.f32 "
        "{%0,%1,%2,%3}, {%4,%5,%6,%7}, {%8,%9}, {%0,%1,%2,%3};"
        : "+f"(d[0]), "+f"(d[1]), "+f"(d[2]), "+f"(d[3])
        : "r"(a[0]), "r"(a[1]), "r"(a[2]), "r"(a[3]),
          "r"(b[0]), "r"(b[1]));
}

__device__ __forceinline__ uint32_t smem_u32(const void* p) {
    uint32_t a;
    asm("{ .reg .u64 t; cvta.to.shared.u64 t, %1; cvt.u32.u64 %0, t; }"
        : "=r"(a) : "l"(p));
    return a;
}

__device__ __forceinline__ void ldsm_x4(uint32_t* r, uint32_t addr) {
    asm volatile("ldmatrix.sync.aligned.m8n8.x4.shared.b16 {%0,%1,%2,%3}, [%4];"
        : "=r"(r[0]), "=r"(r[1]), "=r"(r[2]), "=r"(r[3]) : "r"(addr));
}

// ---------------------------------------------------------------------------
// B/C projection, TF32, BN=64 (256 CTAs -> full wave)
// ---------------------------------------------------------------------------
__global__ __launch_bounds__(256) void proj_bc64(
    const float* __restrict__ x,
    const float* __restrict__ B_w, const float* __restrict__ B_b,
    const float* __restrict__ C_w, const float* __restrict__ C_b)
{
    __shared__ float As[64*36];
    __shared__ float Ws[64*36];
    const int tid = threadIdx.x;
    const int wid = tid >> 5, lane = tid & 31;
    const int wm = wid >> 2, wn = wid & 3;
    const int lg = lane >> 2, lq = lane & 3;
    const int m0 = blockIdx.x * 64;
    const int osel = blockIdx.y;
    const float* W = osel ? C_w : B_w;
    const float* bias = osel ? C_b : B_b;
    float* out = osel ? g_C : g_B;

    float acc[2][2][4];
    #pragma unroll
    for (int i = 0; i < 2; i++)
        #pragma unroll
        for (int j = 0; j < 2; j++)
            #pragma unroll
            for (int q = 0; q < 4; q++) acc[i][j][q] = 0.f;

    for (int k0 = 0; k0 < ND; k0 += 32) {
        int v = tid;
        #pragma unroll
        for (int it = 0; it < 2; it++, v += 256) {
            int row = v >> 3, c4 = (v & 7) * 4;
            float4 av = *(const float4*)&x[(size_t)(m0 + row) * ND + k0 + c4];
            *(float4*)&As[row*36 + c4] = tf32x4(av);
            float4 wv = *(const float4*)&W[(size_t)row * ND + k0 + c4];
            *(float4*)&Ws[row*36 + c4] = tf32x4(wv);
        }
        __syncthreads();
        #pragma unroll
        for (int kk = 0; kk < 32; kk += 8) {
            uint32_t af[2][4], bf[2][2];
            #pragma unroll
            for (int i = 0; i < 2; i++) {
                int r = wm*32 + i*16 + lg;
                af[i][0] = __float_as_uint(As[r*36 + kk + lq]);
                af[i][1] = __float_as_uint(As[(r+8)*36 + kk + lq]);
                af[i][2] = __float_as_uint(As[r*36 + kk + 4 + lq]);
                af[i][3] = __float_as_uint(As[(r+8)*36 + kk + 4 + lq]);
            }
            #pragma unroll
            for (int j = 0; j < 2; j++) {
                int n = wn*16 + j*8 + lg;
                bf[j][0] = __float_as_uint(Ws[n*36 + kk + lq]);
                bf[j][1] = __float_as_uint(Ws[n*36 + kk + 4 + lq]);
            }
            #pragma unroll
            for (int i = 0; i < 2; i++)
                #pragma unroll
                for (int j = 0; j < 2; j++)
                    mma_tf32(acc[i][j], af[i], bf[j]);
        }
        __syncthreads();
    }
    #pragma unroll
    for (int i = 0; i < 2; i++) {
        int r = m0 + wm*32 + i*16 + lg;
        #pragma unroll
        for (int j = 0; j < 2; j++) {
            int n = wn*16 + j*8 + 2*lq;
            float b0 = bias[n], b1 = bias[n+1];
            out[(size_t)r*64 + n]       = acc[i][j][0] + b0;
            out[(size_t)r*64 + n + 1]   = acc[i][j][1] + b1;
            out[(size_t)(r+8)*64 + n]   = acc[i][j][2] + b0;
            out[(size_t)(r+8)*64 + n+1] = acc[i][j][3] + b1;
        }
    }
}

// ---------------------------------------------------------------------------
// dt projection, fp32 scalar, BM=32, 256 CTAs
// ---------------------------------------------------------------------------
__global__ __launch_bounds__(256) void proj_dt32(
    const float* __restrict__ A, const float* __restrict__ W,
    const float* __restrict__ bias)
{
    __shared__ float As[32][36];
    __shared__ float Ws[32][36];
    const int tid = threadIdx.x;
    const int tn = tid & 15, tm = tid >> 4;
    const int m0 = blockIdx.x * 32;
    const int lr = tid >> 3, lk = (tid & 7) * 4;
    float acc[2][2] = {};

    for (int k0 = 0; k0 < ND; k0 += 32) {
        float4 av = *(const float4*)&A[(size_t)(m0 + lr) * ND + k0 + lk];
        float4 wv = *(const float4*)&W[(size_t)lr * ND + k0 + lk];
        As[lk+0][lr] = av.x; As[lk+1][lr] = av.y; As[lk+2][lr] = av.z; As[lk+3][lr] = av.w;
        Ws[lk+0][lr] = wv.x; Ws[lk+1][lr] = wv.y; Ws[lk+2][lr] = wv.z; Ws[lk+3][lr] = wv.w;
        __syncthreads();
        #pragma unroll
        for (int k = 0; k < 32; k++) {
            float a0 = As[k][tm*2], a1 = As[k][tm*2+1];
            float b0 = Ws[k][tn*2], b1 = Ws[k][tn*2+1];
            acc[0][0] = fmaf(a0, b0, acc[0][0]);
            acc[0][1] = fmaf(a0, b1, acc[0][1]);
            acc[1][0] = fmaf(a1, b0, acc[1][0]);
            acc[1][1] = fmaf(a1, b1, acc[1][1]);
        }
        __syncthreads();
    }
    #pragma unroll
    for (int i = 0; i < 2; i++)
        #pragma unroll
        for (int j = 0; j < 2; j++) {
            int m = m0 + tm*2 + i, n = tn*2 + j;
            g_dt[(size_t)m * NH + n] = softplus_f(acc[i][j] + bias[n]);
        }
}

// ---------------------------------------------------------------------------
// Per-(b,h,c) inclusive cumsum of dA = dt * A  over the chunk (L=256)
// ---------------------------------------------------------------------------
__global__ void cumsum_kernel(const float* __restrict__ A_log)
{
    __shared__ float sm[NL];
    int bid = blockIdx.x;
    int c = bid % NC, h = (bid / NC) % NH, b = bid / (NC * NH);
    int s = threadIdx.x;
    float Ah = -expf(A_log[h]);
    int t = c * NL + s;
    sm[s] = g_dt[(size_t)(b*NT + t)*NH + h] * Ah;
    __syncthreads();
    for (int off = 1; off < NL; off <<= 1) {
        float add = (s >= off) ? sm[s - off] : 0.f;
        __syncthreads();
        sm[s] += add;
        __syncthreads();
    }
    g_cum[(size_t)bid * NL + s] = sm[s];
}

// ---------------------------------------------------------------------------
// Chunk states, 1xTF32 mma, pad-72 tiles (proven R10)
// ---------------------------------------------------------------------------
__global__ __launch_bounds__(256) void states_tc(const float* __restrict__ x)
{
    __shared__ float BT[64*P72];
    __shared__ float XS[64*P72];
    int bid = blockIdx.x;
    int h = bid % NH, c = (bid / NH) % NC, b = bid / (NH*NC);
    const int tid = threadIdx.x;
    const int wid = tid >> 5, lane = tid & 31;
    const int wm = wid >> 1, wn = wid & 1;
    const int lg = lane >> 2, lq = lane & 3;
    const float* cumc = &g_cum[(size_t)((b*NH + h)*NC + c) * NL];
    const float cum_last = cumc[NL-1];
    const int lr0 = wm*16 + lg;

    float acc[4][4];
    #pragma unroll
    for (int j = 0; j < 4; j++)
        #pragma unroll
        for (int q = 0; q < 4; q++) acc[j][q] = 0.f;

    for (int s0 = 0; s0 < NL; s0 += 64) {
        if (s0) __syncthreads();
        int v = tid;
        #pragma unroll
        for (int it = 0; it < 4; it++, v += 256) {
            int row = v >> 4, c4 = (v & 15) * 4;
            int gt = c*NL + s0 + row;
            float w = __expf(cum_last - cumc[s0 + row]) *
                      g_dt[(size_t)(b*NT + gt)*NH + h];
            float4 bv = *(const float4*)&g_B[(size_t)(b*NT + gt)*NN + c4];
            float4 xv = *(const float4*)&x[(size_t)(b*NT + gt)*ND + h*NP + c4];
            *(float4*)&BT[row*P72 + c4] =
                make_float4(to_tf32(bv.x*w), to_tf32(bv.y*w),
                            to_tf32(bv.z*w), to_tf32(bv.w*w));
            *(float4*)&XS[row*P72 + c4] = tf32x4(xv);
        }
        __syncthreads();
        #pragma unroll
        for (int kk = 0; kk < 64; kk += 8) {
            uint32_t ah[4];
            ah[0] = __float_as_uint(BT[(kk+lq)*P72   + lr0]);
            ah[1] = __float_as_uint(BT[(kk+lq)*P72   + lr0 + 8]);
            ah[2] = __float_as_uint(BT[(kk+4+lq)*P72 + lr0]);
            ah[3] = __float_as_uint(BT[(kk+4+lq)*P72 + lr0 + 8]);
            #pragma unroll
            for (int j = 0; j < 4; j++) {
                int p = wn*32 + j*8 + lg;
                uint32_t bh[2];
                bh[0] = __float_as_uint(XS[(kk+lq)*P72   + p]);
                bh[1] = __float_as_uint(XS[(kk+4+lq)*P72 + p]);
                mma_tf32(acc[j], ah, bh);
            }
        }
    }
    float* S = &g_states[(((size_t)b*NC + c)*NH + h) * (NN*NP)];
    #pragma unroll
    for (int j = 0; j < 4; j++) {
        int p = wn*32 + j*8 + 2*lq;
        S[(size_t)lr0*NP + p]         = acc[j][0];
        S[(size_t)lr0*NP + p + 1]     = acc[j][1];
        S[(size_t)(lr0+8)*NP + p]     = acc[j][2];
        S[(size_t)(lr0+8)*NP + p + 1] = acc[j][3];
    }
}

// ---------------------------------------------------------------------------
// Inter-chunk scan, element-parallel (proven R10)
// ---------------------------------------------------------------------------
__global__ void scan_kernel()
{
    int bid = blockIdx.x;
    int ec = bid & 15;
    int bh = bid >> 4;
    int h = bh % NH, b = bh / NH;
    int e = ec * 256 + threadIdx.x;
    float R = 0.f;
    #pragma unroll 1
    for (int c = 0; c < NC; c++) {
        size_t off = (((size_t)b*NC + c)*NH + h) * (NN*NP) + e;
        g_prev[off] = R;
        float dec = __expf(g_cum[(size_t)((b*NH + h)*NC + c)*NL + NL - 1]);
        R = fmaf(dec, R, g_states[off]);
    }
}

// ---------------------------------------------------------------------------
// Y kernel, merged l-tile pairs (proven R11)
// ---------------------------------------------------------------------------
#define Y_SMEM ((5*4096 + 64*P72 + 64)*4)
__global__ __launch_bounds__(256) void y_kernel_tc(const float* __restrict__ x,
                                                   const float* __restrict__ Dvec)
{
    extern __shared__ float ysm[];
    float* Cs  = ysm;
    float* BG  = ysm + 8192;
    float* GS  = ysm + 12288;
    float* XT  = ysm + 20480;
    float* ES  = ysm + 20480 + 64*P72;

    int bid = blockIdx.x;
    int pr = bid & 1;
    int h  = (bid >> 1) & 31;
    int c  = (bid >> 6) & 15;
    int b  = bid >> 10;
    const int lt0 = pr*2, lt1 = lt0 + 1;
    const int tid = threadIdx.x;
    const int wid = tid >> 5, lane = tid & 31;
    const int wm = wid >> 1, wn = wid & 1;
    const int lg = lane >> 2, lq = lane & 3;
    const int t0 = c * NL;
    const float* cumc = &g_cum[(size_t)((b*NH + h)*NC + c) * NL];

    {
        const float* S = &g_prev[(((size_t)b*NC + c)*NH + h) * (NN*NP)];
        #pragma unroll
        for (int t = 0; t < 2; t++) {
            int v = tid;
            #pragma unroll
            for (int it = 0; it < 4; it++, v += 256) {
                int row = v >> 4, c4 = (v & 15) * 4;
                float4 cv = *(const float4*)
                    &g_C[(size_t)(b*NT + t0 + (lt0+t)*64 + row)*NN + c4];
                *(float4*)&Cs[t*4096 + SW(row, c4)] = tf32x4(cv);
            }
        }
        int v = tid;
        #pragma unroll
        for (int it = 0; it < 4; it++, v += 256) {
            int row = v >> 4, c4 = (v & 15) * 4;
            float4 sv = *(const float4*)&S[row*64 + c4];
            *(float4*)&XT[row*P72 + c4] = tf32x4(sv);
        }
    }
    __syncthreads();

    const int lr0 = wm*16 + lg;
    float cl[2][2];
    #pragma unroll
    for (int t = 0; t < 2; t++) {
        cl[t][0] = cumc[(lt0+t)*64 + lr0];
        cl[t][1] = cumc[(lt0+t)*64 + lr0 + 8];
    }

    float acc[2][4][4];
    #pragma unroll
    for (int t = 0; t < 2; t++)
        #pragma unroll
        for (int j = 0; j < 4; j++)
            #pragma unroll
            for (int q = 0; q < 4; q++) acc[t][j][q] = 0.f;

    #pragma unroll
    for (int t = 0; t < 2; t++) {
        const float* Ct = Cs + t*4096;
        #pragma unroll
        for (int kk = 0; kk < 64; kk += 8) {
            uint32_t ah[4];
            ah[0] = __float_as_uint(Ct[SW(lr0,   kk + lq)]);
            ah[1] = __float_as_uint(Ct[SW(lr0+8, kk + lq)]);
            ah[2] = __float_as_uint(Ct[SW(lr0,   kk + 4 + lq)]);
            ah[3] = __float_as_uint(Ct[SW(lr0+8, kk + 4 + lq)]);
            #pragma unroll
            for (int j = 0; j < 4; j++) {
                int p = wn*32 + j*8 + lg;
                uint32_t bh[2];
                bh[0] = __float_as_uint(XT[(kk+lq)*P72   + p]);
                bh[1] = __float_as_uint(XT[(kk+4+lq)*P72 + p]);
                mma_tf32(acc[t][j], ah, bh);
            }
        }
        float e0 = __expf(cl[t][0]), e1 = __expf(cl[t][1]);
        #pragma unroll
        for (int j = 0; j < 4; j++) {
            acc[t][j][0] *= e0; acc[t][j][1] *= e0;
            acc[t][j][2] *= e1; acc[t][j][3] *= e1;
        }
    }

    for (int st = 0; st <= lt1; st++) {
        const float m = cumc[st*64 + 63];
        __syncthreads();
        {
            int v = tid;
            #pragma unroll
            for (int it = 0; it < 4; it++, v += 256) {
                int row = v >> 4, c4 = (v & 15) * 4;
                int gt = t0 + st*64 + row;
                float4 bv = *(const float4*)&g_B[(size_t)(b*NT + gt)*NN + c4];
                *(float4*)&BG[SW(row, c4)] = tf32x4(bv);
                float sc = g_dt[(size_t)(b*NT + gt)*NH + h];
                float4 xv = *(const float4*)&x[(size_t)(b*NT + gt)*ND + h*NP + c4];
                *(float4*)&XT[row*P72 + c4] =
                    make_float4(to_tf32(xv.x*sc), to_tf32(xv.y*sc),
                                to_tf32(xv.z*sc), to_tf32(xv.w*sc));
            }
            if (tid < 64) ES[tid] = __expf(m - cumc[st*64 + tid]);
        }
        __syncthreads();

        #pragma unroll
        for (int t = 0; t < 2; t++) {
            int lt = lt0 + t;
            if (st > lt) continue;
            const float* Ct = Cs + t*4096;
            float ga[4][4];
            #pragma unroll
            for (int j = 0; j < 4; j++)
                #pragma unroll
                for (int q = 0; q < 4; q++) ga[j][q] = 0.f;
            #pragma unroll
            for (int kk = 0; kk < 64; kk += 8) {
                uint32_t ah[4];
                ah[0] = __float_as_uint(Ct[SW(lr0,   kk + lq)]);
                ah[1] = __float_as_uint(Ct[SW(lr0+8, kk + lq)]);
                ah[2] = __float_as_uint(Ct[SW(lr0,   kk + 4 + lq)]);
                ah[3] = __float_as_uint(Ct[SW(lr0+8, kk + 4 + lq)]);
                #pragma unroll
                for (int j = 0; j < 4; j++) {
                    int s = wn*32 + j*8 + lg;
                    uint32_t bh[2];
                    bh[0] = __float_as_uint(BG[SW(s, kk + lq)]);
                    bh[1] = __float_as_uint(BG[SW(s, kk + 4 + lq)]);
                    mma_tf32(ga[j], ah, bh);
                }
            }
            if (st == lt) {
                int l0 = lr0, l1 = lr0 + 8;
                #pragma unroll
                for (int j = 0; j < 4; j++) {
                    int s0c = wn*32 + j*8 + 2*lq;
                    float cs0 = cumc[st*64 + s0c];
                    float cs1 = cumc[st*64 + s0c + 1];
                    ga[j][0] = (s0c     <= l0) ? ga[j][0] * __expf(cl[t][0] - cs0) : 0.f;
                    ga[j][1] = (s0c + 1 <= l0) ? ga[j][1] * __expf(cl[t][0] - cs1) : 0.f;
                    ga[j][2] = (s0c     <= l1) ? ga[j][2] * __expf(cl[t][1] - cs0) : 0.f;
                    ga[j][3] = (s0c + 1 <= l1) ? ga[j][3] * __expf(cl[t][1] - cs1) : 0.f;
                }
            } else {
                #pragma unroll
                for (int j = 0; j < 4; j++) {
                    int s0c = wn*32 + j*8 + 2*lq;
                    float e0 = ES[s0c], e1 = ES[s0c + 1];
                    ga[j][0] *= e0; ga[j][1] *= e1;
                    ga[j][2] *= e0; ga[j][3] *= e1;
                }
            }
            float* Gt = GS + t*4096;
            #pragma unroll
            for (int j = 0; j < 4; j++) {
                int col = wn*32 + j*8 + 2*lq;
                Gt[SW(lr0,   col)]     = to_tf32(ga[j][0]);
                Gt[SW(lr0,   col + 1)] = to_tf32(ga[j][1]);
                Gt[SW(lr0+8, col)]     = to_tf32(ga[j][2]);
                Gt[SW(lr0+8, col + 1)] = to_tf32(ga[j][3]);
            }
        }
        __syncthreads();

        #pragma unroll
        for (int t = 0; t < 2; t++) {
            int lt = lt0 + t;
            if (st > lt) continue;
            const float* Gt = GS + t*4096;
            if (st == lt) {
                #pragma unroll
                for (int kk = 0; kk < 64; kk += 8) {
                    uint32_t ah[4];
                    ah[0] = __float_as_uint(Gt[SW(lr0,   kk + lq)]);
                    ah[1] = __float_as_uint(Gt[SW(lr0+8, kk + lq)]);
                    ah[2] = __float_as_uint(Gt[SW(lr0,   kk + 4 + lq)]);
                    ah[3] = __float_as_uint(Gt[SW(lr0+8, kk + 4 + lq)]);
                    #pragma unroll
                    for (int j = 0; j < 4; j++) {
                        int p = wn*32 + j*8 + lg;
                        uint32_t bh[2];
                        bh[0] = __float_as_uint(XT[(kk+lq)*P72   + p]);
                        bh[1] = __float_as_uint(XT[(kk+4+lq)*P72 + p]);
                        mma_tf32(acc[t][j], ah, bh);
                    }
                }
            } else {
                float ga[4][4];
                #pragma unroll
                for (int j = 0; j < 4; j++)
                    #pragma unroll
                    for (int q = 0; q < 4; q++) ga[j][q] = 0.f;
                #pragma unroll
                for (int kk = 0; kk < 64; kk += 8) {
                    uint32_t ah[4];
                    ah[0] = __float_as_uint(Gt[SW(lr0,   kk + lq)]);
                    ah[1] = __float_as_uint(Gt[SW(lr0+8, kk + lq)]);
                    ah[2] = __float_as_uint(Gt[SW(lr0,   kk + 4 + lq)]);
                    ah[3] = __float_as_uint(Gt[SW(lr0+8, kk + 4 + lq)]);
                    #pragma unroll
                    for (int j = 0; j < 4; j++) {
                        int p = wn*32 + j*8 + lg;
                        uint32_t bh[2];
                        bh[0] = __float_as_uint(XT[(kk+lq)*P72   + p]);
                        bh[1] = __float_as_uint(XT[(kk+4+lq)*P72 + p]);
                        mma_tf32(ga[j], ah, bh);
                    }
                }
                float e0 = __expf(cl[t][0] - m), e1 = __expf(cl[t][1] - m);
                #pragma unroll
                for (int j = 0; j < 4; j++) {
                    acc[t][j][0] = fmaf(e0, ga[j][0], acc[t][j][0]);
                    acc[t][j][1] = fmaf(e0, ga[j][1], acc[t][j][1]);
                    acc[t][j][2] = fmaf(e1, ga[j][2], acc[t][j][2]);
                    acc[t][j][3] = fmaf(e1, ga[j][3], acc[t][j][3]);
                }
            }
        }
    }

    float Dh = Dvec[h];
    #pragma unroll
    for (int t = 0; t < 2; t++) {
        int gt0 = t0 + (lt0+t)*64 + lr0;
        #pragma unroll
        for (int j = 0; j < 4; j++) {
            int p = wn*32 + j*8 + 2*lq;
            size_t o0 = (size_t)(b*NT + gt0)*ND + h*NP + p;
            size_t o1 = o0 + (size_t)8*ND;
            g_Y[o0]     = acc[t][j][0] + Dh * x[o0];
            g_Y[o0 + 1] = acc[t][j][1] + Dh * x[o0 + 1];
            g_Y[o1]     = acc[t][j][2] + Dh * x[o1];
            g_Y[o1 + 1] = acc[t][j][3] + Dh * x[o1 + 1];
        }
    }
}

// ---------------------------------------------------------------------------
// Output projection, TF32 mma.sync + ldmatrix fragment loads:
// per kk-step: 4x ldmatrix.x4 (A) + 2x ldmatrix.x4 (B) replace 24 scalar LDS.
// stride-36 rows: the 8 quadrant rows map to banks 4r..4r+3 -> conflict-free.
// ---------------------------------------------------------------------------
__global__ __launch_bounds__(256) void out_gemm_tf32(
    const float* __restrict__ W, const float* __restrict__ bias,
    float* __restrict__ out)
{
    __shared__ float As[128][36];
    __shared__ float Ws[128][36];
    const int tid  = threadIdx.x;
    const int wid  = tid >> 5, lane = tid & 31;
    const int warp_m = wid >> 2, warp_n = wid & 3;   // 2 x 4
    const int m0 = blockIdx.y * 128, n0 = blockIdx.x * 128;
    const int qrow = tid >> 3;
    const int qc4  = (tid & 7) * 4;
    const int lg = lane >> 2, lq = lane & 3;
    const float* A = g_Y;

    // ldmatrix per-lane base addresses
    // A: m0=rows(base..+7,col kk) m1=(rows+8,kk) m2=(rows,kk+4) m3=(rows+8,kk+4)
    const int lrow8 = lane & 7;
    const int aRow = warp_m*64 + ((lane >> 3) & 1)*8 + lrow8;
    const int aCol = ((lane >> 4) & 1)*4;
    const uint32_t baseA = smem_u32(As) + (uint32_t)(aRow*36 + aCol)*4u;
    // B: m0=(rows nj, kk) m1=(rows nj, kk+4) m2=(rows nj+8, kk) m3=(rows nj+8, kk+4)
    const int bRow = warp_n*32 + ((lane >> 4) & 1)*8 + lrow8;
    const int bCol = ((lane >> 3) & 1)*4;
    const uint32_t baseB = smem_u32(Ws) + (uint32_t)(bRow*36 + bCol)*4u;

    float acc[4][4][4];
    #pragma unroll
    for (int i = 0; i < 4; i++)
        #pragma unroll
        for (int j = 0; j < 4; j++)
            #pragma unroll
            for (int q = 0; q < 4; q++) acc[i][j][q] = 0.f;

    float4 pa[4], pw[4];
    #pragma unroll
    for (int it = 0; it < 4; it++) {
        int r = qrow + it * 32;
        pa[it] = *(const float4*)&A[(size_t)(m0 + r) * ND + qc4];
        pw[it] = *(const float4*)&W[(size_t)(n0 + r) * ND + qc4];
    }

    for (int k0 = 0; k0 < ND; k0 += 32) {
        #pragma unroll
        for (int it = 0; it < 4; it++) {
            int r = qrow + it * 32;
            As[r][qc4+0] = to_tf32(pa[it].x); As[r][qc4+1] = to_tf32(pa[it].y);
            As[r][qc4+2] = to_tf32(pa[it].z); As[r][qc4+3] = to_tf32(pa[it].w);
            Ws[r][qc4+0] = to_tf32(pw[it].x); Ws[r][qc4+1] = to_tf32(pw[it].y);
            Ws[r][qc4+2] = to_tf32(pw[it].z); Ws[r][qc4+3] = to_tf32(pw[it].w);
        }
        __syncthreads();

        if (k0 + 32 < ND) {
            #pragma unroll
            for (int it = 0; it < 4; it++) {
                int r = qrow + it * 32;
                pa[it] = *(const float4*)&A[(size_t)(m0 + r) * ND + k0 + 32 + qc4];
                pw[it] = *(const float4*)&W[(size_t)(n0 + r) * ND + k0 + 32 + qc4];
            }
        }

        #pragma unroll
        for (int kk = 0; kk < 32; kk += 8) {
            uint32_t afr[4][4], bfr[4][2];
            #pragma unroll
            for (int i = 0; i < 4; i++)
                ldsm_x4(afr[i], baseA + (uint32_t)(i*16*36 + kk)*4u);
            #pragma unroll
            for (int jp = 0; jp < 2; jp++) {
                uint32_t bt[4];
                ldsm_x4(bt, baseB + (uint32_t)(jp*16*36 + kk)*4u);
                bfr[2*jp][0]   = bt[0]; bfr[2*jp][1]   = bt[1];
                bfr[2*jp+1][0] = bt[2]; bfr[2*jp+1][1] = bt[3];
            }
            #pragma unroll
            for (int i = 0; i < 4; i++)
                #pragma unroll
                for (int j = 0; j < 4; j++)
                    mma_tf32(acc[i][j], afr[i], bfr[j]);
        }
        __syncthreads();
    }

    #pragma unroll
    for (int i = 0; i < 4; i++) {
        int r0 = m0 + warp_m*64 + i*16 + lg;
        #pragma unroll
        for (int j = 0; j < 4; j++) {
            int cc = n0 + warp_n*32 + j*8 + lq*2;
            float b0 = bias[cc], b1 = bias[cc+1];
            out[(size_t)r0       * ND + cc    ] = acc[i][j][0] + b0;
            out[(size_t)r0       * ND + cc + 1] = acc[i][j][1] + b1;
            out[(size_t)(r0 + 8) * ND + cc    ] = acc[i][j][2] + b0;
            out[(size_t)(r0 + 8) * ND + cc + 1] = acc[i][j][3] + b1;
        }
    }
}

// ---------------------------------------------------------------------------
extern "C" void kernel_launch(void* const* d_in, const int* in_sizes, int n_in,
                              void* d_out, int out_size)
{
    const float* x     = (const float*)d_in[0];
    const float* A_log = (const float*)d_in[1];
    const float* Dvec  = (const float*)d_in[2];
    const float* B_w   = (const float*)d_in[3];
    const float* B_b   = (const float*)d_in[4];
    const float* C_w   = (const float*)d_in[5];
    const float* C_b   = (const float*)d_in[6];
    const float* dt_w  = (const float*)d_in[7];
    const float* dt_b  = (const float*)d_in[8];
    const float* out_w = (const float*)d_in[9];
    const float* out_b = (const float*)d_in[10];
    float* out = (float*)d_out;

    cudaFuncSetAttribute(y_kernel_tc, cudaFuncAttributeMaxDynamicSharedMemorySize,
                         Y_SMEM);

    proj_bc64<<<dim3(NTOK/64, 2), 256>>>(x, B_w, B_b, C_w, C_b);
    proj_dt32<<<NTOK/32, 256>>>(x, dt_w, dt_b);
    cumsum_kernel<<<NB*NH*NC, NL>>>(A_log);
    states_tc<<<NB*NC*NH, 256>>>(x);
    scan_kernel<<<NB*NH*16, 256>>>();
    y_kernel_tc<<<NB*NC*NH*2, 256, Y_SMEM>>>(x, Dvec);
    out_gemm_tf32<<<dim3(ND/128, NTOK/128), 256>>>(out_w, out_b, out);
}

// round 14
// speedup vs baseline: 3.0904x; 1.1423x over previous
#include <cuda_runtime.h>
#include <cstdint>
#include <math.h>

#define NB 2
#define NT 4096
#define ND 2048
#define NH 32
#define NN 64
#define NP 64
#define NL 256
#define NC 16
#define NTOK (NB*NT)   // 8192

// swizzled [64][64] accessor (A-frag tiles): 4-group-preserving, conflict-free
#define SW(r,c) (((r)<<6) + ((c) ^ (((r)&15)<<2)))
// pad-72 k-major tiles: conflict-free transposed fragment gathers
#define P72 72

// ---------------- scratch (device globals; no runtime allocation) ----------
__device__ float g_B[(size_t)NTOK*NN];
__device__ float g_C[(size_t)NTOK*NN];
__device__ float g_dt[(size_t)NTOK*NH];
__device__ float g_cum[(size_t)NB*NH*NC*NL];
__device__ float g_states[(size_t)NB*NC*NH*NN*NP];
__device__ float g_prev[(size_t)NB*NC*NH*NN*NP];
__device__ float g_Y[(size_t)NTOK*ND];

__device__ __forceinline__ float softplus_f(float v) {
    return v > 20.f ? v : log1pf(expf(v));
}

__device__ __forceinline__ float to_tf32(float v) {
    uint32_t u;
    asm("cvt.rna.tf32.f32 %0, %1;" : "=r"(u) : "f"(v));
    return __uint_as_float(u);
}

__device__ __forceinline__ float4 tf32x4(float4 v) {
    return make_float4(to_tf32(v.x), to_tf32(v.y), to_tf32(v.z), to_tf32(v.w));
}

__device__ __forceinline__ void mma_tf32(float* d, const uint32_t* a, const uint32_t* b) {
    asm volatile(
        "mma.sync.aligned.m16n8k8.row.col.f32.tf32.tf32.f32 "
        "{%0,%1,%2,%3}, {%4,%5,%6,%7}, {%8,%9}, {%0,%1,%2,%3};"
        : "+f"(d[0]), "+f"(d[1]), "+f"(d[2]), "+f"(d[3])
        : "r"(a[0]), "r"(a[1]), "r"(a[2]), "r"(a[3]),
          "r"(b[0]), "r"(b[1]));
}

__device__ __forceinline__ uint32_t smem_u32(const void* p) {
    uint32_t a;
    asm("{ .reg .u64 t; cvta.to.shared.u64 t, %1; cvt.u32.u64 %0, t; }"
        : "=r"(a) : "l"(p));
    return a;
}

__device__ __forceinline__ void ldsm_x4(uint32_t* r, uint32_t addr) {
    asm volatile("ldmatrix.sync.aligned.m8n8.x4.shared.b16 {%0,%1,%2,%3}, [%4];"
        : "=r"(r[0]), "=r"(r[1]), "=r"(r[2]), "=r"(r[3]) : "r"(addr));
}

// ---------------------------------------------------------------------------
// Fused projections, one launch: grid (128, 3)
//   y=0: g_B = x @ B_w^T + B_b   (tf32 mma, BM=64, BN=64)
//   y=1: g_C = x @ C_w^T + C_b
//   y=2: g_dt = softplus(x @ dt_w^T + dt_b)  (fp32 scalar, BM=64, N=32)
// ---------------------------------------------------------------------------
__global__ __launch_bounds__(256) void proj_fused(
    const float* __restrict__ x,
    const float* __restrict__ B_w, const float* __restrict__ B_b,
    const float* __restrict__ C_w, const float* __restrict__ C_b,
    const float* __restrict__ dt_w, const float* __restrict__ dt_b)
{
    __shared__ float sm[4608];
    const int tid = threadIdx.x;
    const int m0 = blockIdx.x * 64;

    if (blockIdx.y < 2) {
        float* As = sm;               // 64 x 36
        float* Ws = sm + 2304;        // 64 x 36
        const int wid = tid >> 5, lane = tid & 31;
        const int wm = wid >> 2, wn = wid & 3;
        const int lg = lane >> 2, lq = lane & 3;
        const int osel = blockIdx.y;
        const float* W = osel ? C_w : B_w;
        const float* bias = osel ? C_b : B_b;
        float* out = osel ? g_C : g_B;

        float acc[2][2][4];
        #pragma unroll
        for (int i = 0; i < 2; i++)
            #pragma unroll
            for (int j = 0; j < 2; j++)
                #pragma unroll
                for (int q = 0; q < 4; q++) acc[i][j][q] = 0.f;

        for (int k0 = 0; k0 < ND; k0 += 32) {
            int v = tid;
            #pragma unroll
            for (int it = 0; it < 2; it++, v += 256) {
                int row = v >> 3, c4 = (v & 7) * 4;
                float4 av = *(const float4*)&x[(size_t)(m0 + row) * ND + k0 + c4];
                *(float4*)&As[row*36 + c4] = tf32x4(av);
                float4 wv = *(const float4*)&W[(size_t)row * ND + k0 + c4];
                *(float4*)&Ws[row*36 + c4] = tf32x4(wv);
            }
            __syncthreads();
            #pragma unroll
            for (int kk = 0; kk < 32; kk += 8) {
                uint32_t af[2][4], bf[2][2];
                #pragma unroll
                for (int i = 0; i < 2; i++) {
                    int r = wm*32 + i*16 + lg;
                    af[i][0] = __float_as_uint(As[r*36 + kk + lq]);
                    af[i][1] = __float_as_uint(As[(r+8)*36 + kk + lq]);
                    af[i][2] = __float_as_uint(As[r*36 + kk + 4 + lq]);
                    af[i][3] = __float_as_uint(As[(r+8)*36 + kk + 4 + lq]);
                }
                #pragma unroll
                for (int j = 0; j < 2; j++) {
                    int n = wn*16 + j*8 + lg;
                    bf[j][0] = __float_as_uint(Ws[n*36 + kk + lq]);
                    bf[j][1] = __float_as_uint(Ws[n*36 + kk + 4 + lq]);
                }
                #pragma unroll
                for (int i = 0; i < 2; i++)
                    #pragma unroll
                    for (int j = 0; j < 2; j++)
                        mma_tf32(acc[i][j], af[i], bf[j]);
            }
            __syncthreads();
        }
        #pragma unroll
        for (int i = 0; i < 2; i++) {
            int r = m0 + wm*32 + i*16 + lg;
            #pragma unroll
            for (int j = 0; j < 2; j++) {
                int n = wn*16 + j*8 + 2*lq;
                float b0 = bias[n], b1 = bias[n+1];
                out[(size_t)r*64 + n]       = acc[i][j][0] + b0;
                out[(size_t)r*64 + n + 1]   = acc[i][j][1] + b1;
                out[(size_t)(r+8)*64 + n]   = acc[i][j][2] + b0;
                out[(size_t)(r+8)*64 + n+1] = acc[i][j][3] + b1;
            }
        }
    } else {
        // dt path: BM=64, N=32, fp32 scalar (transposed smem [k][m])
        float* Asd = sm;              // 32 x 68
        float* Wsd = sm + 2176;       // 32 x 68
        const int tn = tid & 15, tm = tid >> 4;
        float acc[4][2] = {};

        for (int k0 = 0; k0 < ND; k0 += 32) {
            int v = tid;
            #pragma unroll
            for (int it = 0; it < 2; it++, v += 256) {
                int row = v >> 3, c4 = (v & 7) * 4;
                float4 av = *(const float4*)&x[(size_t)(m0 + row) * ND + k0 + c4];
                Asd[(c4+0)*68 + row] = av.x;
                Asd[(c4+1)*68 + row] = av.y;
                Asd[(c4+2)*68 + row] = av.z;
                Asd[(c4+3)*68 + row] = av.w;
            }
            {
                int row = tid >> 3, c4 = (tid & 7) * 4;  // 32 rows exactly
                float4 wv = *(const float4*)&dt_w[(size_t)row * ND + k0 + c4];
                Wsd[(c4+0)*68 + row] = wv.x;
                Wsd[(c4+1)*68 + row] = wv.y;
                Wsd[(c4+2)*68 + row] = wv.z;
                Wsd[(c4+3)*68 + row] = wv.w;
            }
            __syncthreads();
            #pragma unroll
            for (int k = 0; k < 32; k++) {
                float a[4], b[2];
                #pragma unroll
                for (int i = 0; i < 4; i++) a[i] = Asd[k*68 + tm*4 + i];
                b[0] = Wsd[k*68 + tn*2];
                b[1] = Wsd[k*68 + tn*2 + 1];
                #pragma unroll
                for (int i = 0; i < 4; i++) {
                    acc[i][0] = fmaf(a[i], b[0], acc[i][0]);
                    acc[i][1] = fmaf(a[i], b[1], acc[i][1]);
                }
            }
            __syncthreads();
        }
        #pragma unroll
        for (int i = 0; i < 4; i++)
            #pragma unroll
            for (int j = 0; j < 2; j++) {
                int m = m0 + tm*4 + i, n = tn*2 + j;
                g_dt[(size_t)m * NH + n] = softplus_f(acc[i][j] + dt_b[n]);
            }
    }
}

// ---------------------------------------------------------------------------
// Per-(b,h,c) inclusive cumsum of dA = dt * A  over the chunk (L=256)
// ---------------------------------------------------------------------------
__global__ void cumsum_kernel(const float* __restrict__ A_log)
{
    __shared__ float sm[NL];
    int bid = blockIdx.x;
    int c = bid % NC, h = (bid / NC) % NH, b = bid / (NC * NH);
    int s = threadIdx.x;
    float Ah = -expf(A_log[h]);
    int t = c * NL + s;
    sm[s] = g_dt[(size_t)(b*NT + t)*NH + h] * Ah;
    __syncthreads();
    for (int off = 1; off < NL; off <<= 1) {
        float add = (s >= off) ? sm[s - off] : 0.f;
        __syncthreads();
        sm[s] += add;
        __syncthreads();
    }
    g_cum[(size_t)bid * NL + s] = sm[s];
}

// ---------------------------------------------------------------------------
// Chunk states, 1xTF32 mma, pad-72 tiles (proven R10)
// ---------------------------------------------------------------------------
__global__ __launch_bounds__(256) void states_tc(const float* __restrict__ x)
{
    __shared__ float BT[64*P72];
    __shared__ float XS[64*P72];
    int bid = blockIdx.x;
    int h = bid % NH, c = (bid / NH) % NC, b = bid / (NH*NC);
    const int tid = threadIdx.x;
    const int wid = tid >> 5, lane = tid & 31;
    const int wm = wid >> 1, wn = wid & 1;
    const int lg = lane >> 2, lq = lane & 3;
    const float* cumc = &g_cum[(size_t)((b*NH + h)*NC + c) * NL];
    const float cum_last = cumc[NL-1];
    const int lr0 = wm*16 + lg;

    float acc[4][4];
    #pragma unroll
    for (int j = 0; j < 4; j++)
        #pragma unroll
        for (int q = 0; q < 4; q++) acc[j][q] = 0.f;

    for (int s0 = 0; s0 < NL; s0 += 64) {
        if (s0) __syncthreads();
        int v = tid;
        #pragma unroll
        for (int it = 0; it < 4; it++, v += 256) {
            int row = v >> 4, c4 = (v & 15) * 4;
            int gt = c*NL + s0 + row;
            float w = __expf(cum_last - cumc[s0 + row]) *
                      g_dt[(size_t)(b*NT + gt)*NH + h];
            float4 bv = *(const float4*)&g_B[(size_t)(b*NT + gt)*NN + c4];
            float4 xv = *(const float4*)&x[(size_t)(b*NT + gt)*ND + h*NP + c4];
            *(float4*)&BT[row*P72 + c4] =
                make_float4(to_tf32(bv.x*w), to_tf32(bv.y*w),
                            to_tf32(bv.z*w), to_tf32(bv.w*w));
            *(float4*)&XS[row*P72 + c4] = tf32x4(xv);
        }
        __syncthreads();
        #pragma unroll
        for (int kk = 0; kk < 64; kk += 8) {
            uint32_t ah[4];
            ah[0] = __float_as_uint(BT[(kk+lq)*P72   + lr0]);
            ah[1] = __float_as_uint(BT[(kk+lq)*P72   + lr0 + 8]);
            ah[2] = __float_as_uint(BT[(kk+4+lq)*P72 + lr0]);
            ah[3] = __float_as_uint(BT[(kk+4+lq)*P72 + lr0 + 8]);
            #pragma unroll
            for (int j = 0; j < 4; j++) {
                int p = wn*32 + j*8 + lg;
                uint32_t bh[2];
                bh[0] = __float_as_uint(XS[(kk+lq)*P72   + p]);
                bh[1] = __float_as_uint(XS[(kk+4+lq)*P72 + p]);
                mma_tf32(acc[j], ah, bh);
            }
        }
    }
    float* S = &g_states[(((size_t)b*NC + c)*NH + h) * (NN*NP)];
    #pragma unroll
    for (int j = 0; j < 4; j++) {
        int p = wn*32 + j*8 + 2*lq;
        S[(size_t)lr0*NP + p]         = acc[j][0];
        S[(size_t)lr0*NP + p + 1]     = acc[j][1];
        S[(size_t)(lr0+8)*NP + p]     = acc[j][2];
        S[(size_t)(lr0+8)*NP + p + 1] = acc[j][3];
    }
}

// ---------------------------------------------------------------------------
// Inter-chunk scan, element-parallel (proven R10)
// ---------------------------------------------------------------------------
__global__ void scan_kernel()
{
    int bid = blockIdx.x;
    int ec = bid & 15;
    int bh = bid >> 4;
    int h = bh % NH, b = bh / NH;
    int e = ec * 256 + threadIdx.x;
    float R = 0.f;
    #pragma unroll 1
    for (int c = 0; c < NC; c++) {
        size_t off = (((size_t)b*NC + c)*NH + h) * (NN*NP) + e;
        g_prev[off] = R;
        float dec = __expf(g_cum[(size_t)((b*NH + h)*NC + c)*NL + NL - 1]);
        R = fmaf(dec, R, g_states[off]);
    }
}

// ---------------------------------------------------------------------------
// Y kernel, merged l-tile pairs + ldmatrix fragment loads for swizzled tiles
// (Cs/GS A-frags, BG B-frags). XT (k-major) B-frags stay scalar.
// ---------------------------------------------------------------------------
#define Y_SMEM ((5*4096 + 64*P72 + 64)*4)
__global__ __launch_bounds__(256) void y_kernel_tc(const float* __restrict__ x,
                                                   const float* __restrict__ Dvec)
{
    extern __shared__ float ysm[];
    float* Cs  = ysm;
    float* BG  = ysm + 8192;
    float* GS  = ysm + 12288;
    float* XT  = ysm + 20480;
    float* ES  = ysm + 20480 + 64*P72;

    int bid = blockIdx.x;
    int pr = bid & 1;
    int h  = (bid >> 1) & 31;
    int c  = (bid >> 6) & 15;
    int b  = bid >> 10;
    const int lt0 = pr*2, lt1 = lt0 + 1;
    const int tid = threadIdx.x;
    const int wid = tid >> 5, lane = tid & 31;
    const int wm = wid >> 1, wn = wid & 1;
    const int lg = lane >> 2, lq = lane & 3;
    const int t0 = c * NL;
    const float* cumc = &g_cum[(size_t)((b*NH + h)*NC + c) * NL];

    // ---- per-lane ldmatrix address precompute
    const int lrow8 = lane & 7;
    // A role (16-row tiles at row wm*16)
    const int aR  = wm*16 + ((lane >> 3) & 1)*8 + lrow8;
    const uint32_t aXor = (uint32_t)((aR & 15) << 2);
    const uint32_t aCb  = (uint32_t)(((lane >> 4) & 1) * 4);
    const uint32_t csA0 = smem_u32(Cs) + (uint32_t)aR*256u;           // + t*16384
    const uint32_t gsA0 = smem_u32(GS) + (uint32_t)aR*256u;
    // B role on BG (rows wn*32 .. +31, j-pairs of 16)
    const int bmid = lane >> 3;                          // matrix id 0..3
    const int bR   = wn*32 + ((bmid >> 1) & 1)*8 + lrow8;
    const uint32_t bXor = (uint32_t)((bR & 15) << 2);
    const uint32_t bCb  = (uint32_t)((bmid & 1) * 4);
    const uint32_t bgB0 = smem_u32(BG) + (uint32_t)bR*256u;           // jp: +16*256

    {
        const float* S = &g_prev[(((size_t)b*NC + c)*NH + h) * (NN*NP)];
        #pragma unroll
        for (int t = 0; t < 2; t++) {
            int v = tid;
            #pragma unroll
            for (int it = 0; it < 4; it++, v += 256) {
                int row = v >> 4, c4 = (v & 15) * 4;
                float4 cv = *(const float4*)
                    &g_C[(size_t)(b*NT + t0 + (lt0+t)*64 + row)*NN + c4];
                *(float4*)&Cs[t*4096 + SW(row, c4)] = tf32x4(cv);
            }
        }
        int v = tid;
        #pragma unroll
        for (int it = 0; it < 4; it++, v += 256) {
            int row = v >> 4, c4 = (v & 15) * 4;
            float4 sv = *(const float4*)&S[row*64 + c4];
            *(float4*)&XT[row*P72 + c4] = tf32x4(sv);
        }
    }
    __syncthreads();

    const int lr0 = wm*16 + lg;
    float cl[2][2];
    #pragma unroll
    for (int t = 0; t < 2; t++) {
        cl[t][0] = cumc[(lt0+t)*64 + lr0];
        cl[t][1] = cumc[(lt0+t)*64 + lr0 + 8];
    }

    float acc[2][4][4];
    #pragma unroll
    for (int t = 0; t < 2; t++)
        #pragma unroll
        for (int j = 0; j < 4; j++)
            #pragma unroll
            for (int q = 0; q < 4; q++) acc[t][j][q] = 0.f;

    // ---- Y_off = C @ S_prev (A via ldsm from Cs; B scalar from XT)
    #pragma unroll
    for (int t = 0; t < 2; t++) {
        const uint32_t ctA = csA0 + (uint32_t)t*16384u;
        #pragma unroll
        for (int kk = 0; kk < 64; kk += 8) {
            uint32_t ah[4];
            ldsm_x4(ah, ctA + ((((uint32_t)kk | aCb) ^ aXor) << 2));
            #pragma unroll
            for (int j = 0; j < 4; j++) {
                int p = wn*32 + j*8 + lg;
                uint32_t bh[2];
                bh[0] = __float_as_uint(XT[(kk+lq)*P72   + p]);
                bh[1] = __float_as_uint(XT[(kk+4+lq)*P72 + p]);
                mma_tf32(acc[t][j], ah, bh);
            }
        }
        float e0 = __expf(cl[t][0]), e1 = __expf(cl[t][1]);
        #pragma unroll
        for (int j = 0; j < 4; j++) {
            acc[t][j][0] *= e0; acc[t][j][1] *= e0;
            acc[t][j][2] *= e1; acc[t][j][3] *= e1;
        }
    }

    for (int st = 0; st <= lt1; st++) {
        const float m = cumc[st*64 + 63];
        __syncthreads();
        {
            int v = tid;
            #pragma unroll
            for (int it = 0; it < 4; it++, v += 256) {
                int row = v >> 4, c4 = (v & 15) * 4;
                int gt = t0 + st*64 + row;
                float4 bv = *(const float4*)&g_B[(size_t)(b*NT + gt)*NN + c4];
                *(float4*)&BG[SW(row, c4)] = tf32x4(bv);
                float sc = g_dt[(size_t)(b*NT + gt)*NH + h];
                float4 xv = *(const float4*)&x[(size_t)(b*NT + gt)*ND + h*NP + c4];
                *(float4*)&XT[row*P72 + c4] =
                    make_float4(to_tf32(xv.x*sc), to_tf32(xv.y*sc),
                                to_tf32(xv.z*sc), to_tf32(xv.w*sc));
            }
            if (tid < 64) ES[tid] = __expf(m - cumc[st*64 + tid]);
        }
        __syncthreads();

        #pragma unroll
        for (int t = 0; t < 2; t++) {
            int lt = lt0 + t;
            if (st > lt) continue;
            const uint32_t ctA = csA0 + (uint32_t)t*16384u;
            float ga[4][4];
            #pragma unroll
            for (int j = 0; j < 4; j++)
                #pragma unroll
                for (int q = 0; q < 4; q++) ga[j][q] = 0.f;
            #pragma unroll
            for (int kk = 0; kk < 64; kk += 8) {
                uint32_t ah[4];
                ldsm_x4(ah, ctA + ((((uint32_t)kk | aCb) ^ aXor) << 2));
                uint32_t bfr[4][2];
                #pragma unroll
                for (int jp = 0; jp < 2; jp++) {
                    uint32_t bt[4];
                    ldsm_x4(bt, bgB0 + (uint32_t)jp*4096u
                                + ((((uint32_t)kk | bCb) ^ bXor) << 2));
                    bfr[2*jp][0]   = bt[0]; bfr[2*jp][1]   = bt[1];
                    bfr[2*jp+1][0] = bt[2]; bfr[2*jp+1][1] = bt[3];
                }
                #pragma unroll
                for (int j = 0; j < 4; j++)
                    mma_tf32(ga[j], ah, bfr[j]);
            }
            if (st == lt) {
                int l0 = lr0, l1 = lr0 + 8;
                #pragma unroll
                for (int j = 0; j < 4; j++) {
                    int s0c = wn*32 + j*8 + 2*lq;
                    float cs0 = cumc[st*64 + s0c];
                    float cs1 = cumc[st*64 + s0c + 1];
                    ga[j][0] = (s0c     <= l0) ? ga[j][0] * __expf(cl[t][0] - cs0) : 0.f;
                    ga[j][1] = (s0c + 1 <= l0) ? ga[j][1] * __expf(cl[t][0] - cs1) : 0.f;
                    ga[j][2] = (s0c     <= l1) ? ga[j][2] * __expf(cl[t][1] - cs0) : 0.f;
                    ga[j][3] = (s0c + 1 <= l1) ? ga[j][3] * __expf(cl[t][1] - cs1) : 0.f;
                }
            } else {
                #pragma unroll
                for (int j = 0; j < 4; j++) {
                    int s0c = wn*32 + j*8 + 2*lq;
                    float e0 = ES[s0c], e1 = ES[s0c + 1];
                    ga[j][0] *= e0; ga[j][1] *= e1;
                    ga[j][2] *= e0; ga[j][3] *= e1;
                }
            }
            float* Gt = GS + t*4096;
            #pragma unroll
            for (int j = 0; j < 4; j++) {
                int col = wn*32 + j*8 + 2*lq;
                Gt[SW(lr0,   col)]     = to_tf32(ga[j][0]);
                Gt[SW(lr0,   col + 1)] = to_tf32(ga[j][1]);
                Gt[SW(lr0+8, col)]     = to_tf32(ga[j][2]);
                Gt[SW(lr0+8, col + 1)] = to_tf32(ga[j][3]);
            }
        }
        __syncthreads();

        #pragma unroll
        for (int t = 0; t < 2; t++) {
            int lt = lt0 + t;
            if (st > lt) continue;
            const uint32_t gtA = gsA0 + (uint32_t)t*16384u;
            if (st == lt) {
                #pragma unroll
                for (int kk = 0; kk < 64; kk += 8) {
                    uint32_t ah[4];
                    ldsm_x4(ah, gtA + ((((uint32_t)kk | aCb) ^ aXor) << 2));
                    #pragma unroll
                    for (int j = 0; j < 4; j++) {
                        int p = wn*32 + j*8 + lg;
                        uint32_t bh[2];
                        bh[0] = __float_as_uint(XT[(kk+lq)*P72   + p]);
                        bh[1] = __float_as_uint(XT[(kk+4+lq)*P72 + p]);
                        mma_tf32(acc[t][j], ah, bh);
                    }
                }
            } else {
                float ga[4][4];
                #pragma unroll
                for (int j = 0; j < 4; j++)
                    #pragma unroll
                    for (int q = 0; q < 4; q++) ga[j][q] = 0.f;
                #pragma unroll
                for (int kk = 0; kk < 64; kk += 8) {
                    uint32_t ah[4];
                    ldsm_x4(ah, gtA + ((((uint32_t)kk | aCb) ^ aXor) << 2));
                    #pragma unroll
                    for (int j = 0; j < 4; j++) {
                        int p = wn*32 + j*8 + lg;
                        uint32_t bh[2];
                        bh[0] = __float_as_uint(XT[(kk+lq)*P72   + p]);
                        bh[1] = __float_as_uint(XT[(kk+4+lq)*P72 + p]);
                        mma_tf32(ga[j], ah, bh);
                    }
                }
                float e0 = __expf(cl[t][0] - m), e1 = __expf(cl[t][1] - m);
                #pragma unroll
                for (int j = 0; j < 4; j++) {
                    acc[t][j][0] = fmaf(e0, ga[j][0], acc[t][j][0]);
                    acc[t][j][1] = fmaf(e0, ga[j][1], acc[t][j][1]);
                    acc[t][j][2] = fmaf(e1, ga[j][2], acc[t][j][2]);
                    acc[t][j][3] = fmaf(e1, ga[j][3], acc[t][j][3]);
                }
            }
        }
    }

    float Dh = Dvec[h];
    #pragma unroll
    for (int t = 0; t < 2; t++) {
        int gt0 = t0 + (lt0+t)*64 + lr0;
        #pragma unroll
        for (int j = 0; j < 4; j++) {
            int p = wn*32 + j*8 + 2*lq;
            size_t o0 = (size_t)(b*NT + gt0)*ND + h*NP + p;
            size_t o1 = o0 + (size_t)8*ND;
            g_Y[o0]     = acc[t][j][0] + Dh * x[o0];
            g_Y[o0 + 1] = acc[t][j][1] + Dh * x[o0 + 1];
            g_Y[o1]     = acc[t][j][2] + Dh * x[o1];
            g_Y[o1 + 1] = acc[t][j][3] + Dh * x[o1 + 1];
        }
    }
}

// ---------------------------------------------------------------------------
// Output projection, TF32 mma.sync + ldmatrix (proven R12, at HMMA ceiling)
// ---------------------------------------------------------------------------
__global__ __launch_bounds__(256) void out_gemm_tf32(
    const float* __restrict__ W, const float* __restrict__ bias,
    float* __restrict__ out)
{
    __shared__ float As[128][36];
    __shared__ float Ws[128][36];
    const int tid  = threadIdx.x;
    const int wid  = tid >> 5, lane = tid & 31;
    const int warp_m = wid >> 2, warp_n = wid & 3;
    const int m0 = blockIdx.y * 128, n0 = blockIdx.x * 128;
    const int qrow = tid >> 3;
    const int qc4  = (tid & 7) * 4;
    const int lg = lane >> 2, lq = lane & 3;
    const float* A = g_Y;

    const int lrow8 = lane & 7;
    const int aRow = warp_m*64 + ((lane >> 3) & 1)*8 + lrow8;
    const int aCol = ((lane >> 4) & 1)*4;
    const uint32_t baseA = smem_u32(As) + (uint32_t)(aRow*36 + aCol)*4u;
    const int bRow = warp_n*32 + ((lane >> 4) & 1)*8 + lrow8;
    const int bCol = ((lane >> 3) & 1)*4;
    const uint32_t baseB = smem_u32(Ws) + (uint32_t)(bRow*36 + bCol)*4u;

    float acc[4][4][4];
    #pragma unroll
    for (int i = 0; i < 4; i++)
        #pragma unroll
        for (int j = 0; j < 4; j++)
            #pragma unroll
            for (int q = 0; q < 4; q++) acc[i][j][q] = 0.f;

    float4 pa[4], pw[4];
    #pragma unroll
    for (int it = 0; it < 4; it++) {
        int r = qrow + it * 32;
        pa[it] = *(const float4*)&A[(size_t)(m0 + r) * ND + qc4];
        pw[it] = *(const float4*)&W[(size_t)(n0 + r) * ND + qc4];
    }

    for (int k0 = 0; k0 < ND; k0 += 32) {
        #pragma unroll
        for (int it = 0; it < 4; it++) {
            int r = qrow + it * 32;
            As[r][qc4+0] = to_tf32(pa[it].x); As[r][qc4+1] = to_tf32(pa[it].y);
            As[r][qc4+2] = to_tf32(pa[it].z); As[r][qc4+3] = to_tf32(pa[it].w);
            Ws[r][qc4+0] = to_tf32(pw[it].x); Ws[r][qc4+1] = to_tf32(pw[it].y);
            Ws[r][qc4+2] = to_tf32(pw[it].z); Ws[r][qc4+3] = to_tf32(pw[it].w);
        }
        __syncthreads();

        if (k0 + 32 < ND) {
            #pragma unroll
            for (int it = 0; it < 4; it++) {
                int r = qrow + it * 32;
                pa[it] = *(const float4*)&A[(size_t)(m0 + r) * ND + k0 + 32 + qc4];
                pw[it] = *(const float4*)&W[(size_t)(n0 + r) * ND + k0 + 32 + qc4];
            }
        }

        #pragma unroll
        for (int kk = 0; kk < 32; kk += 8) {
            uint32_t afr[4][4], bfr[4][2];
            #pragma unroll
            for (int i = 0; i < 4; i++)
                ldsm_x4(afr[i], baseA + (uint32_t)(i*16*36 + kk)*4u);
            #pragma unroll
            for (int jp = 0; jp < 2; jp++) {
                uint32_t bt[4];
                ldsm_x4(bt, baseB + (uint32_t)(jp*16*36 + kk)*4u);
                bfr[2*jp][0]   = bt[0]; bfr[2*jp][1]   = bt[1];
                bfr[2*jp+1][0] = bt[2]; bfr[2*jp+1][1] = bt[3];
            }
            #pragma unroll
            for (int i = 0; i < 4; i++)
                #pragma unroll
                for (int j = 0; j < 4; j++)
                    mma_tf32(acc[i][j], afr[i], bfr[j]);
        }
        __syncthreads();
    }

    #pragma unroll
    for (int i = 0; i < 4; i++) {
        int r0 = m0 + warp_m*64 + i*16 + lg;
        #pragma unroll
        for (int j = 0; j < 4; j++) {
            int cc = n0 + warp_n*32 + j*8 + lq*2;
            float b0 = bias[cc], b1 = bias[cc+1];
            out[(size_t)r0       * ND + cc    ] = acc[i][j][0] + b0;
            out[(size_t)r0       * ND + cc + 1] = acc[i][j][1] + b1;
            out[(size_t)(r0 + 8) * ND + cc    ] = acc[i][j][2] + b0;
            out[(size_t)(r0 + 8) * ND + cc + 1] = acc[i][j][3] + b1;
        }
    }
}

// ---------------------------------------------------------------------------
extern "C" void kernel_launch(void* const* d_in, const int* in_sizes, int n_in,
                              void* d_out, int out_size)
{
    const float* x     = (const float*)d_in[0];
    const float* A_log = (const float*)d_in[1];
    const float* Dvec  = (const float*)d_in[2];
    const float* B_w   = (const float*)d_in[3];
    const float* B_b   = (const float*)d_in[4];
    const float* C_w   = (const float*)d_in[5];
    const float* C_b   = (const float*)d_in[6];
    const float* dt_w  = (const float*)d_in[7];
    const float* dt_b  = (const float*)d_in[8];
    const float* out_w = (const float*)d_in[9];
    const float* out_b = (const float*)d_in[10];
    float* out = (float*)d_out;

    cudaFuncSetAttribute(y_kernel_tc, cudaFuncAttributeMaxDynamicSharedMemorySize,
                         Y_SMEM);

    proj_fused<<<dim3(NTOK/64, 3), 256>>>(x, B_w, B_b, C_w, C_b, dt_w, dt_b);
    cumsum_kernel<<<NB*NH*NC, NL>>>(A_log);
    states_tc<<<NB*NC*NH, 256>>>(x);
    scan_kernel<<<NB*NH*16, 256>>>();
    y_kernel_tc<<<NB*NC*NH*2, 256, Y_SMEM>>>(x, Dvec);
    out_gemm_tf32<<<dim3(ND/128, NTOK/128), 256>>>(out_w, out_b, out);
}

// round 16
// speedup vs baseline: 3.8101x; 1.2329x over previous
#include <cuda_runtime.h>
#include <cuda_fp16.h>
#include <cstdint>
#include <math.h>

#define NB 2
#define NT 4096
#define ND 2048
#define NH 32
#define NN 64
#define NP 64
#define NL 256
#define NC 16
#define NTOK (NB*NT)   // 8192

// swizzled [64][64] accessor (A-frag tiles): 4-group-preserving, conflict-free
#define SW(r,c) (((r)<<6) + ((c) ^ (((r)&15)<<2)))
// pad-72 k-major tiles: conflict-free transposed fragment gathers
#define P72 72

// ---------------- scratch (device globals; no runtime allocation) ----------
__device__ float g_B[(size_t)NTOK*NN];
__device__ float g_C[(size_t)NTOK*NN];
__device__ float g_dt[(size_t)NTOK*NH];
__device__ float g_cum[(size_t)NB*NH*NC*NL];
__device__ float g_states[(size_t)NB*NC*NH*NN*NP];
__device__ float g_prev[(size_t)NB*NC*NH*NN*NP];
__device__ float g_Y[(size_t)NTOK*ND];

__device__ __forceinline__ float softplus_f(float v) {
    return v > 20.f ? v : log1pf(expf(v));
}

__device__ __forceinline__ float to_tf32(float v) {
    uint32_t u;
    asm("cvt.rna.tf32.f32 %0, %1;" : "=r"(u) : "f"(v));
    return __uint_as_float(u);
}

__device__ __forceinline__ float4 tf32x4(float4 v) {
    return make_float4(to_tf32(v.x), to_tf32(v.y), to_tf32(v.z), to_tf32(v.w));
}

__device__ __forceinline__ void mma_tf32(float* d, const uint32_t* a, const uint32_t* b) {
    asm volatile(
        "mma.sync.aligned.m16n8k8.row.col.f32.tf32.tf32.f32 "
        "{%0,%1,%2,%3}, {%4,%5,%6,%7}, {%8,%9}, {%0,%1,%2,%3};"
        : "+f"(d[0]), "+f"(d[1]), "+f"(d[2]), "+f"(d[3])
        : "r"(a[0]), "r"(a[1]), "r"(a[2]), "r"(a[3]),
          "r"(b[0]), "r"(b[1]));
}

__device__ __forceinline__ void mma_f16(float* d, const uint32_t* a, const uint32_t* b) {
    asm volatile(
        "mma.sync.aligned.m16n8k16.row.col.f32.f16.f16.f32 "
        "{%0,%1,%2,%3}, {%4,%5,%6,%7}, {%8,%9}, {%0,%1,%2,%3};"
        : "+f"(d[0]), "+f"(d[1]), "+f"(d[2]), "+f"(d[3])
        : "r"(a[0]), "r"(a[1]), "r"(a[2]), "r"(a[3]),
          "r"(b[0]), "r"(b[1]));
}

__device__ __forceinline__ uint32_t smem_u32(const void* p) {
    uint32_t a;
    asm("{ .reg .u64 t; cvta.to.shared.u64 t, %1; cvt.u32.u64 %0, t; }"
        : "=r"(a) : "l"(p));
    return a;
}

__device__ __forceinline__ void ldsm_x4(uint32_t* r, uint32_t addr) {
    asm volatile("ldmatrix.sync.aligned.m8n8.x4.shared.b16 {%0,%1,%2,%3}, [%4];"
        : "=r"(r[0]), "=r"(r[1]), "=r"(r[2]), "=r"(r[3]) : "r"(addr));
}

// ---------------------------------------------------------------------------
// Fused projections, one launch: grid (128, 3)  (proven R13)
// ---------------------------------------------------------------------------
__global__ __launch_bounds__(256) void proj_fused(
    const float* __restrict__ x,
    const float* __restrict__ B_w, const float* __restrict__ B_b,
    const float* __restrict__ C_w, const float* __restrict__ C_b,
    const float* __restrict__ dt_w, const float* __restrict__ dt_b)
{
    __shared__ float sm[4608];
    const int tid = threadIdx.x;
    const int m0 = blockIdx.x * 64;

    if (blockIdx.y < 2) {
        float* As = sm;
        float* Ws = sm + 2304;
        const int wid = tid >> 5, lane = tid & 31;
        const int wm = wid >> 2, wn = wid & 3;
        const int lg = lane >> 2, lq = lane & 3;
        const int osel = blockIdx.y;
        const float* W = osel ? C_w : B_w;
        const float* bias = osel ? C_b : B_b;
        float* out = osel ? g_C : g_B;

        float acc[2][2][4];
        #pragma unroll
        for (int i = 0; i < 2; i++)
            #pragma unroll
            for (int j = 0; j < 2; j++)
                #pragma unroll
                for (int q = 0; q < 4; q++) acc[i][j][q] = 0.f;

        for (int k0 = 0; k0 < ND; k0 += 32) {
            int v = tid;
            #pragma unroll
            for (int it = 0; it < 2; it++, v += 256) {
                int row = v >> 3, c4 = (v & 7) * 4;
                float4 av = *(const float4*)&x[(size_t)(m0 + row) * ND + k0 + c4];
                *(float4*)&As[row*36 + c4] = tf32x4(av);
                float4 wv = *(const float4*)&W[(size_t)row * ND + k0 + c4];
                *(float4*)&Ws[row*36 + c4] = tf32x4(wv);
            }
            __syncthreads();
            #pragma unroll
            for (int kk = 0; kk < 32; kk += 8) {
                uint32_t af[2][4], bf[2][2];
                #pragma unroll
                for (int i = 0; i < 2; i++) {
                    int r = wm*32 + i*16 + lg;
                    af[i][0] = __float_as_uint(As[r*36 + kk + lq]);
                    af[i][1] = __float_as_uint(As[(r+8)*36 + kk + lq]);
                    af[i][2] = __float_as_uint(As[r*36 + kk + 4 + lq]);
                    af[i][3] = __float_as_uint(As[(r+8)*36 + kk + 4 + lq]);
                }
                #pragma unroll
                for (int j = 0; j < 2; j++) {
                    int n = wn*16 + j*8 + lg;
                    bf[j][0] = __float_as_uint(Ws[n*36 + kk + lq]);
                    bf[j][1] = __float_as_uint(Ws[n*36 + kk + 4 + lq]);
                }
                #pragma unroll
                for (int i = 0; i < 2; i++)
                    #pragma unroll
                    for (int j = 0; j < 2; j++)
                        mma_tf32(acc[i][j], af[i], bf[j]);
            }
            __syncthreads();
        }
        #pragma unroll
        for (int i = 0; i < 2; i++) {
            int r = m0 + wm*32 + i*16 + lg;
            #pragma unroll
            for (int j = 0; j < 2; j++) {
                int n = wn*16 + j*8 + 2*lq;
                float b0 = bias[n], b1 = bias[n+1];
                out[(size_t)r*64 + n]       = acc[i][j][0] + b0;
                out[(size_t)r*64 + n + 1]   = acc[i][j][1] + b1;
                out[(size_t)(r+8)*64 + n]   = acc[i][j][2] + b0;
                out[(size_t)(r+8)*64 + n+1] = acc[i][j][3] + b1;
            }
        }
    } else {
        float* Asd = sm;
        float* Wsd = sm + 2176;
        const int tn = tid & 15, tm = tid >> 4;
        float acc[4][2] = {};

        for (int k0 = 0; k0 < ND; k0 += 32) {
            int v = tid;
            #pragma unroll
            for (int it = 0; it < 2; it++, v += 256) {
                int row = v >> 3, c4 = (v & 7) * 4;
                float4 av = *(const float4*)&x[(size_t)(m0 + row) * ND + k0 + c4];
                Asd[(c4+0)*68 + row] = av.x;
                Asd[(c4+1)*68 + row] = av.y;
                Asd[(c4+2)*68 + row] = av.z;
                Asd[(c4+3)*68 + row] = av.w;
            }
            {
                int row = tid >> 3, c4 = (tid & 7) * 4;
                float4 wv = *(const float4*)&dt_w[(size_t)row * ND + k0 + c4];
                Wsd[(c4+0)*68 + row] = wv.x;
                Wsd[(c4+1)*68 + row] = wv.y;
                Wsd[(c4+2)*68 + row] = wv.z;
                Wsd[(c4+3)*68 + row] = wv.w;
            }
            __syncthreads();
            #pragma unroll
            for (int k = 0; k < 32; k++) {
                float a[4], b[2];
                #pragma unroll
                for (int i = 0; i < 4; i++) a[i] = Asd[k*68 + tm*4 + i];
                b[0] = Wsd[k*68 + tn*2];
                b[1] = Wsd[k*68 + tn*2 + 1];
                #pragma unroll
                for (int i = 0; i < 4; i++) {
                    acc[i][0] = fmaf(a[i], b[0], acc[i][0]);
                    acc[i][1] = fmaf(a[i], b[1], acc[i][1]);
                }
            }
            __syncthreads();
        }
        #pragma unroll
        for (int i = 0; i < 4; i++)
            #pragma unroll
            for (int j = 0; j < 2; j++) {
                int m = m0 + tm*4 + i, n = tn*2 + j;
                g_dt[(size_t)m * NH + n] = softplus_f(acc[i][j] + dt_b[n]);
            }
    }
}

// ---------------------------------------------------------------------------
// Per-(b,h,c) inclusive cumsum of dA = dt * A  over the chunk (L=256)
// ---------------------------------------------------------------------------
__global__ void cumsum_kernel(const float* __restrict__ A_log)
{
    __shared__ float sm[NL];
    int bid = blockIdx.x;
    int c = bid % NC, h = (bid / NC) % NH, b = bid / (NC * NH);
    int s = threadIdx.x;
    float Ah = -expf(A_log[h]);
    int t = c * NL + s;
    sm[s] = g_dt[(size_t)(b*NT + t)*NH + h] * Ah;
    __syncthreads();
    for (int off = 1; off < NL; off <<= 1) {
        float add = (s >= off) ? sm[s - off] : 0.f;
        __syncthreads();
        sm[s] += add;
        __syncthreads();
    }
    g_cum[(size_t)bid * NL + s] = sm[s];
}

// ---------------------------------------------------------------------------
// Chunk states, 1xTF32 mma, pad-72 tiles (proven R10)
// ---------------------------------------------------------------------------
__global__ __launch_bounds__(256) void states_tc(const float* __restrict__ x)
{
    __shared__ float BT[64*P72];
    __shared__ float XS[64*P72];
    int bid = blockIdx.x;
    int h = bid % NH, c = (bid / NH) % NC, b = bid / (NH*NC);
    const int tid = threadIdx.x;
    const int wid = tid >> 5, lane = tid & 31;
    const int wm = wid >> 1, wn = wid & 1;
    const int lg = lane >> 2, lq = lane & 3;
    const float* cumc = &g_cum[(size_t)((b*NH + h)*NC + c) * NL];
    const float cum_last = cumc[NL-1];
    const int lr0 = wm*16 + lg;

    float acc[4][4];
    #pragma unroll
    for (int j = 0; j < 4; j++)
        #pragma unroll
        for (int q = 0; q < 4; q++) acc[j][q] = 0.f;

    for (int s0 = 0; s0 < NL; s0 += 64) {
        if (s0) __syncthreads();
        int v = tid;
        #pragma unroll
        for (int it = 0; it < 4; it++, v += 256) {
            int row = v >> 4, c4 = (v & 15) * 4;
            int gt = c*NL + s0 + row;
            float w = __expf(cum_last - cumc[s0 + row]) *
                      g_dt[(size_t)(b*NT + gt)*NH + h];
            float4 bv = *(const float4*)&g_B[(size_t)(b*NT + gt)*NN + c4];
            float4 xv = *(const float4*)&x[(size_t)(b*NT + gt)*ND + h*NP + c4];
            *(float4*)&BT[row*P72 + c4] =
                make_float4(to_tf32(bv.x*w), to_tf32(bv.y*w),
                            to_tf32(bv.z*w), to_tf32(bv.w*w));
            *(float4*)&XS[row*P72 + c4] = tf32x4(xv);
        }
        __syncthreads();
        #pragma unroll
        for (int kk = 0; kk < 64; kk += 8) {
            uint32_t ah[4];
            ah[0] = __float_as_uint(BT[(kk+lq)*P72   + lr0]);
            ah[1] = __float_as_uint(BT[(kk+lq)*P72   + lr0 + 8]);
            ah[2] = __float_as_uint(BT[(kk+4+lq)*P72 + lr0]);
            ah[3] = __float_as_uint(BT[(kk+4+lq)*P72 + lr0 + 8]);
            #pragma unroll
            for (int j = 0; j < 4; j++) {
                int p = wn*32 + j*8 + lg;
                uint32_t bh[2];
                bh[0] = __float_as_uint(XS[(kk+lq)*P72   + p]);
                bh[1] = __float_as_uint(XS[(kk+4+lq)*P72 + p]);
                mma_tf32(acc[j], ah, bh);
            }
        }
    }
    float* S = &g_states[(((size_t)b*NC + c)*NH + h) * (NN*NP)];
    #pragma unroll
    for (int j = 0; j < 4; j++) {
        int p = wn*32 + j*8 + 2*lq;
        S[(size_t)lr0*NP + p]         = acc[j][0];
        S[(size_t)lr0*NP + p + 1]     = acc[j][1];
        S[(size_t)(lr0+8)*NP + p]     = acc[j][2];
        S[(size_t)(lr0+8)*NP + p + 1] = acc[j][3];
    }
}

// ---------------------------------------------------------------------------
// Inter-chunk scan, element-parallel (proven R10)
// ---------------------------------------------------------------------------
__global__ void scan_kernel()
{
    int bid = blockIdx.x;
    int ec = bid & 15;
    int bh = bid >> 4;
    int h = bh % NH, b = bh / NH;
    int e = ec * 256 + threadIdx.x;
    float R = 0.f;
    #pragma unroll 1
    for (int c = 0; c < NC; c++) {
        size_t off = (((size_t)b*NC + c)*NH + h) * (NN*NP) + e;
        g_prev[off] = R;
        float dec = __expf(g_cum[(size_t)((b*NH + h)*NC + c)*NL + NL - 1]);
        R = fmaf(dec, R, g_states[off]);
    }
}

// ---------------------------------------------------------------------------
// Y kernel, merged l-tile pairs + ldmatrix (proven R13)
// ---------------------------------------------------------------------------
#define Y_SMEM ((5*4096 + 64*P72 + 64)*4)
__global__ __launch_bounds__(256) void y_kernel_tc(const float* __restrict__ x,
                                                   const float* __restrict__ Dvec)
{
    extern __shared__ float ysm[];
    float* Cs  = ysm;
    float* BG  = ysm + 8192;
    float* GS  = ysm + 12288;
    float* XT  = ysm + 20480;
    float* ES  = ysm + 20480 + 64*P72;

    int bid = blockIdx.x;
    int pr = bid & 1;
    int h  = (bid >> 1) & 31;
    int c  = (bid >> 6) & 15;
    int b  = bid >> 10;
    const int lt0 = pr*2, lt1 = lt0 + 1;
    const int tid = threadIdx.x;
    const int wid = tid >> 5, lane = tid & 31;
    const int wm = wid >> 1, wn = wid & 1;
    const int lg = lane >> 2, lq = lane & 3;
    const int t0 = c * NL;
    const float* cumc = &g_cum[(size_t)((b*NH + h)*NC + c) * NL];

    const int lrow8 = lane & 7;
    const int aR  = wm*16 + ((lane >> 3) & 1)*8 + lrow8;
    const uint32_t aXor = (uint32_t)((aR & 15) << 2);
    const uint32_t aCb  = (uint32_t)(((lane >> 4) & 1) * 4);
    const uint32_t csA0 = smem_u32(Cs) + (uint32_t)aR*256u;
    const uint32_t gsA0 = smem_u32(GS) + (uint32_t)aR*256u;
    const int bmid = lane >> 3;
    const int bR   = wn*32 + ((bmid >> 1) & 1)*8 + lrow8;
    const uint32_t bXor = (uint32_t)((bR & 15) << 2);
    const uint32_t bCb  = (uint32_t)((bmid & 1) * 4);
    const uint32_t bgB0 = smem_u32(BG) + (uint32_t)bR*256u;

    {
        const float* S = &g_prev[(((size_t)b*NC + c)*NH + h) * (NN*NP)];
        #pragma unroll
        for (int t = 0; t < 2; t++) {
            int v = tid;
            #pragma unroll
            for (int it = 0; it < 4; it++, v += 256) {
                int row = v >> 4, c4 = (v & 15) * 4;
                float4 cv = *(const float4*)
                    &g_C[(size_t)(b*NT + t0 + (lt0+t)*64 + row)*NN + c4];
                *(float4*)&Cs[t*4096 + SW(row, c4)] = tf32x4(cv);
            }
        }
        int v = tid;
        #pragma unroll
        for (int it = 0; it < 4; it++, v += 256) {
            int row = v >> 4, c4 = (v & 15) * 4;
            float4 sv = *(const float4*)&S[row*64 + c4];
            *(float4*)&XT[row*P72 + c4] = tf32x4(sv);
        }
    }
    __syncthreads();

    const int lr0 = wm*16 + lg;
    float cl[2][2];
    #pragma unroll
    for (int t = 0; t < 2; t++) {
        cl[t][0] = cumc[(lt0+t)*64 + lr0];
        cl[t][1] = cumc[(lt0+t)*64 + lr0 + 8];
    }

    float acc[2][4][4];
    #pragma unroll
    for (int t = 0; t < 2; t++)
        #pragma unroll
        for (int j = 0; j < 4; j++)
            #pragma unroll
            for (int q = 0; q < 4; q++) acc[t][j][q] = 0.f;

    #pragma unroll
    for (int t = 0; t < 2; t++) {
        const uint32_t ctA = csA0 + (uint32_t)t*16384u;
        #pragma unroll
        for (int kk = 0; kk < 64; kk += 8) {
            uint32_t ah[4];
            ldsm_x4(ah, ctA + ((((uint32_t)kk | aCb) ^ aXor) << 2));
            #pragma unroll
            for (int j = 0; j < 4; j++) {
                int p = wn*32 + j*8 + lg;
                uint32_t bh[2];
                bh[0] = __float_as_uint(XT[(kk+lq)*P72   + p]);
                bh[1] = __float_as_uint(XT[(kk+4+lq)*P72 + p]);
                mma_tf32(acc[t][j], ah, bh);
            }
        }
        float e0 = __expf(cl[t][0]), e1 = __expf(cl[t][1]);
        #pragma unroll
        for (int j = 0; j < 4; j++) {
            acc[t][j][0] *= e0; acc[t][j][1] *= e0;
            acc[t][j][2] *= e1; acc[t][j][3] *= e1;
        }
    }

    for (int st = 0; st <= lt1; st++) {
        const float m = cumc[st*64 + 63];
        __syncthreads();
        {
            int v = tid;
            #pragma unroll
            for (int it = 0; it < 4; it++, v += 256) {
                int row = v >> 4, c4 = (v & 15) * 4;
                int gt = t0 + st*64 + row;
                float4 bv = *(const float4*)&g_B[(size_t)(b*NT + gt)*NN + c4];
                *(float4*)&BG[SW(row, c4)] = tf32x4(bv);
                float sc = g_dt[(size_t)(b*NT + gt)*NH + h];
                float4 xv = *(const float4*)&x[(size_t)(b*NT + gt)*ND + h*NP + c4];
                *(float4*)&XT[row*P72 + c4] =
                    make_float4(to_tf32(xv.x*sc), to_tf32(xv.y*sc),
                                to_tf32(xv.z*sc), to_tf32(xv.w*sc));
            }
            if (tid < 64) ES[tid] = __expf(m - cumc[st*64 + tid]);
        }
        __syncthreads();

        #pragma unroll
        for (int t = 0; t < 2; t++) {
            int lt = lt0 + t;
            if (st > lt) continue;
            const uint32_t ctA = csA0 + (uint32_t)t*16384u;
            float ga[4][4];
            #pragma unroll
            for (int j = 0; j < 4; j++)
                #pragma unroll
                for (int q = 0; q < 4; q++) ga[j][q] = 0.f;
            #pragma unroll
            for (int kk = 0; kk < 64; kk += 8) {
                uint32_t ah[4];
                ldsm_x4(ah, ctA + ((((uint32_t)kk | aCb) ^ aXor) << 2));
                uint32_t bfr[4][2];
                #pragma unroll
                for (int jp = 0; jp < 2; jp++) {
                    uint32_t bt[4];
                    ldsm_x4(bt, bgB0 + (uint32_t)jp*4096u
                                + ((((uint32_t)kk | bCb) ^ bXor) << 2));
                    bfr[2*jp][0]   = bt[0]; bfr[2*jp][1]   = bt[1];
                    bfr[2*jp+1][0] = bt[2]; bfr[2*jp+1][1] = bt[3];
                }
                #pragma unroll
                for (int j = 0; j < 4; j++)
                    mma_tf32(ga[j], ah, bfr[j]);
            }
            if (st == lt) {
                int l0 = lr0, l1 = lr0 + 8;
                #pragma unroll
                for (int j = 0; j < 4; j++) {
                    int s0c = wn*32 + j*8 + 2*lq;
                    float cs0 = cumc[st*64 + s0c];
                    float cs1 = cumc[st*64 + s0c + 1];
                    ga[j][0] = (s0c     <= l0) ? ga[j][0] * __expf(cl[t][0] - cs0) : 0.f;
                    ga[j][1] = (s0c + 1 <= l0) ? ga[j][1] * __expf(cl[t][0] - cs1) : 0.f;
                    ga[j][2] = (s0c     <= l1) ? ga[j][2] * __expf(cl[t][1] - cs0) : 0.f;
                    ga[j][3] = (s0c + 1 <= l1) ? ga[j][3] * __expf(cl[t][1] - cs1) : 0.f;
                }
            } else {
                #pragma unroll
                for (int j = 0; j < 4; j++) {
                    int s0c = wn*32 + j*8 + 2*lq;
                    float e0 = ES[s0c], e1 = ES[s0c + 1];
                    ga[j][0] *= e0; ga[j][1] *= e1;
                    ga[j][2] *= e0; ga[j][3] *= e1;
                }
            }
            float* Gt = GS + t*4096;
            #pragma unroll
            for (int j = 0; j < 4; j++) {
                int col = wn*32 + j*8 + 2*lq;
                Gt[SW(lr0,   col)]     = to_tf32(ga[j][0]);
                Gt[SW(lr0,   col + 1)] = to_tf32(ga[j][1]);
                Gt[SW(lr0+8, col)]     = to_tf32(ga[j][2]);
                Gt[SW(lr0+8, col + 1)] = to_tf32(ga[j][3]);
            }
        }
        __syncthreads();

        #pragma unroll
        for (int t = 0; t < 2; t++) {
            int lt = lt0 + t;
            if (st > lt) continue;
            const uint32_t gtA = gsA0 + (uint32_t)t*16384u;
            if (st == lt) {
                #pragma unroll
                for (int kk = 0; kk < 64; kk += 8) {
                    uint32_t ah[4];
                    ldsm_x4(ah, gtA + ((((uint32_t)kk | aCb) ^ aXor) << 2));
                    #pragma unroll
                    for (int j = 0; j < 4; j++) {
                        int p = wn*32 + j*8 + lg;
                        uint32_t bh[2];
                        bh[0] = __float_as_uint(XT[(kk+lq)*P72   + p]);
                        bh[1] = __float_as_uint(XT[(kk+4+lq)*P72 + p]);
                        mma_tf32(acc[t][j], ah, bh);
                    }
                }
            } else {
                float ga[4][4];
                #pragma unroll
                for (int j = 0; j < 4; j++)
                    #pragma unroll
                    for (int q = 0; q < 4; q++) ga[j][q] = 0.f;
                #pragma unroll
                for (int kk = 0; kk < 64; kk += 8) {
                    uint32_t ah[4];
                    ldsm_x4(ah, gtA + ((((uint32_t)kk | aCb) ^ aXor) << 2));
                    #pragma unroll
                    for (int j = 0; j < 4; j++) {
                        int p = wn*32 + j*8 + lg;
                        uint32_t bh[2];
                        bh[0] = __float_as_uint(XT[(kk+lq)*P72   + p]);
                        bh[1] = __float_as_uint(XT[(kk+4+lq)*P72 + p]);
                        mma_tf32(ga[j], ah, bh);
                    }
                }
                float e0 = __expf(cl[t][0] - m), e1 = __expf(cl[t][1] - m);
                #pragma unroll
                for (int j = 0; j < 4; j++) {
                    acc[t][j][0] = fmaf(e0, ga[j][0], acc[t][j][0]);
                    acc[t][j][1] = fmaf(e0, ga[j][1], acc[t][j][1]);
                    acc[t][j][2] = fmaf(e1, ga[j][2], acc[t][j][2]);
                    acc[t][j][3] = fmaf(e1, ga[j][3], acc[t][j][3]);
                }
            }
        }
    }

    float Dh = Dvec[h];
    #pragma unroll
    for (int t = 0; t < 2; t++) {
        int gt0 = t0 + (lt0+t)*64 + lr0;
        #pragma unroll
        for (int j = 0; j < 4; j++) {
            int p = wn*32 + j*8 + 2*lq;
            size_t o0 = (size_t)(b*NT + gt0)*ND + h*NP + p;
            size_t o1 = o0 + (size_t)8*ND;
            g_Y[o0]     = acc[t][j][0] + Dh * x[o0];
            g_Y[o0 + 1] = acc[t][j][1] + Dh * x[o0 + 1];
            g_Y[o1]     = acc[t][j][2] + Dh * x[o1];
            g_Y[o1 + 1] = acc[t][j][3] + Dh * x[o1 + 1];
        }
    }
}

// ---------------------------------------------------------------------------
// Output projection, FP16 m16n8k16 mma (fp16 mantissa == tf32 mantissa; fp32
// accumulate). smem half[128][40]: pad-40 rows -> ldmatrix conflict-free.
// Per 32-slab: 2 k16 steps, mma count halved vs tf32.
// ---------------------------------------------------------------------------
__global__ __launch_bounds__(256) void out_gemm_f16(
    const float* __restrict__ W, const float* __restrict__ bias,
    float* __restrict__ out)
{
    __shared__ __half As[128][40];
    __shared__ __half Ws[128][40];
    const int tid  = threadIdx.x;
    const int wid  = tid >> 5, lane = tid & 31;
    const int warp_m = wid >> 2, warp_n = wid & 3;   // 2 x 4
    const int m0 = blockIdx.y * 128, n0 = blockIdx.x * 128;
    const int qrow = tid >> 3;
    const int qc4  = (tid & 7) * 4;
    const int lg = lane >> 2, lq = lane & 3;
    const float* A = g_Y;

    // ldmatrix addresses (b16 elements, row stride 40)
    const int lrow8 = lane & 7;
    // A 16x16 tile: m0=rows0-7 k0-7, m1=rows8-15 k0-7, m2=rows0-7 k8-15, m3=rows8-15 k8-15
    const int aRow = warp_m*64 + ((lane >> 3) & 1)*8 + lrow8;
    const int aColH = ((lane >> 4) & 1)*8;
    const uint32_t baseA = smem_u32(As) + (uint32_t)(aRow*40 + aColH)*2u;
    // B j-pair: m0=rows nj0-7 k0-7, m1=same rows k8-15, m2=rows+8 k0-7, m3=rows+8 k8-15
    const int bmid = lane >> 3;
    const int bRow = warp_n*32 + ((bmid >> 1) & 1)*8 + lrow8;
    const int bColH = (bmid & 1)*8;
    const uint32_t baseB = smem_u32(Ws) + (uint32_t)(bRow*40 + bColH)*2u;

    float acc[4][4][4];
    #pragma unroll
    for (int i = 0; i < 4; i++)
        #pragma unroll
        for (int j = 0; j < 4; j++)
            #pragma unroll
            for (int q = 0; q < 4; q++) acc[i][j][q] = 0.f;

    float4 pa[4], pw[4];
    #pragma unroll
    for (int it = 0; it < 4; it++) {
        int r = qrow + it * 32;
        pa[it] = *(const float4*)&A[(size_t)(m0 + r) * ND + qc4];
        pw[it] = *(const float4*)&W[(size_t)(n0 + r) * ND + qc4];
    }

    for (int k0 = 0; k0 < ND; k0 += 32) {
        #pragma unroll
        for (int it = 0; it < 4; it++) {
            int r = qrow + it * 32;
            *(__half2*)&As[r][qc4]     = __floats2half2_rn(pa[it].x, pa[it].y);
            *(__half2*)&As[r][qc4 + 2] = __floats2half2_rn(pa[it].z, pa[it].w);
            *(__half2*)&Ws[r][qc4]     = __floats2half2_rn(pw[it].x, pw[it].y);
            *(__half2*)&Ws[r][qc4 + 2] = __floats2half2_rn(pw[it].z, pw[it].w);
        }
        __syncthreads();

        if (k0 + 32 < ND) {
            #pragma unroll
            for (int it = 0; it < 4; it++) {
                int r = qrow + it * 32;
                pa[it] = *(const float4*)&A[(size_t)(m0 + r) * ND + k0 + 32 + qc4];
                pw[it] = *(const float4*)&W[(size_t)(n0 + r) * ND + k0 + 32 + qc4];
            }
        }

        #pragma unroll
        for (int kk = 0; kk < 32; kk += 16) {
            uint32_t afr[4][4], bfr[4][2];
            #pragma unroll
            for (int i = 0; i < 4; i++)
                ldsm_x4(afr[i], baseA + (uint32_t)(i*16*40 + kk)*2u);
            #pragma unroll
            for (int jp = 0; jp < 2; jp++) {
                uint32_t bt[4];
                ldsm_x4(bt, baseB + (uint32_t)(jp*16*40 + kk)*2u);
                bfr[2*jp][0]   = bt[0]; bfr[2*jp][1]   = bt[1];
                bfr[2*jp+1][0] = bt[2]; bfr[2*jp+1][1] = bt[3];
            }
            #pragma unroll
            for (int i = 0; i < 4; i++)
                #pragma unroll
                for (int j = 0; j < 4; j++)
                    mma_f16(acc[i][j], afr[i], bfr[j]);
        }
        __syncthreads();
    }

    #pragma unroll
    for (int i = 0; i < 4; i++) {
        int r0 = m0 + warp_m*64 + i*16 + lg;
        #pragma unroll
        for (int j = 0; j < 4; j++) {
            int cc = n0 + warp_n*32 + j*8 + lq*2;
            float b0 = bias[cc], b1 = bias[cc+1];
            out[(size_t)r0       * ND + cc    ] = acc[i][j][0] + b0;
            out[(size_t)r0       * ND + cc + 1] = acc[i][j][1] + b1;
            out[(size_t)(r0 + 8) * ND + cc    ] = acc[i][j][2] + b0;
            out[(size_t)(r0 + 8) * ND + cc + 1] = acc[i][j][3] + b1;
        }
    }
}

// ---------------------------------------------------------------------------
extern "C" void kernel_launch(void* const* d_in, const int* in_sizes, int n_in,
                              void* d_out, int out_size)
{
    const float* x     = (const float*)d_in[0];
    const float* A_log = (const float*)d_in[1];
    const float* Dvec  = (const float*)d_in[2];
    const float* B_w   = (const float*)d_in[3];
    const float* B_b   = (const float*)d_in[4];
    const float* C_w   = (const float*)d_in[5];
    const float* C_b   = (const float*)d_in[6];
    const float* dt_w  = (const float*)d_in[7];
    const float* dt_b  = (const float*)d_in[8];
    const float* out_w = (const float*)d_in[9];
    const float* out_b = (const float*)d_in[10];
    float* out = (float*)d_out;

    cudaFuncSetAttribute(y_kernel_tc, cudaFuncAttributeMaxDynamicSharedMemorySize,
                         Y_SMEM);

    proj_fused<<<dim3(NTOK/64, 3), 256>>>(x, B_w, B_b, C_w, C_b, dt_w, dt_b);
    cumsum_kernel<<<NB*NH*NC, NL>>>(A_log);
    states_tc<<<NB*NC*NH, 256>>>(x);
    scan_kernel<<<NB*NH*16, 256>>>();
    y_kernel_tc<<<NB*NC*NH*2, 256, Y_SMEM>>>(x, Dvec);
    out_gemm_f16<<<dim3(ND/128, NTOK/128), 256>>>(out_w, out_b, out);
}